// round 3
// baseline (speedup 1.0000x reference)
#include <cuda_runtime.h>
#include <math.h>

#define BB   2
#define NN   2048
#define DIMM 1024
#define HH   8
#define DHH  128
#define S3   (3*DIMM)
#define SCALE_Q 0.08838834764831845f
#define EPSV 1e-10f

// ---------------- scratch (static device globals; no allocation) ----------------
__device__ float g_xn  [BB*NN*DIMM];
__device__ float g_q   [BB*HH*NN*DHH];
__device__ float g_k   [BB*HH*NN*DHH];
__device__ float g_v   [BB*HH*NN*DHH];
__device__ float g_qr  [BB*HH*NN*DHH];
__device__ float g_kr  [BB*HH*NN*DHH];
__device__ float g_qf  [BB*HH*NN*DHH];
__device__ float g_kf  [BB*HH*NN*DHH];
__device__ float g_attn[BB*HH*NN*DHH];
__device__ float g_comb[BB*NN*DIMM];

// ---------------- 1) RMSNorm ----------------
__global__ void rmsnorm_k(const float* __restrict__ x, const float* __restrict__ gamma) {
    int row = blockIdx.x;                      // b*NN + n
    const float* xr = x + (size_t)row * DIMM;
    float ss = 0.f;
    for (int i = threadIdx.x; i < DIMM; i += 256) { float v = xr[i]; ss += v * v; }
    #pragma unroll
    for (int o = 16; o > 0; o >>= 1) ss += __shfl_xor_sync(0xffffffffu, ss, o);
    __shared__ float red[8];
    __shared__ float sinv;
    if ((threadIdx.x & 31) == 0) red[threadIdx.x >> 5] = ss;
    __syncthreads();
    if (threadIdx.x == 0) {
        float t = 0.f;
        #pragma unroll
        for (int i = 0; i < 8; i++) t += red[i];
        sinv = 32.0f / fmaxf(sqrtf(t), 1e-12f);   // sqrt(1024)=32
    }
    __syncthreads();
    float inv = sinv;
    float* o = g_xn + (size_t)row * DIMM;
    for (int i = threadIdx.x; i < DIMM; i += 256) o[i] = xr[i] * inv * gamma[i];
}

// ---------------- 2/6) SGEMM  C = A @ W^T,  A:[M,1024], W:[Ncols,1024] ----------------
// mode 0: A = g_xn,  Ncols=3072, epilogue scatters into g_q/g_k/g_v  [b,h,n,d]
// mode 1: A = g_comb, Ncols=1024, epilogue writes outp row-major
__global__ void __launch_bounds__(256) sgemm_k(int mode, const float* __restrict__ W,
                                               float* __restrict__ outp) {
    const float* A = (mode == 0) ? g_xn : g_comb;
    const int K = DIMM;
    __shared__ float As[8][128];
    __shared__ float Bs[8][128];
    int tid  = threadIdx.x;
    int tx   = tid & 15, ty = tid >> 4;
    int arow = tid >> 1, acol = (tid & 1) * 4;
    const float* Ap = A + (size_t)(blockIdx.y * 128 + arow) * K + acol;
    const float* Bp = W + (size_t)(blockIdx.x * 128 + arow) * K + acol;
    float acc[8][8];
    #pragma unroll
    for (int i = 0; i < 8; i++)
        #pragma unroll
        for (int j = 0; j < 8; j++) acc[i][j] = 0.f;

    for (int k0 = 0; k0 < K; k0 += 8) {
        float4 av = *(const float4*)(Ap + k0);
        float4 bv = *(const float4*)(Bp + k0);
        As[acol+0][arow]=av.x; As[acol+1][arow]=av.y; As[acol+2][arow]=av.z; As[acol+3][arow]=av.w;
        Bs[acol+0][arow]=bv.x; Bs[acol+1][arow]=bv.y; Bs[acol+2][arow]=bv.z; Bs[acol+3][arow]=bv.w;
        __syncthreads();
        #pragma unroll
        for (int kk = 0; kk < 8; kk++) {
            float a[8], b[8];
            *(float4*)(a)   = *(const float4*)&As[kk][ty*8];
            *(float4*)(a+4) = *(const float4*)&As[kk][ty*8+4];
            *(float4*)(b)   = *(const float4*)&Bs[kk][tx*8];
            *(float4*)(b+4) = *(const float4*)&Bs[kk][tx*8+4];
            #pragma unroll
            for (int i = 0; i < 8; i++)
                #pragma unroll
                for (int j = 0; j < 8; j++) acc[i][j] += a[i] * b[j];
        }
        __syncthreads();
    }

    if (mode == 0) {
        #pragma unroll
        for (int i = 0; i < 8; i++) {
            int row = blockIdx.y * 128 + ty * 8 + i;
            int b_ = row >> 11, n_ = row & (NN - 1);
            #pragma unroll
            for (int j = 0; j < 8; j++) {
                int col = blockIdx.x * 128 + tx * 8 + j;
                int sel = col >> 10, rem = col & 1023;
                int h = rem >> 7, dd = rem & 127;
                float* dst = (sel == 0) ? g_q : ((sel == 1) ? g_k : g_v);
                dst[((size_t)(b_ * HH + h) * NN + n_) * DHH + dd] = acc[i][j];
            }
        }
    } else {
        #pragma unroll
        for (int i = 0; i < 8; i++) {
            int row = blockIdx.y * 128 + ty * 8 + i;
            #pragma unroll
            for (int j = 0; j < 8; j++) {
                int col = blockIdx.x * 128 + tx * 8 + j;
                outp[(size_t)row * DIMM + col] = acc[i][j];
            }
        }
    }
}

// ---------------- 3) RoPE + elu features ----------------
__global__ void rope_feat_k() {
    int gid = blockIdx.x * blockDim.y + threadIdx.y;  // (b*H+h)*N + n
    int p   = threadIdx.x;                            // pair index 0..63
    int n_  = gid & (NN - 1);
    size_t base = (size_t)gid * DHH;
    float inv = powf(10000.0f, -(float)(2 * p) * (1.0f / 128.0f));
    float ang = (float)n_ * inv;
    float s, c;
    sincosf(ang, &s, &c);
    float q0 = g_q[base + 2*p], q1 = g_q[base + 2*p + 1];
    float k0 = g_k[base + 2*p], k1 = g_k[base + 2*p + 1];
    float sq0 = q0 * SCALE_Q, sq1 = q1 * SCALE_Q;
    g_qr[base + 2*p]     = sq0 * c - sq1 * s;
    g_qr[base + 2*p + 1] = sq1 * c + sq0 * s;
    g_kr[base + 2*p]     = k0 * c - k1 * s;
    g_kr[base + 2*p + 1] = k1 * c + k0 * s;
    g_qf[base + 2*p]     = (q0 > 0.f) ? q0 + 1.f : expf(q0);
    g_qf[base + 2*p + 1] = (q1 > 0.f) ? q1 + 1.f : expf(q1);
    g_kf[base + 2*p]     = (k0 > 0.f) ? k0 + 1.f : expf(k0);
    g_kf[base + 2*p + 1] = (k1 > 0.f) ? k1 + 1.f : expf(k1);
}

// ---------------- 4) causal flash attention ----------------
// grid (N/64, B*H), 256 threads: 64 q-rows x 4 lanes; each lane owns 32 dims.
// Per-lane rotation (d + 8*c4)&31 -> conflict-free K/V smem reads.
__global__ void __launch_bounds__(256) flash_k() {
    int bh  = blockIdx.y;
    int it  = blockIdx.x;
    int tid = threadIdx.x;
    int r   = tid >> 2;
    int c4  = tid & 3;
    int rot = c4 << 3;
    int qglob = it * 64 + r;
    __shared__ float Ks[32][128];
    __shared__ float Vs[32][128];

    float qfr[32];
    const float* Qb = g_qr + ((size_t)bh * NN + qglob) * DHH + c4 * 32;
    #pragma unroll
    for (int d = 0; d < 32; d++) qfr[d] = Qb[(d + rot) & 31];

    float acc[32];
    #pragma unroll
    for (int d = 0; d < 32; d++) acc[d] = 0.f;
    float m = -1e30f, l = 0.f;
    int lbase = (tid & 31) & ~3;
    int ntiles = 2 * (it + 1);

    for (int jt = 0; jt < ntiles; jt++) {
        size_t kb = ((size_t)bh * NN + jt * 32) * DHH;
        float* ks = &Ks[0][0];
        float* vs = &Vs[0][0];
        #pragma unroll
        for (int i = 0; i < 4; i++) {
            int idx = tid + i * 256;
            ((float4*)ks)[idx] = ((const float4*)(g_kr + kb))[idx];
            ((float4*)vs)[idx] = ((const float4*)(g_v  + kb))[idx];
        }
        __syncthreads();

        float sc[8];
        for (int c = 0; c < 32; c++) {
            const float* kr = &Ks[c][c4 * 32];
            float pp = 0.f;
            #pragma unroll
            for (int d = 0; d < 32; d++) pp += qfr[d] * kr[(d + rot) & 31];
            pp += __shfl_xor_sync(0xffffffffu, pp, 1);
            pp += __shfl_xor_sync(0xffffffffu, pp, 2);
            if ((c & 3) == c4) {
                int kg = jt * 32 + c;
                sc[c >> 2] = (kg <= qglob) ? pp : -1e30f;
            }
        }
        float tmax = -1e30f;
        #pragma unroll
        for (int i = 0; i < 8; i++) tmax = fmaxf(tmax, sc[i]);
        tmax = fmaxf(tmax, __shfl_xor_sync(0xffffffffu, tmax, 1));
        tmax = fmaxf(tmax, __shfl_xor_sync(0xffffffffu, tmax, 2));
        float mnew  = fmaxf(m, tmax);
        float alpha = expf(m - mnew);
        float pv[8];
        float psum = 0.f;
        #pragma unroll
        for (int i = 0; i < 8; i++) { pv[i] = expf(sc[i] - mnew); psum += pv[i]; }
        psum += __shfl_xor_sync(0xffffffffu, psum, 1);
        psum += __shfl_xor_sync(0xffffffffu, psum, 2);
        l = l * alpha + psum;
        m = mnew;
        #pragma unroll
        for (int d = 0; d < 32; d++) acc[d] *= alpha;

        for (int c = 0; c < 32; c++) {
            float p = __shfl_sync(0xffffffffu, pv[c >> 2], lbase + (c & 3));
            const float* vr = &Vs[c][c4 * 32];
            #pragma unroll
            for (int d = 0; d < 32; d++) acc[d] += p * vr[(d + rot) & 31];
        }
        __syncthreads();
    }
    float invl = 1.f / l;
    float* outp = g_attn + ((size_t)bh * NN + qglob) * DHH + c4 * 32;
    #pragma unroll
    for (int d = 0; d < 32; d++) outp[(d + rot) & 31] = acc[d] * invl;
}

// ---------------- 5) memory retrieval + gate blend -> g_comb [b,n,h*d] ----------------
__global__ void retrieve_gate_k(const float* __restrict__ mem_kv,
                                const float* __restrict__ mem_norm,
                                const float* __restrict__ head_gates) {
    int bh = blockIdx.y;
    int b_ = bh >> 3, h = bh & 7;
    int t0 = blockIdx.x * 32;
    int v  = threadIdx.x;                       // 128 threads = output dim
    __shared__ float qsT[128][36];              // transposed qf tile; stride 36 keeps float4 alignment
    __shared__ float dn[32];
    __shared__ float mn[128];
    mn[v] = mem_norm[bh * DHH + v];
    const float* qf = g_qf + ((size_t)bh * NN + t0) * DHH;
    for (int i = v; i < 32 * 32; i += 128) {    // 1024 float4 loads
        int t = i >> 5;
        int k4 = (i & 31) * 4;
        float4 qv = *(const float4*)(qf + (size_t)t * DHH + k4);
        qsT[k4+0][t] = qv.x; qsT[k4+1][t] = qv.y; qsT[k4+2][t] = qv.z; qsT[k4+3][t] = qv.w;
    }
    __syncthreads();
    if (v < 32) {
        float s = 0.f;
        #pragma unroll 8
        for (int k = 0; k < 128; k++) s += qsT[k][v] * mn[k];
        dn[v] = fmaxf(s, EPSV);
    }
    __syncthreads();
    const float* mkv = mem_kv + (size_t)bh * DHH * DHH;
    float num[32];
    #pragma unroll
    for (int t = 0; t < 32; t++) num[t] = 0.f;
    for (int k = 0; k < 128; k++) {
        float mval = mkv[k * DHH + v];
        #pragma unroll
        for (int t8 = 0; t8 < 8; t8++) {
            float4 qv = *(const float4*)&qsT[k][t8 * 4];
            num[t8*4+0] += qv.x * mval;
            num[t8*4+1] += qv.y * mval;
            num[t8*4+2] += qv.z * mval;
            num[t8*4+3] += qv.w * mval;
        }
    }
    float g = 1.f / (1.f + expf(-head_gates[h]));
    const float* at = g_attn + ((size_t)bh * NN + t0) * DHH;
    float* cb = g_comb + ((size_t)b_ * NN + t0) * DIMM + h * DHH;
    #pragma unroll 4
    for (int t = 0; t < 32; t++) {
        float mo = num[t] / dn[t];
        cb[(size_t)t * DIMM + v] = at[(size_t)t * DHH + v] * g + mo * (1.f - g);
    }
}

// ---------------- 7) delta-rule new_kv ----------------
__global__ void __launch_bounds__(256) newkv_k(const float* __restrict__ mem_kv,
                                               const float* __restrict__ mem_norm,
                                               float* __restrict__ out_kv) {
    int bh  = blockIdx.x;
    int tid = threadIdx.x;
    int tx = tid & 15, ty = tid >> 4;
    __shared__ float kfs[32][128];
    __shared__ float vns[32][128];
    __shared__ float mn[128];
    __shared__ float dns[32];
    if (tid < 128) mn[tid] = mem_norm[bh * DHH + tid];
    const float* mkv = mem_kv + (size_t)bh * DHH * DHH;
    const float* kfb = g_kf + (size_t)bh * NN * DHH;
    const float* vb  = g_v  + (size_t)bh * NN * DHH;
    float C[8][8];
    #pragma unroll
    for (int i = 0; i < 8; i++)
        #pragma unroll
        for (int j = 0; j < 8; j++) C[i][j] = 0.f;

    for (int t0 = 0; t0 < NN; t0 += 32) {
        __syncthreads();
        #pragma unroll
        for (int i = 0; i < 4; i++) {
            int idx = tid + i * 256;
            ((float4*)&kfs[0][0])[idx] = ((const float4*)(kfb + (size_t)t0 * DHH))[idx];
            ((float4*)&vns[0][0])[idx] = ((const float4*)(vb  + (size_t)t0 * DHH))[idx];
        }
        __syncthreads();
        if (tid < 32) {                         // denominators (rotated: conflict-free)
            float s = 0.f;
            #pragma unroll 8
            for (int k = 0; k < 128; k++) {
                int kk = (k + tid) & 127;
                s += kfs[tid][kk] * mn[kk];
            }
            dns[tid] = fmaxf(s, EPSV);
        }
        __syncthreads();
        {                                       // v_new = v - retrieve(kf)
            int v = tid & 127, th = tid >> 7;
            float numv[16];
            #pragma unroll
            for (int t = 0; t < 16; t++) numv[t] = 0.f;
            for (int k = 0; k < 128; k++) {
                float mval = mkv[k * DHH + v];
                #pragma unroll
                for (int t = 0; t < 16; t++) numv[t] += kfs[th * 16 + t][k] * mval;
            }
            #pragma unroll
            for (int t = 0; t < 16; t++) vns[th * 16 + t][v] -= numv[t] / dns[th * 16 + t];
        }
        __syncthreads();
        #pragma unroll 4
        for (int t = 0; t < 32; t++) {          // C += kf^T v_new
            float a[8], bvv[8];
            *(float4*)(a)     = *(const float4*)&kfs[t][ty*8];
            *(float4*)(a+4)   = *(const float4*)&kfs[t][ty*8+4];
            *(float4*)(bvv)   = *(const float4*)&vns[t][tx*8];
            *(float4*)(bvv+4) = *(const float4*)&vns[t][tx*8+4];
            #pragma unroll
            for (int i = 0; i < 8; i++)
                #pragma unroll
                for (int j = 0; j < 8; j++) C[i][j] += a[i] * bvv[j];
        }
    }
    #pragma unroll
    for (int i = 0; i < 8; i++)
        #pragma unroll
        for (int j = 0; j < 8; j++) {
            int kd = ty * 8 + i, vd = tx * 8 + j;
            out_kv[(size_t)bh * DHH * DHH + kd * DHH + vd] = C[i][j] + mkv[kd * DHH + vd];
        }
}

// ---------------- 8) new_norm ----------------
__global__ void newnorm_k(const float* __restrict__ mem_norm, float* __restrict__ out_norm) {
    int bh = blockIdx.x;
    int k  = threadIdx.x;                      // 128
    const float* kf = g_kf + (size_t)bh * NN * DHH;
    float s = mem_norm[bh * DHH + k];
    #pragma unroll 8
    for (int n_ = 0; n_ < NN; n_++) s += kf[(size_t)n_ * DHH + k];
    out_norm[bh * DHH + k] = s;
}

// ---------------- launch ----------------
extern "C" void kernel_launch(void* const* d_in, const int* in_sizes, int n_in,
                              void* d_out, int out_size) {
    (void)in_sizes; (void)n_in; (void)out_size;
    const float* x          = (const float*)d_in[0];
    const float* gamma      = (const float*)d_in[1];
    const float* w_qkv      = (const float*)d_in[2];
    const float* w_out      = (const float*)d_in[3];
    const float* head_gates = (const float*)d_in[4];
    const float* mem_kv     = (const float*)d_in[5];
    const float* mem_norm   = (const float*)d_in[6];
    float* out      = (float*)d_out;
    float* out_kv   = out + (size_t)BB * NN * DIMM;
    float* out_norm = out_kv + BB * HH * DHH * DHH;

    rmsnorm_k<<<BB * NN, 256>>>(x, gamma);
    sgemm_k<<<dim3(S3 / 128, BB * NN / 128), 256>>>(0, w_qkv, nullptr);
    rope_feat_k<<<BB * HH * NN / 4, dim3(64, 4)>>>();
    flash_k<<<dim3(NN / 64, BB * HH), 256>>>();
    retrieve_gate_k<<<dim3(NN / 32, BB * HH), 128>>>(mem_kv, mem_norm, head_gates);
    sgemm_k<<<dim3(DIMM / 128, BB * NN / 128), 256>>>(1, w_out, out);
    newkv_k<<<BB * HH, 256>>>(mem_kv, mem_norm, out_kv);
    newnorm_k<<<BB * HH, 128>>>(mem_norm, out_norm);
}

// round 6
// speedup vs baseline: 1.4365x; 1.4365x over previous
#include <cuda_runtime.h>
#include <math.h>
#include <stdint.h>

#define BB   2
#define NN   2048
#define DIMM 1024
#define HH   8
#define DHH  128
#define S3   (3*DIMM)
#define SCALE_Q 0.08838834764831845f
#define EPSV 1e-10f

// ---------------- scratch (static device globals; no allocation) ----------------
__device__ float g_xn  [BB*NN*DIMM];
__device__ float g_q   [BB*HH*NN*DHH];
__device__ float g_k   [BB*HH*NN*DHH];
__device__ float g_v   [BB*HH*NN*DHH];
__device__ float g_qr  [BB*HH*NN*DHH];
__device__ float g_kr  [BB*HH*NN*DHH];
__device__ float g_qf  [BB*HH*NN*DHH];
__device__ float g_kf  [BB*HH*NN*DHH];
__device__ float g_attn[BB*HH*NN*DHH];
__device__ float g_comb[BB*NN*DIMM];
__device__ float g_pnorm[BB*HH*8*DHH];

// ---------------- helpers ----------------
__device__ __forceinline__ uint32_t f2tf32(float f) {
    uint32_t r;
    asm("cvt.rna.tf32.f32 %0, %1;" : "=r"(r) : "f"(f));
    return r;
}

__device__ __forceinline__ void mma_tf32(float* d, const uint32_t* a, const uint32_t* b) {
    asm volatile(
        "mma.sync.aligned.m16n8k8.row.col.f32.tf32.tf32.f32 "
        "{%0,%1,%2,%3}, {%4,%5,%6,%7}, {%8,%9}, {%0,%1,%2,%3};\n"
        : "+f"(d[0]), "+f"(d[1]), "+f"(d[2]), "+f"(d[3])
        : "r"(a[0]), "r"(a[1]), "r"(a[2]), "r"(a[3]), "r"(b[0]), "r"(b[1]));
}

// ---------------- 1) RMSNorm ----------------
__global__ void rmsnorm_k(const float* __restrict__ x, const float* __restrict__ gamma) {
    int row = blockIdx.x;                      // b*NN + n
    const float* xr = x + (size_t)row * DIMM;
    float ss = 0.f;
    for (int i = threadIdx.x; i < DIMM; i += 256) { float v = xr[i]; ss += v * v; }
    #pragma unroll
    for (int o = 16; o > 0; o >>= 1) ss += __shfl_xor_sync(0xffffffffu, ss, o);
    __shared__ float red[8];
    __shared__ float sinv;
    if ((threadIdx.x & 31) == 0) red[threadIdx.x >> 5] = ss;
    __syncthreads();
    if (threadIdx.x == 0) {
        float t = 0.f;
        #pragma unroll
        for (int i = 0; i < 8; i++) t += red[i];
        sinv = 32.0f / fmaxf(sqrtf(t), 1e-12f);   // sqrt(1024)=32
    }
    __syncthreads();
    float inv = sinv;
    float* o = g_xn + (size_t)row * DIMM;
    for (int i = threadIdx.x; i < DIMM; i += 256) o[i] = xr[i] * inv * gamma[i];
}

// ---------------- 2/6) tf32 tensor-core GEMM  C = A @ W^T ----------------
// A:[M,1024] row-major, W:[Ncols,1024] row-major (so B = W^T is col-major k x n).
// Block tile 128x128, kt=32. 8 warps in 2(M) x 4(N) grid, each 64x32 via m16n8k8.
// mode 0: A=g_xn, epilogue scatters into g_q/g_k/g_v; mode 1: A=g_comb -> outp.
__global__ void __launch_bounds__(256) sgemm_tc(int mode, const float* __restrict__ W,
                                                float* __restrict__ outp) {
    const float* A = (mode == 0) ? g_xn : g_comb;
    const int K = DIMM;
    __shared__ uint32_t As[128][36];   // stride 36 floats: conflict-free frags, 16B-aligned rows
    __shared__ uint32_t Bs[128][36];
    int tid  = threadIdx.x;
    int lane = tid & 31, warp = tid >> 5;
    int wm = warp >> 2, wn = warp & 3;        // 2 x 4 warp grid
    int r  = lane >> 2, cc = lane & 3;

    float acc[4][4][4];
    #pragma unroll
    for (int mt = 0; mt < 4; mt++)
        #pragma unroll
        for (int nt = 0; nt < 4; nt++)
            #pragma unroll
            for (int i = 0; i < 4; i++) acc[mt][nt][i] = 0.f;

    size_t aBase = (size_t)(blockIdx.y * 128) * K;
    size_t bBase = (size_t)(blockIdx.x * 128) * K;

    for (int k0 = 0; k0 < K; k0 += 32) {
        #pragma unroll
        for (int i = 0; i < 4; i++) {
            int idx = tid + i * 256;           // 1024 float4 per tile
            int row = idx >> 3;
            int kq  = (idx & 7) * 4;
            float4 av = *(const float4*)(A + aBase + (size_t)row * K + k0 + kq);
            float4 bv = *(const float4*)(W + bBase + (size_t)row * K + k0 + kq);
            *(uint4*)&As[row][kq] = make_uint4(f2tf32(av.x), f2tf32(av.y), f2tf32(av.z), f2tf32(av.w));
            *(uint4*)&Bs[row][kq] = make_uint4(f2tf32(bv.x), f2tf32(bv.y), f2tf32(bv.z), f2tf32(bv.w));
        }
        __syncthreads();
        #pragma unroll
        for (int ks = 0; ks < 32; ks += 8) {
            uint32_t af[4][4], bf[4][2];
            #pragma unroll
            for (int mt = 0; mt < 4; mt++) {
                int m0 = wm * 64 + mt * 16;
                af[mt][0] = As[m0 + r    ][ks + cc];
                af[mt][1] = As[m0 + r + 8][ks + cc];
                af[mt][2] = As[m0 + r    ][ks + cc + 4];
                af[mt][3] = As[m0 + r + 8][ks + cc + 4];
            }
            #pragma unroll
            for (int nt = 0; nt < 4; nt++) {
                int n0 = wn * 32 + nt * 8;
                bf[nt][0] = Bs[n0 + r][ks + cc];
                bf[nt][1] = Bs[n0 + r][ks + cc + 4];
            }
            #pragma unroll
            for (int mt = 0; mt < 4; mt++)
                #pragma unroll
                for (int nt = 0; nt < 4; nt++)
                    mma_tf32(acc[mt][nt], af[mt], bf[nt]);
        }
        __syncthreads();
    }

    // epilogue: C element (m0+r(+8), n0+2cc(+1)) = acc[..][0..3]
    #pragma unroll
    for (int mt = 0; mt < 4; mt++) {
        #pragma unroll
        for (int half = 0; half < 2; half++) {
            int row = blockIdx.y * 128 + wm * 64 + mt * 16 + r + half * 8;
            #pragma unroll
            for (int nt = 0; nt < 4; nt++) {
                int col = blockIdx.x * 128 + wn * 32 + nt * 8 + 2 * cc;
                float v0 = acc[mt][nt][half * 2 + 0];
                float v1 = acc[mt][nt][half * 2 + 1];
                if (mode == 0) {
                    int b_ = row >> 11, n_ = row & (NN - 1);
                    int sel = col >> 10, rem = col & 1023;
                    int h = rem >> 7, dd = rem & 127;
                    float* dst = (sel == 0) ? g_q : ((sel == 1) ? g_k : g_v);
                    float2* p = (float2*)&dst[((size_t)(b_ * HH + h) * NN + n_) * DHH + dd];
                    *p = make_float2(v0, v1);
                } else {
                    float2* p = (float2*)&outp[(size_t)row * DIMM + col];
                    *p = make_float2(v0, v1);
                }
            }
        }
    }
}

// ---------------- 3) RoPE + elu features ----------------
__global__ void rope_feat_k() {
    int gid = blockIdx.x * blockDim.y + threadIdx.y;  // (b*H+h)*N + n
    int p   = threadIdx.x;                            // pair index 0..63
    int n_  = gid & (NN - 1);
    size_t base = (size_t)gid * DHH;
    float inv = powf(10000.0f, -(float)(2 * p) * (1.0f / 128.0f));
    float ang = (float)n_ * inv;
    float s, c;
    sincosf(ang, &s, &c);
    float q0 = g_q[base + 2*p], q1 = g_q[base + 2*p + 1];
    float k0 = g_k[base + 2*p], k1 = g_k[base + 2*p + 1];
    float sq0 = q0 * SCALE_Q, sq1 = q1 * SCALE_Q;
    g_qr[base + 2*p]     = sq0 * c - sq1 * s;
    g_qr[base + 2*p + 1] = sq1 * c + sq0 * s;
    g_kr[base + 2*p]     = k0 * c - k1 * s;
    g_kr[base + 2*p + 1] = k1 * c + k0 * s;
    g_qf[base + 2*p]     = (q0 > 0.f) ? q0 + 1.f : expf(q0);
    g_qf[base + 2*p + 1] = (q1 > 0.f) ? q1 + 1.f : expf(q1);
    g_kf[base + 2*p]     = (k0 > 0.f) ? k0 + 1.f : expf(k0);
    g_kf[base + 2*p + 1] = (k1 > 0.f) ? k1 + 1.f : expf(k1);
}

// ---------------- 4) causal flash attention (unchanged this round) ----------------
__global__ void __launch_bounds__(256) flash_k() {
    int bh  = blockIdx.y;
    int it  = blockIdx.x;
    int tid = threadIdx.x;
    int r   = tid >> 2;
    int c4  = tid & 3;
    int rot = c4 << 3;
    int qglob = it * 64 + r;
    __shared__ float Ks[32][128];
    __shared__ float Vs[32][128];

    float qfr[32];
    const float* Qb = g_qr + ((size_t)bh * NN + qglob) * DHH + c4 * 32;
    #pragma unroll
    for (int d = 0; d < 32; d++) qfr[d] = Qb[(d + rot) & 31];

    float acc[32];
    #pragma unroll
    for (int d = 0; d < 32; d++) acc[d] = 0.f;
    float m = -1e30f, l = 0.f;
    int lbase = (tid & 31) & ~3;
    int ntiles = 2 * (it + 1);

    for (int jt = 0; jt < ntiles; jt++) {
        size_t kb = ((size_t)bh * NN + jt * 32) * DHH;
        float* ks = &Ks[0][0];
        float* vs = &Vs[0][0];
        #pragma unroll
        for (int i = 0; i < 4; i++) {
            int idx = tid + i * 256;
            ((float4*)ks)[idx] = ((const float4*)(g_kr + kb))[idx];
            ((float4*)vs)[idx] = ((const float4*)(g_v  + kb))[idx];
        }
        __syncthreads();

        float sc[8];
        for (int c = 0; c < 32; c++) {
            const float* kr = &Ks[c][c4 * 32];
            float pp = 0.f;
            #pragma unroll
            for (int d = 0; d < 32; d++) pp += qfr[d] * kr[(d + rot) & 31];
            pp += __shfl_xor_sync(0xffffffffu, pp, 1);
            pp += __shfl_xor_sync(0xffffffffu, pp, 2);
            if ((c & 3) == c4) {
                int kg = jt * 32 + c;
                sc[c >> 2] = (kg <= qglob) ? pp : -1e30f;
            }
        }
        float tmax = -1e30f;
        #pragma unroll
        for (int i = 0; i < 8; i++) tmax = fmaxf(tmax, sc[i]);
        tmax = fmaxf(tmax, __shfl_xor_sync(0xffffffffu, tmax, 1));
        tmax = fmaxf(tmax, __shfl_xor_sync(0xffffffffu, tmax, 2));
        float mnew  = fmaxf(m, tmax);
        float alpha = expf(m - mnew);
        float pv[8];
        float psum = 0.f;
        #pragma unroll
        for (int i = 0; i < 8; i++) { pv[i] = expf(sc[i] - mnew); psum += pv[i]; }
        psum += __shfl_xor_sync(0xffffffffu, psum, 1);
        psum += __shfl_xor_sync(0xffffffffu, psum, 2);
        l = l * alpha + psum;
        m = mnew;
        #pragma unroll
        for (int d = 0; d < 32; d++) acc[d] *= alpha;

        for (int c = 0; c < 32; c++) {
            float p = __shfl_sync(0xffffffffu, pv[c >> 2], lbase + (c & 3));
            const float* vr = &Vs[c][c4 * 32];
            #pragma unroll
            for (int d = 0; d < 32; d++) acc[d] += p * vr[(d + rot) & 31];
        }
        __syncthreads();
    }
    float invl = 1.f / l;
    float* outp = g_attn + ((size_t)bh * NN + qglob) * DHH + c4 * 32;
    #pragma unroll
    for (int d = 0; d < 32; d++) outp[(d + rot) & 31] = acc[d] * invl;
}

// ---------------- 5) memory retrieval + gate blend -> g_comb [b,n,h*d] ----------------
__global__ void retrieve_gate_k(const float* __restrict__ mem_kv,
                                const float* __restrict__ mem_norm,
                                const float* __restrict__ head_gates) {
    int bh = blockIdx.y;
    int b_ = bh >> 3, h = bh & 7;
    int t0 = blockIdx.x * 32;
    int v  = threadIdx.x;                       // 128 threads = output dim
    __shared__ float qsT[128][36];              // stride 36 keeps float4 alignment
    __shared__ float dn[32];
    __shared__ float mn[128];
    mn[v] = mem_norm[bh * DHH + v];
    const float* qf = g_qf + ((size_t)bh * NN + t0) * DHH;
    for (int i = v; i < 32 * 32; i += 128) {    // 1024 float4 loads
        int t = i >> 5;
        int k4 = (i & 31) * 4;
        float4 qv = *(const float4*)(qf + (size_t)t * DHH + k4);
        qsT[k4+0][t] = qv.x; qsT[k4+1][t] = qv.y; qsT[k4+2][t] = qv.z; qsT[k4+3][t] = qv.w;
    }
    __syncthreads();
    if (v < 32) {
        float s = 0.f;
        #pragma unroll 8
        for (int k = 0; k < 128; k++) s += qsT[k][v] * mn[k];
        dn[v] = fmaxf(s, EPSV);
    }
    __syncthreads();
    const float* mkv = mem_kv + (size_t)bh * DHH * DHH;
    float num[32];
    #pragma unroll
    for (int t = 0; t < 32; t++) num[t] = 0.f;
    for (int k = 0; k < 128; k++) {
        float mval = mkv[k * DHH + v];
        #pragma unroll
        for (int t8 = 0; t8 < 8; t8++) {
            float4 qv = *(const float4*)&qsT[k][t8 * 4];
            num[t8*4+0] += qv.x * mval;
            num[t8*4+1] += qv.y * mval;
            num[t8*4+2] += qv.z * mval;
            num[t8*4+3] += qv.w * mval;
        }
    }
    float g = 1.f / (1.f + expf(-head_gates[h]));
    const float* at = g_attn + ((size_t)bh * NN + t0) * DHH;
    float* cb = g_comb + ((size_t)b_ * NN + t0) * DIMM + h * DHH;
    #pragma unroll 4
    for (int t = 0; t < 32; t++) {
        float mo = num[t] / dn[t];
        cb[(size_t)t * DIMM + v] = at[(size_t)t * DHH + v] * g + mo * (1.f - g);
    }
}

// ---------------- 7) delta-rule new_kv (split 4x over v-dim) ----------------
// grid (BB*HH, 4); block 256. Each block owns C slice [128 k][32 v].
__global__ void __launch_bounds__(256) newkv_k(const float* __restrict__ mem_kv,
                                               const float* __restrict__ mem_norm,
                                               float* __restrict__ out_kv) {
    int bh    = blockIdx.x;
    int vbase = blockIdx.y * 32;
    int tid   = threadIdx.x;
    int ty = tid >> 3, tx = tid & 7;           // 32 k-groups x 8 v-groups (of 4)
    __shared__ float kfs[32][128];
    __shared__ float vns[32][32];
    __shared__ float mn[128];
    __shared__ float dns[32];
    if (tid < 128) mn[tid] = mem_norm[bh * DHH + tid];
    const float* mkv = mem_kv + (size_t)bh * DHH * DHH;
    const float* kfb = g_kf + (size_t)bh * NN * DHH;
    const float* vb  = g_v  + (size_t)bh * NN * DHH;
    float C[4][4];
    #pragma unroll
    for (int i = 0; i < 4; i++)
        #pragma unroll
        for (int j = 0; j < 4; j++) C[i][j] = 0.f;

    int vlane = tid & 31, tg = tid >> 5;       // for v_new: 8 groups x 4 tokens

    for (int t0 = 0; t0 < NN; t0 += 32) {
        __syncthreads();
        #pragma unroll
        for (int i = 0; i < 4; i++) {          // kf tile 32x128
            int idx = tid + i * 256;
            int t = idx >> 5, kq = (idx & 31) * 4;
            *(float4*)&kfs[t][kq] = *(const float4*)(kfb + (size_t)(t0 + t) * DHH + kq);
        }
        {                                      // v slice 32x32
            int t = tid >> 3, vq = (tid & 7) * 4;
            *(float4*)&vns[t][vq] = *(const float4*)(vb + (size_t)(t0 + t) * DHH + vbase + vq);
        }
        __syncthreads();
        if (tid < 32) {                        // denominators (rotated: conflict-free)
            float s = 0.f;
            #pragma unroll 8
            for (int k = 0; k < 128; k++) {
                int kk = (k + tid) & 127;
                s += kfs[tid][kk] * mn[kk];
            }
            dns[tid] = fmaxf(s, EPSV);
        }
        __syncthreads();
        {                                      // v_new = v - retrieve(kf) on slice
            float numv[4] = {0.f, 0.f, 0.f, 0.f};
            for (int k = 0; k < 128; k++) {
                float mval = mkv[k * DHH + vbase + vlane];
                #pragma unroll
                for (int j = 0; j < 4; j++) numv[j] += kfs[tg * 4 + j][k] * mval;
            }
            #pragma unroll
            for (int j = 0; j < 4; j++) vns[tg * 4 + j][vlane] -= numv[j] / dns[tg * 4 + j];
        }
        __syncthreads();
        #pragma unroll 4
        for (int t = 0; t < 32; t++) {         // C += kf^T v_new
            float4 a = *(const float4*)&kfs[t][ty * 4];
            float4 b = *(const float4*)&vns[t][tx * 4];
            float av[4] = {a.x, a.y, a.z, a.w};
            float bv[4] = {b.x, b.y, b.z, b.w};
            #pragma unroll
            for (int i = 0; i < 4; i++)
                #pragma unroll
                for (int j = 0; j < 4; j++) C[i][j] += av[i] * bv[j];
        }
    }
    #pragma unroll
    for (int i = 0; i < 4; i++)
        #pragma unroll
        for (int j = 0; j < 4; j++) {
            int kd = ty * 4 + i, vd = vbase + tx * 4 + j;
            out_kv[(size_t)bh * DHH * DHH + kd * DHH + vd] = C[i][j] + mkv[kd * DHH + vd];
        }
}

// ---------------- 8) new_norm: two-stage parallel sum ----------------
__global__ void newnorm_part_k() {
    int bh = blockIdx.x, ch = blockIdx.y;
    int k  = threadIdx.x;                      // 128
    const float* kf = g_kf + (size_t)bh * NN * DHH + (size_t)ch * 256 * DHH;
    float s = 0.f;
    #pragma unroll 8
    for (int n_ = 0; n_ < 256; n_++) s += kf[(size_t)n_ * DHH + k];
    g_pnorm[((size_t)bh * 8 + ch) * DHH + k] = s;
}
__global__ void newnorm_red_k(const float* __restrict__ mem_norm, float* __restrict__ out_norm) {
    int bh = blockIdx.x;
    int k  = threadIdx.x;
    float s = mem_norm[bh * DHH + k];
    #pragma unroll
    for (int c = 0; c < 8; c++) s += g_pnorm[((size_t)bh * 8 + c) * DHH + k];
    out_norm[bh * DHH + k] = s;
}

// ---------------- launch ----------------
extern "C" void kernel_launch(void* const* d_in, const int* in_sizes, int n_in,
                              void* d_out, int out_size) {
    (void)in_sizes; (void)n_in; (void)out_size;
    const float* x          = (const float*)d_in[0];
    const float* gamma      = (const float*)d_in[1];
    const float* w_qkv      = (const float*)d_in[2];
    const float* w_out      = (const float*)d_in[3];
    const float* head_gates = (const float*)d_in[4];
    const float* mem_kv     = (const float*)d_in[5];
    const float* mem_norm   = (const float*)d_in[6];
    float* out      = (float*)d_out;
    float* out_kv   = out + (size_t)BB * NN * DIMM;
    float* out_norm = out_kv + BB * HH * DHH * DHH;

    rmsnorm_k<<<BB * NN, 256>>>(x, gamma);
    sgemm_tc<<<dim3(S3 / 128, BB * NN / 128), 256>>>(0, w_qkv, nullptr);
    rope_feat_k<<<BB * HH * NN / 4, dim3(64, 4)>>>();
    flash_k<<<dim3(NN / 64, BB * HH), 256>>>();
    retrieve_gate_k<<<dim3(NN / 32, BB * HH), 128>>>(mem_kv, mem_norm, head_gates);
    sgemm_tc<<<dim3(DIMM / 128, BB * NN / 128), 256>>>(1, w_out, out);
    newkv_k<<<dim3(BB * HH, 4), 256>>>(mem_kv, mem_norm, out_kv);
    newnorm_part_k<<<dim3(BB * HH, 8), 128>>>();
    newnorm_red_k<<<BB * HH, 128>>>(mem_norm, out_norm);
}

// round 7
// speedup vs baseline: 2.6558x; 1.8488x over previous
#include <cuda_runtime.h>
#include <math.h>
#include <stdint.h>

#define BB   2
#define NN   2048
#define DIMM 1024
#define HH   8
#define DHH  128
#define S3   (3*DIMM)
#define SCALE_Q 0.08838834764831845f
#define EPSV 1e-10f

// ---------------- scratch (static device globals; no allocation) ----------------
__device__ float g_xn  [BB*NN*DIMM];
__device__ float g_q   [BB*HH*NN*DHH];
__device__ float g_k   [BB*HH*NN*DHH];
__device__ float g_v   [BB*HH*NN*DHH];
__device__ float g_qr  [BB*HH*NN*DHH];
__device__ float g_kr  [BB*HH*NN*DHH];
__device__ float g_qf  [BB*HH*NN*DHH];
__device__ float g_kf  [BB*HH*NN*DHH];
__device__ float g_attn[BB*HH*NN*DHH];
__device__ float g_comb[BB*NN*DIMM];
__device__ float g_pnorm[BB*HH*8*DHH];

// ---------------- helpers ----------------
__device__ __forceinline__ uint32_t f2tf32(float f) {
    uint32_t r;
    asm("cvt.rna.tf32.f32 %0, %1;" : "=r"(r) : "f"(f));
    return r;
}
__device__ __forceinline__ float tf32f(float f) { return __uint_as_float(f2tf32(f)); }

__device__ __forceinline__ void mma_tf32(float* d, const uint32_t* a, const uint32_t* b) {
    asm volatile(
        "mma.sync.aligned.m16n8k8.row.col.f32.tf32.tf32.f32 "
        "{%0,%1,%2,%3}, {%4,%5,%6,%7}, {%8,%9}, {%0,%1,%2,%3};\n"
        : "+f"(d[0]), "+f"(d[1]), "+f"(d[2]), "+f"(d[3])
        : "r"(a[0]), "r"(a[1]), "r"(a[2]), "r"(a[3]), "r"(b[0]), "r"(b[1]));
}

// ---------------- 1) RMSNorm ----------------
__global__ void rmsnorm_k(const float* __restrict__ x, const float* __restrict__ gamma) {
    int row = blockIdx.x;                      // b*NN + n
    const float* xr = x + (size_t)row * DIMM;
    float ss = 0.f;
    for (int i = threadIdx.x; i < DIMM; i += 256) { float v = xr[i]; ss += v * v; }
    #pragma unroll
    for (int o = 16; o > 0; o >>= 1) ss += __shfl_xor_sync(0xffffffffu, ss, o);
    __shared__ float red[8];
    __shared__ float sinv;
    if ((threadIdx.x & 31) == 0) red[threadIdx.x >> 5] = ss;
    __syncthreads();
    if (threadIdx.x == 0) {
        float t = 0.f;
        #pragma unroll
        for (int i = 0; i < 8; i++) t += red[i];
        sinv = 32.0f / fmaxf(sqrtf(t), 1e-12f);   // sqrt(1024)=32
    }
    __syncthreads();
    float inv = sinv;
    float* o = g_xn + (size_t)row * DIMM;
    for (int i = threadIdx.x; i < DIMM; i += 256) o[i] = xr[i] * inv * gamma[i];
}

// ---------------- 2/6) tf32 tensor-core GEMM  C = A @ W^T ----------------
__global__ void __launch_bounds__(256) sgemm_tc(int mode, const float* __restrict__ W,
                                                float* __restrict__ outp) {
    const float* A = (mode == 0) ? g_xn : g_comb;
    const int K = DIMM;
    __shared__ uint32_t As[128][36];
    __shared__ uint32_t Bs[128][36];
    int tid  = threadIdx.x;
    int lane = tid & 31, warp = tid >> 5;
    int wm = warp >> 2, wn = warp & 3;
    int r  = lane >> 2, cc = lane & 3;

    float acc[4][4][4];
    #pragma unroll
    for (int mt = 0; mt < 4; mt++)
        #pragma unroll
        for (int nt = 0; nt < 4; nt++)
            #pragma unroll
            for (int i = 0; i < 4; i++) acc[mt][nt][i] = 0.f;

    size_t aBase = (size_t)(blockIdx.y * 128) * K;
    size_t bBase = (size_t)(blockIdx.x * 128) * K;

    for (int k0 = 0; k0 < K; k0 += 32) {
        #pragma unroll
        for (int i = 0; i < 4; i++) {
            int idx = tid + i * 256;
            int row = idx >> 3;
            int kq  = (idx & 7) * 4;
            float4 av = *(const float4*)(A + aBase + (size_t)row * K + k0 + kq);
            float4 bv = *(const float4*)(W + bBase + (size_t)row * K + k0 + kq);
            *(uint4*)&As[row][kq] = make_uint4(f2tf32(av.x), f2tf32(av.y), f2tf32(av.z), f2tf32(av.w));
            *(uint4*)&Bs[row][kq] = make_uint4(f2tf32(bv.x), f2tf32(bv.y), f2tf32(bv.z), f2tf32(bv.w));
        }
        __syncthreads();
        #pragma unroll
        for (int ks = 0; ks < 32; ks += 8) {
            uint32_t af[4][4], bf[4][2];
            #pragma unroll
            for (int mt = 0; mt < 4; mt++) {
                int m0 = wm * 64 + mt * 16;
                af[mt][0] = As[m0 + r    ][ks + cc];
                af[mt][1] = As[m0 + r + 8][ks + cc];
                af[mt][2] = As[m0 + r    ][ks + cc + 4];
                af[mt][3] = As[m0 + r + 8][ks + cc + 4];
            }
            #pragma unroll
            for (int nt = 0; nt < 4; nt++) {
                int n0 = wn * 32 + nt * 8;
                bf[nt][0] = Bs[n0 + r][ks + cc];
                bf[nt][1] = Bs[n0 + r][ks + cc + 4];
            }
            #pragma unroll
            for (int mt = 0; mt < 4; mt++)
                #pragma unroll
                for (int nt = 0; nt < 4; nt++)
                    mma_tf32(acc[mt][nt], af[mt], bf[nt]);
        }
        __syncthreads();
    }

    #pragma unroll
    for (int mt = 0; mt < 4; mt++) {
        #pragma unroll
        for (int half = 0; half < 2; half++) {
            int row = blockIdx.y * 128 + wm * 64 + mt * 16 + r + half * 8;
            #pragma unroll
            for (int nt = 0; nt < 4; nt++) {
                int col = blockIdx.x * 128 + wn * 32 + nt * 8 + 2 * cc;
                float v0 = acc[mt][nt][half * 2 + 0];
                float v1 = acc[mt][nt][half * 2 + 1];
                if (mode == 0) {
                    int b_ = row >> 11, n_ = row & (NN - 1);
                    int sel = col >> 10, rem = col & 1023;
                    int h = rem >> 7, dd = rem & 127;
                    float* dst = (sel == 0) ? g_q : ((sel == 1) ? g_k : g_v);
                    float2* p = (float2*)&dst[((size_t)(b_ * HH + h) * NN + n_) * DHH + dd];
                    *p = make_float2(v0, v1);
                } else {
                    float2* p = (float2*)&outp[(size_t)row * DIMM + col];
                    *p = make_float2(v0, v1);
                }
            }
        }
    }
}

// ---------------- 3) RoPE + elu features ----------------
__global__ void rope_feat_k() {
    int gid = blockIdx.x * blockDim.y + threadIdx.y;  // (b*H+h)*N + n
    int p   = threadIdx.x;                            // pair index 0..63
    int n_  = gid & (NN - 1);
    size_t base = (size_t)gid * DHH;
    float inv = powf(10000.0f, -(float)(2 * p) * (1.0f / 128.0f));
    float ang = (float)n_ * inv;
    float s, c;
    sincosf(ang, &s, &c);
    float q0 = g_q[base + 2*p], q1 = g_q[base + 2*p + 1];
    float k0 = g_k[base + 2*p], k1 = g_k[base + 2*p + 1];
    float sq0 = q0 * SCALE_Q, sq1 = q1 * SCALE_Q;
    g_qr[base + 2*p]     = sq0 * c - sq1 * s;
    g_qr[base + 2*p + 1] = sq1 * c + sq0 * s;
    g_kr[base + 2*p]     = k0 * c - k1 * s;
    g_kr[base + 2*p + 1] = k1 * c + k0 * s;
    g_qf[base + 2*p]     = (q0 > 0.f) ? q0 + 1.f : expf(q0);
    g_qf[base + 2*p + 1] = (q1 > 0.f) ? q1 + 1.f : expf(q1);
    g_kf[base + 2*p]     = (k0 > 0.f) ? k0 + 1.f : expf(k0);
    g_kf[base + 2*p + 1] = (k1 > 0.f) ? k1 + 1.f : expf(k1);
}

// ---------------- 4) tensor-core causal flash attention ----------------
// grid (32, 16): block = 64 q-rows (it reversed for scheduling), 128 threads (4 warps x m16).
// K-tiles of 32 keys. tf32 MMA with 3-term hi/lo splits (error ~2^-22).
// smem: Qs fp32 [64][132]; Khl/Vhl hi-lo float2 [32][132]. 101376 B dynamic.
__global__ void __launch_bounds__(128) flash_tc() {
    extern __shared__ float smem_dyn[];
    float*  Qs  = smem_dyn;                               // [64][132]
    float2* Khl = (float2*)(smem_dyn + 64 * 132);         // [32][132]
    float2* Vhl = (float2*)(smem_dyn + 64 * 132 + 2 * 32 * 132);

    int bh  = blockIdx.y;
    int it  = gridDim.x - 1 - blockIdx.x;                 // longest blocks first
    int tid = threadIdx.x;
    int lane = tid & 31, w = tid >> 5;
    int r = lane >> 2, c = lane & 3;

    // load Q tile [64][128]
    const float* Qg = g_qr + ((size_t)bh * NN + it * 64) * DHH;
    for (int i = tid; i < 64 * 32; i += 128) {
        int row = i >> 5, col4 = (i & 31) * 4;
        *(float4*)&Qs[row * 132 + col4] = *(const float4*)(Qg + (size_t)row * DHH + col4);
    }

    float o[16][4];
    #pragma unroll
    for (int dt = 0; dt < 16; dt++)
        #pragma unroll
        for (int i = 0; i < 4; i++) o[dt][i] = 0.f;
    float m0 = -1e30f, m1 = -1e30f, l0 = 0.f, l1 = 0.f;
    int rg0 = it * 64 + w * 16 + r;          // this thread's first row
    int rg1 = rg0 + 8;
    int ntiles = 2 * it + 2;

    for (int jt = 0; jt < ntiles; jt++) {
        __syncthreads();                      // prev tile fully consumed
        const float* Kg = g_kr + ((size_t)bh * NN + jt * 32) * DHH;
        const float* Vg = g_v  + ((size_t)bh * NN + jt * 32) * DHH;
        for (int i = tid; i < 32 * 32; i += 128) {
            int row = i >> 5, col4 = (i & 31) * 4;
            float4 kv = *(const float4*)(Kg + (size_t)row * DHH + col4);
            float4 vv = *(const float4*)(Vg + (size_t)row * DHH + col4);
            float h;
            h = tf32f(kv.x); Khl[row*132 + col4+0] = make_float2(h, tf32f(kv.x - h));
            h = tf32f(kv.y); Khl[row*132 + col4+1] = make_float2(h, tf32f(kv.y - h));
            h = tf32f(kv.z); Khl[row*132 + col4+2] = make_float2(h, tf32f(kv.z - h));
            h = tf32f(kv.w); Khl[row*132 + col4+3] = make_float2(h, tf32f(kv.w - h));
            h = tf32f(vv.x); Vhl[row*132 + col4+0] = make_float2(h, tf32f(vv.x - h));
            h = tf32f(vv.y); Vhl[row*132 + col4+1] = make_float2(h, tf32f(vv.y - h));
            h = tf32f(vv.z); Vhl[row*132 + col4+2] = make_float2(h, tf32f(vv.z - h));
            h = tf32f(vv.w); Vhl[row*132 + col4+3] = make_float2(h, tf32f(vv.w - h));
        }
        __syncthreads();

        // warps 0,1 are fully masked on the last (odd diagonal) tile
        if (jt == 2 * it + 1 && w < 2) continue;

        // ---- S = Qr @ Kr^T (3-term tf32) ----
        float s[4][4];
        #pragma unroll
        for (int nt = 0; nt < 4; nt++)
            #pragma unroll
            for (int i = 0; i < 4; i++) s[nt][i] = 0.f;

        #pragma unroll 4
        for (int ks = 0; ks < 16; ks++) {
            float qa0 = Qs[(w*16 + r    ) * 132 + ks*8 + c];
            float qa1 = Qs[(w*16 + r + 8) * 132 + ks*8 + c];
            float qa2 = Qs[(w*16 + r    ) * 132 + ks*8 + c + 4];
            float qa3 = Qs[(w*16 + r + 8) * 132 + ks*8 + c + 4];
            uint32_t ah[4], al[4];
            ah[0] = f2tf32(qa0); al[0] = f2tf32(qa0 - __uint_as_float(ah[0]));
            ah[1] = f2tf32(qa1); al[1] = f2tf32(qa1 - __uint_as_float(ah[1]));
            ah[2] = f2tf32(qa2); al[2] = f2tf32(qa2 - __uint_as_float(ah[2]));
            ah[3] = f2tf32(qa3); al[3] = f2tf32(qa3 - __uint_as_float(ah[3]));
            #pragma unroll
            for (int nt = 0; nt < 4; nt++) {
                float2 b0 = Khl[(nt*8 + r) * 132 + ks*8 + c];
                float2 b1 = Khl[(nt*8 + r) * 132 + ks*8 + c + 4];
                uint32_t bh_[2] = { __float_as_uint(b0.x), __float_as_uint(b1.x) };
                uint32_t bl_[2] = { __float_as_uint(b0.y), __float_as_uint(b1.y) };
                mma_tf32(s[nt], ah, bh_);
                mma_tf32(s[nt], ah, bl_);
                mma_tf32(s[nt], al, bh_);
            }
        }

        // ---- causal mask ----
        if (jt * 32 + 31 > rg0) {
            #pragma unroll
            for (int nt = 0; nt < 4; nt++) {
                int cg = jt * 32 + nt * 8 + 2 * c;
                if (cg     > rg0) s[nt][0] = -1e30f;
                if (cg + 1 > rg0) s[nt][1] = -1e30f;
                if (cg     > rg1) s[nt][2] = -1e30f;
                if (cg + 1 > rg1) s[nt][3] = -1e30f;
            }
        }

        // ---- online softmax ----
        float tmax0 = -1e30f, tmax1 = -1e30f;
        #pragma unroll
        for (int nt = 0; nt < 4; nt++) {
            tmax0 = fmaxf(tmax0, fmaxf(s[nt][0], s[nt][1]));
            tmax1 = fmaxf(tmax1, fmaxf(s[nt][2], s[nt][3]));
        }
        tmax0 = fmaxf(tmax0, __shfl_xor_sync(0xffffffffu, tmax0, 1));
        tmax0 = fmaxf(tmax0, __shfl_xor_sync(0xffffffffu, tmax0, 2));
        tmax1 = fmaxf(tmax1, __shfl_xor_sync(0xffffffffu, tmax1, 1));
        tmax1 = fmaxf(tmax1, __shfl_xor_sync(0xffffffffu, tmax1, 2));
        float mn0 = fmaxf(m0, tmax0), mn1 = fmaxf(m1, tmax1);
        float al0 = __expf(m0 - mn0), al1 = __expf(m1 - mn1);
        float ps0 = 0.f, ps1 = 0.f;
        #pragma unroll
        for (int nt = 0; nt < 4; nt++) {
            s[nt][0] = __expf(s[nt][0] - mn0);
            s[nt][1] = __expf(s[nt][1] - mn0);
            s[nt][2] = __expf(s[nt][2] - mn1);
            s[nt][3] = __expf(s[nt][3] - mn1);
            ps0 += s[nt][0] + s[nt][1];
            ps1 += s[nt][2] + s[nt][3];
        }
        ps0 += __shfl_xor_sync(0xffffffffu, ps0, 1);
        ps0 += __shfl_xor_sync(0xffffffffu, ps0, 2);
        ps1 += __shfl_xor_sync(0xffffffffu, ps1, 1);
        ps1 += __shfl_xor_sync(0xffffffffu, ps1, 2);
        l0 = l0 * al0 + ps0;  l1 = l1 * al1 + ps1;
        m0 = mn0;  m1 = mn1;
        if (__any_sync(0xffffffffu, (al0 < 1.f) | (al1 < 1.f))) {
            #pragma unroll
            for (int dt = 0; dt < 16; dt++) {
                o[dt][0] *= al0; o[dt][1] *= al0;
                o[dt][2] *= al1; o[dt][3] *= al1;
            }
        }

        // ---- O += P @ V (P frag->A frag via quad shuffles; 3-term) ----
        int sA = (lane & ~3) | (c >> 1);
        int sB = sA + 2;
        #pragma unroll
        for (int nt = 0; nt < 4; nt++) {
            float t00 = __shfl_sync(0xffffffffu, s[nt][0], sA);
            float t01 = __shfl_sync(0xffffffffu, s[nt][1], sA);
            float u00 = __shfl_sync(0xffffffffu, s[nt][0], sB);
            float u01 = __shfl_sync(0xffffffffu, s[nt][1], sB);
            float t10 = __shfl_sync(0xffffffffu, s[nt][2], sA);
            float t11 = __shfl_sync(0xffffffffu, s[nt][3], sA);
            float u10 = __shfl_sync(0xffffffffu, s[nt][2], sB);
            float u11 = __shfl_sync(0xffffffffu, s[nt][3], sB);
            float a0 = (c & 1) ? t01 : t00;    // P[r][c]
            float a2 = (c & 1) ? u01 : u00;    // P[r][c+4]
            float a1 = (c & 1) ? t11 : t10;    // P[r+8][c]
            float a3 = (c & 1) ? u11 : u10;    // P[r+8][c+4]
            uint32_t ph[4], pl[4];
            ph[0] = f2tf32(a0); pl[0] = f2tf32(a0 - __uint_as_float(ph[0]));
            ph[1] = f2tf32(a1); pl[1] = f2tf32(a1 - __uint_as_float(ph[1]));
            ph[2] = f2tf32(a2); pl[2] = f2tf32(a2 - __uint_as_float(ph[2]));
            ph[3] = f2tf32(a3); pl[3] = f2tf32(a3 - __uint_as_float(ph[3]));
            #pragma unroll
            for (int dt = 0; dt < 16; dt++) {
                float2 v0 = Vhl[(nt*8 + c    ) * 132 + dt*8 + r];
                float2 v1 = Vhl[(nt*8 + c + 4) * 132 + dt*8 + r];
                uint32_t vh_[2] = { __float_as_uint(v0.x), __float_as_uint(v1.x) };
                uint32_t vl_[2] = { __float_as_uint(v0.y), __float_as_uint(v1.y) };
                mma_tf32(o[dt], ph, vh_);
                mma_tf32(o[dt], ph, vl_);
                mma_tf32(o[dt], pl, vh_);
            }
        }
    }

    // ---- epilogue ----
    float il0 = 1.f / l0, il1 = 1.f / l1;
    float* O0 = g_attn + ((size_t)bh * NN + it * 64 + w * 16 + r    ) * DHH;
    float* O1 = g_attn + ((size_t)bh * NN + it * 64 + w * 16 + r + 8) * DHH;
    #pragma unroll
    for (int dt = 0; dt < 16; dt++) {
        *(float2*)&O0[dt * 8 + 2 * c] = make_float2(o[dt][0] * il0, o[dt][1] * il0);
        *(float2*)&O1[dt * 8 + 2 * c] = make_float2(o[dt][2] * il1, o[dt][3] * il1);
    }
}

// ---------------- 5) memory retrieval + gate blend -> g_comb [b,n,h*d] ----------------
__global__ void retrieve_gate_k(const float* __restrict__ mem_kv,
                                const float* __restrict__ mem_norm,
                                const float* __restrict__ head_gates) {
    int bh = blockIdx.y;
    int b_ = bh >> 3, h = bh & 7;
    int t0 = blockIdx.x * 32;
    int v  = threadIdx.x;
    __shared__ float qsT[128][36];
    __shared__ float dn[32];
    __shared__ float mn[128];
    mn[v] = mem_norm[bh * DHH + v];
    const float* qf = g_qf + ((size_t)bh * NN + t0) * DHH;
    for (int i = v; i < 32 * 32; i += 128) {
        int t = i >> 5;
        int k4 = (i & 31) * 4;
        float4 qv = *(const float4*)(qf + (size_t)t * DHH + k4);
        qsT[k4+0][t] = qv.x; qsT[k4+1][t] = qv.y; qsT[k4+2][t] = qv.z; qsT[k4+3][t] = qv.w;
    }
    __syncthreads();
    if (v < 32) {
        float s = 0.f;
        #pragma unroll 8
        for (int k = 0; k < 128; k++) s += qsT[k][v] * mn[k];
        dn[v] = fmaxf(s, EPSV);
    }
    __syncthreads();
    const float* mkv = mem_kv + (size_t)bh * DHH * DHH;
    float num[32];
    #pragma unroll
    for (int t = 0; t < 32; t++) num[t] = 0.f;
    for (int k = 0; k < 128; k++) {
        float mval = mkv[k * DHH + v];
        #pragma unroll
        for (int t8 = 0; t8 < 8; t8++) {
            float4 qv = *(const float4*)&qsT[k][t8 * 4];
            num[t8*4+0] += qv.x * mval;
            num[t8*4+1] += qv.y * mval;
            num[t8*4+2] += qv.z * mval;
            num[t8*4+3] += qv.w * mval;
        }
    }
    float g = 1.f / (1.f + expf(-head_gates[h]));
    const float* at = g_attn + ((size_t)bh * NN + t0) * DHH;
    float* cb = g_comb + ((size_t)b_ * NN + t0) * DIMM + h * DHH;
    #pragma unroll 4
    for (int t = 0; t < 32; t++) {
        float mo = num[t] / dn[t];
        cb[(size_t)t * DIMM + v] = at[(size_t)t * DHH + v] * g + mo * (1.f - g);
    }
}

// ---------------- 7) delta-rule new_kv (split 4x over v-dim) ----------------
__global__ void __launch_bounds__(256) newkv_k(const float* __restrict__ mem_kv,
                                               const float* __restrict__ mem_norm,
                                               float* __restrict__ out_kv) {
    int bh    = blockIdx.x;
    int vbase = blockIdx.y * 32;
    int tid   = threadIdx.x;
    int ty = tid >> 3, tx = tid & 7;
    __shared__ float kfs[32][128];
    __shared__ float vns[32][32];
    __shared__ float mn[128];
    __shared__ float dns[32];
    if (tid < 128) mn[tid] = mem_norm[bh * DHH + tid];
    const float* mkv = mem_kv + (size_t)bh * DHH * DHH;
    const float* kfb = g_kf + (size_t)bh * NN * DHH;
    const float* vb  = g_v  + (size_t)bh * NN * DHH;
    float C[4][4];
    #pragma unroll
    for (int i = 0; i < 4; i++)
        #pragma unroll
        for (int j = 0; j < 4; j++) C[i][j] = 0.f;

    int vlane = tid & 31, tg = tid >> 5;

    for (int t0 = 0; t0 < NN; t0 += 32) {
        __syncthreads();
        #pragma unroll
        for (int i = 0; i < 4; i++) {
            int idx = tid + i * 256;
            int t = idx >> 5, kq = (idx & 31) * 4;
            *(float4*)&kfs[t][kq] = *(const float4*)(kfb + (size_t)(t0 + t) * DHH + kq);
        }
        {
            int t = tid >> 3, vq = (tid & 7) * 4;
            *(float4*)&vns[t][vq] = *(const float4*)(vb + (size_t)(t0 + t) * DHH + vbase + vq);
        }
        __syncthreads();
        if (tid < 32) {
            float s = 0.f;
            #pragma unroll 8
            for (int k = 0; k < 128; k++) {
                int kk = (k + tid) & 127;
                s += kfs[tid][kk] * mn[kk];
            }
            dns[tid] = fmaxf(s, EPSV);
        }
        __syncthreads();
        {
            float numv[4] = {0.f, 0.f, 0.f, 0.f};
            for (int k = 0; k < 128; k++) {
                float mval = mkv[k * DHH + vbase + vlane];
                #pragma unroll
                for (int j = 0; j < 4; j++) numv[j] += kfs[tg * 4 + j][k] * mval;
            }
            #pragma unroll
            for (int j = 0; j < 4; j++) vns[tg * 4 + j][vlane] -= numv[j] / dns[tg * 4 + j];
        }
        __syncthreads();
        #pragma unroll 4
        for (int t = 0; t < 32; t++) {
            float4 a = *(const float4*)&kfs[t][ty * 4];
            float4 b = *(const float4*)&vns[t][tx * 4];
            float av[4] = {a.x, a.y, a.z, a.w};
            float bv[4] = {b.x, b.y, b.z, b.w};
            #pragma unroll
            for (int i = 0; i < 4; i++)
                #pragma unroll
                for (int j = 0; j < 4; j++) C[i][j] += av[i] * bv[j];
        }
    }
    #pragma unroll
    for (int i = 0; i < 4; i++)
        #pragma unroll
        for (int j = 0; j < 4; j++) {
            int kd = ty * 4 + i, vd = vbase + tx * 4 + j;
            out_kv[(size_t)bh * DHH * DHH + kd * DHH + vd] = C[i][j] + mkv[kd * DHH + vd];
        }
}

// ---------------- 8) new_norm: two-stage parallel sum ----------------
__global__ void newnorm_part_k() {
    int bh = blockIdx.x, ch = blockIdx.y;
    int k  = threadIdx.x;
    const float* kf = g_kf + (size_t)bh * NN * DHH + (size_t)ch * 256 * DHH;
    float s = 0.f;
    #pragma unroll 8
    for (int n_ = 0; n_ < 256; n_++) s += kf[(size_t)n_ * DHH + k];
    g_pnorm[((size_t)bh * 8 + ch) * DHH + k] = s;
}
__global__ void newnorm_red_k(const float* __restrict__ mem_norm, float* __restrict__ out_norm) {
    int bh = blockIdx.x;
    int k  = threadIdx.x;
    float s = mem_norm[bh * DHH + k];
    #pragma unroll
    for (int c = 0; c < 8; c++) s += g_pnorm[((size_t)bh * 8 + c) * DHH + k];
    out_norm[bh * DHH + k] = s;
}

// ---------------- launch ----------------
extern "C" void kernel_launch(void* const* d_in, const int* in_sizes, int n_in,
                              void* d_out, int out_size) {
    (void)in_sizes; (void)n_in; (void)out_size;
    const float* x          = (const float*)d_in[0];
    const float* gamma      = (const float*)d_in[1];
    const float* w_qkv      = (const float*)d_in[2];
    const float* w_out      = (const float*)d_in[3];
    const float* head_gates = (const float*)d_in[4];
    const float* mem_kv     = (const float*)d_in[5];
    const float* mem_norm   = (const float*)d_in[6];
    float* out      = (float*)d_out;
    float* out_kv   = out + (size_t)BB * NN * DIMM;
    float* out_norm = out_kv + BB * HH * DHH * DHH;

    const int FLASH_SMEM = (64 * 132 + 2 * 32 * 132 * 2) * 4;   // 101376 B
    cudaFuncSetAttribute(flash_tc, cudaFuncAttributeMaxDynamicSharedMemorySize, FLASH_SMEM);

    rmsnorm_k<<<BB * NN, 256>>>(x, gamma);
    sgemm_tc<<<dim3(S3 / 128, BB * NN / 128), 256>>>(0, w_qkv, nullptr);
    rope_feat_k<<<BB * HH * NN / 4, dim3(64, 4)>>>();
    flash_tc<<<dim3(NN / 64, BB * HH), 128, FLASH_SMEM>>>();
    retrieve_gate_k<<<dim3(NN / 32, BB * HH), 128>>>(mem_kv, mem_norm, head_gates);
    sgemm_tc<<<dim3(DIMM / 128, BB * NN / 128), 256>>>(1, w_out, out);
    newkv_k<<<dim3(BB * HH, 4), 256>>>(mem_kv, mem_norm, out_kv);
    newnorm_part_k<<<dim3(BB * HH, 8), 128>>>();
    newnorm_red_k<<<BB * HH, 128>>>(mem_norm, out_norm);
}

// round 8
// speedup vs baseline: 2.7222x; 1.0250x over previous
#include <cuda_runtime.h>
#include <math.h>
#include <stdint.h>

#define BB   2
#define NN   2048
#define DIMM 1024
#define HH   8
#define DHH  128
#define S3   (3*DIMM)
#define SCALE_Q 0.08838834764831845f
#define EPSV 1e-10f

// ---------------- scratch (static device globals; no allocation) ----------------
__device__ float g_xn  [BB*NN*DIMM];
__device__ float g_q   [BB*HH*NN*DHH];
__device__ float g_k   [BB*HH*NN*DHH];
__device__ float g_v   [BB*HH*NN*DHH];
__device__ float g_qr  [BB*HH*NN*DHH];
__device__ float g_qf  [BB*HH*NN*DHH];
__device__ float g_kf  [BB*HH*NN*DHH];
__device__ float g_attn[BB*HH*NN*DHH];
__device__ float g_comb[BB*NN*DIMM];
__device__ float g_pnorm[BB*HH*8*DHH];
__device__ float2 g_krhl[BB*HH*NN*DHH];   // pre-split rotated K (tf32 hi, lo)
__device__ float2 g_vhl [BB*HH*NN*DHH];   // pre-split V

// ---------------- helpers ----------------
__device__ __forceinline__ uint32_t f2tf32(float f) {
    uint32_t r;
    asm("cvt.rna.tf32.f32 %0, %1;" : "=r"(r) : "f"(f));
    return r;
}
__device__ __forceinline__ float tf32f(float f) { return __uint_as_float(f2tf32(f)); }

__device__ __forceinline__ void mma_tf32(float* d, const uint32_t* a, const uint32_t* b) {
    asm volatile(
        "mma.sync.aligned.m16n8k8.row.col.f32.tf32.tf32.f32 "
        "{%0,%1,%2,%3}, {%4,%5,%6,%7}, {%8,%9}, {%0,%1,%2,%3};\n"
        : "+f"(d[0]), "+f"(d[1]), "+f"(d[2]), "+f"(d[3])
        : "r"(a[0]), "r"(a[1]), "r"(a[2]), "r"(a[3]), "r"(b[0]), "r"(b[1]));
}

// ---------------- 1) RMSNorm ----------------
__global__ void rmsnorm_k(const float* __restrict__ x, const float* __restrict__ gamma) {
    int row = blockIdx.x;
    const float* xr = x + (size_t)row * DIMM;
    float ss = 0.f;
    for (int i = threadIdx.x; i < DIMM; i += 256) { float v = xr[i]; ss += v * v; }
    #pragma unroll
    for (int o = 16; o > 0; o >>= 1) ss += __shfl_xor_sync(0xffffffffu, ss, o);
    __shared__ float red[8];
    __shared__ float sinv;
    if ((threadIdx.x & 31) == 0) red[threadIdx.x >> 5] = ss;
    __syncthreads();
    if (threadIdx.x == 0) {
        float t = 0.f;
        #pragma unroll
        for (int i = 0; i < 8; i++) t += red[i];
        sinv = 32.0f / fmaxf(sqrtf(t), 1e-12f);
    }
    __syncthreads();
    float inv = sinv;
    float* o = g_xn + (size_t)row * DIMM;
    for (int i = threadIdx.x; i < DIMM; i += 256) o[i] = xr[i] * inv * gamma[i];
}

// ---------------- 2/6) tf32 tensor-core GEMM  C = A @ W^T ----------------
__global__ void __launch_bounds__(256) sgemm_tc(int mode, const float* __restrict__ W,
                                                float* __restrict__ outp) {
    const float* A = (mode == 0) ? g_xn : g_comb;
    const int K = DIMM;
    __shared__ uint32_t As[128][36];
    __shared__ uint32_t Bs[128][36];
    int tid  = threadIdx.x;
    int lane = tid & 31, warp = tid >> 5;
    int wm = warp >> 2, wn = warp & 3;
    int r  = lane >> 2, cc = lane & 3;

    float acc[4][4][4];
    #pragma unroll
    for (int mt = 0; mt < 4; mt++)
        #pragma unroll
        for (int nt = 0; nt < 4; nt++)
            #pragma unroll
            for (int i = 0; i < 4; i++) acc[mt][nt][i] = 0.f;

    size_t aBase = (size_t)(blockIdx.y * 128) * K;
    size_t bBase = (size_t)(blockIdx.x * 128) * K;

    for (int k0 = 0; k0 < K; k0 += 32) {
        #pragma unroll
        for (int i = 0; i < 4; i++) {
            int idx = tid + i * 256;
            int row = idx >> 3;
            int kq  = (idx & 7) * 4;
            float4 av = *(const float4*)(A + aBase + (size_t)row * K + k0 + kq);
            float4 bv = *(const float4*)(W + bBase + (size_t)row * K + k0 + kq);
            *(uint4*)&As[row][kq] = make_uint4(f2tf32(av.x), f2tf32(av.y), f2tf32(av.z), f2tf32(av.w));
            *(uint4*)&Bs[row][kq] = make_uint4(f2tf32(bv.x), f2tf32(bv.y), f2tf32(bv.z), f2tf32(bv.w));
        }
        __syncthreads();
        #pragma unroll
        for (int ks = 0; ks < 32; ks += 8) {
            uint32_t af[4][4], bf[4][2];
            #pragma unroll
            for (int mt = 0; mt < 4; mt++) {
                int m0 = wm * 64 + mt * 16;
                af[mt][0] = As[m0 + r    ][ks + cc];
                af[mt][1] = As[m0 + r + 8][ks + cc];
                af[mt][2] = As[m0 + r    ][ks + cc + 4];
                af[mt][3] = As[m0 + r + 8][ks + cc + 4];
            }
            #pragma unroll
            for (int nt = 0; nt < 4; nt++) {
                int n0 = wn * 32 + nt * 8;
                bf[nt][0] = Bs[n0 + r][ks + cc];
                bf[nt][1] = Bs[n0 + r][ks + cc + 4];
            }
            #pragma unroll
            for (int mt = 0; mt < 4; mt++)
                #pragma unroll
                for (int nt = 0; nt < 4; nt++)
                    mma_tf32(acc[mt][nt], af[mt], bf[nt]);
        }
        __syncthreads();
    }

    #pragma unroll
    for (int mt = 0; mt < 4; mt++) {
        #pragma unroll
        for (int half = 0; half < 2; half++) {
            int row = blockIdx.y * 128 + wm * 64 + mt * 16 + r + half * 8;
            #pragma unroll
            for (int nt = 0; nt < 4; nt++) {
                int col = blockIdx.x * 128 + wn * 32 + nt * 8 + 2 * cc;
                float v0 = acc[mt][nt][half * 2 + 0];
                float v1 = acc[mt][nt][half * 2 + 1];
                if (mode == 0) {
                    int b_ = row >> 11, n_ = row & (NN - 1);
                    int sel = col >> 10, rem = col & 1023;
                    int h = rem >> 7, dd = rem & 127;
                    float* dst = (sel == 0) ? g_q : ((sel == 1) ? g_k : g_v);
                    float2* p = (float2*)&dst[((size_t)(b_ * HH + h) * NN + n_) * DHH + dd];
                    *p = make_float2(v0, v1);
                } else {
                    float2* p = (float2*)&outp[(size_t)row * DIMM + col];
                    *p = make_float2(v0, v1);
                }
            }
        }
    }
}

// ---------------- 3) RoPE + elu features + tf32 hi/lo pre-split of K_rot and V ----------------
__global__ void rope_feat_k() {
    int gid = blockIdx.x * blockDim.y + threadIdx.y;  // (b*H+h)*N + n
    int p   = threadIdx.x;                            // pair index 0..63
    int n_  = gid & (NN - 1);
    size_t base = (size_t)gid * DHH;
    float inv = powf(10000.0f, -(float)(2 * p) * (1.0f / 128.0f));
    float ang = (float)n_ * inv;
    float s, c;
    sincosf(ang, &s, &c);
    float q0 = g_q[base + 2*p], q1 = g_q[base + 2*p + 1];
    float k0 = g_k[base + 2*p], k1 = g_k[base + 2*p + 1];
    float sq0 = q0 * SCALE_Q, sq1 = q1 * SCALE_Q;
    g_qr[base + 2*p]     = sq0 * c - sq1 * s;
    g_qr[base + 2*p + 1] = sq1 * c + sq0 * s;
    float kr0 = k0 * c - k1 * s;
    float kr1 = k1 * c + k0 * s;
    float h;
    h = tf32f(kr0); g_krhl[base + 2*p]     = make_float2(h, tf32f(kr0 - h));
    h = tf32f(kr1); g_krhl[base + 2*p + 1] = make_float2(h, tf32f(kr1 - h));
    float v0 = g_v[base + 2*p], v1 = g_v[base + 2*p + 1];
    h = tf32f(v0); g_vhl[base + 2*p]     = make_float2(h, tf32f(v0 - h));
    h = tf32f(v1); g_vhl[base + 2*p + 1] = make_float2(h, tf32f(v1 - h));
    g_qf[base + 2*p]     = (q0 > 0.f) ? q0 + 1.f : expf(q0);
    g_qf[base + 2*p + 1] = (q1 > 0.f) ? q1 + 1.f : expf(q1);
    g_kf[base + 2*p]     = (k0 > 0.f) ? k0 + 1.f : expf(k0);
    g_kf[base + 2*p + 1] = (k1 > 0.f) ? k1 + 1.f : expf(k1);
}

// ---------------- 4) tensor-core causal flash attention, split-K warp groups ----------------
// grid (32,16), 256 threads = 8 warps. 64 q-rows/block.
// Group wg=0 (warps 0-3): keys 0-15 of each 32-key tile; wg=1: keys 16-31.
// Each group keeps private (m,l,O); exact log-sum-exp merge in epilogue via smem.
// smem: Qs fp32 [64][132] | Khl float2 [32][132] | Vhl float2 [32][132] | m,l [2][64]x2
__global__ void __launch_bounds__(256, 2) flash_tc() {
    extern __shared__ float sm[];
    float*  Qs   = sm;                          // 8448 floats
    float2* Khl  = (float2*)(sm + 8448);        // 8448 floats
    float2* Vhl  = (float2*)(sm + 16896);       // 8448 floats
    float*  sm_m = sm + 25344;                  // 128
    float*  sm_l = sm + 25472;                  // 128

    int bh  = blockIdx.y;
    int it  = gridDim.x - 1 - blockIdx.x;
    int tid = threadIdx.x;
    int lane = tid & 31, warp = tid >> 5;
    int wg = warp >> 2, wq = warp & 3;
    int r = lane >> 2, c = lane & 3;

    const float* Qg = g_qr + ((size_t)bh * NN + it * 64) * DHH;
    for (int i = tid; i < 64 * 32; i += 256) {
        int row = i >> 5, col4 = (i & 31) * 4;
        *(float4*)&Qs[row * 132 + col4] = *(const float4*)(Qg + (size_t)row * DHH + col4);
    }

    float o[16][4];
    #pragma unroll
    for (int dt = 0; dt < 16; dt++)
        #pragma unroll
        for (int i = 0; i < 4; i++) o[dt][i] = 0.f;
    float m0 = -1e30f, m1 = -1e30f, l0 = 0.f, l1 = 0.f;
    int rg0 = it * 64 + wq * 16 + r;
    int rg1 = rg0 + 8;
    int rowmax = it * 64 + wq * 16 + 15;
    int rowmin = it * 64 + wq * 16;
    int ntiles = 2 * it + 2;

    for (int jt = 0; jt < ntiles; jt++) {
        __syncthreads();
        const float4* Kg = (const float4*)(g_krhl + ((size_t)bh * NN + jt * 32) * DHH);
        const float4* Vg = (const float4*)(g_vhl  + ((size_t)bh * NN + jt * 32) * DHH);
        for (int i = tid; i < 2048; i += 256) {          // 32 rows x 64 float4
            int row = i >> 6, q4 = i & 63;
            ((float4*)&Khl[row * 132])[q4] = Kg[row * 64 + q4];
            ((float4*)&Vhl[row * 132])[q4] = Vg[row * 64 + q4];
        }
        __syncthreads();

        int kmin = jt * 32 + wg * 16;                    // this group's first key
        if (kmin > rowmax) continue;                     // fully masked for this warp

        // ---- S = Qr @ Kr^T over this group's 16 keys (3-term tf32) ----
        float s[2][4];
        #pragma unroll
        for (int nt = 0; nt < 2; nt++)
            #pragma unroll
            for (int i = 0; i < 4; i++) s[nt][i] = 0.f;

        #pragma unroll 4
        for (int ks = 0; ks < 16; ks++) {
            float qa0 = Qs[(wq*16 + r    ) * 132 + ks*8 + c];
            float qa1 = Qs[(wq*16 + r + 8) * 132 + ks*8 + c];
            float qa2 = Qs[(wq*16 + r    ) * 132 + ks*8 + c + 4];
            float qa3 = Qs[(wq*16 + r + 8) * 132 + ks*8 + c + 4];
            uint32_t ah[4], al[4];
            ah[0] = f2tf32(qa0); al[0] = f2tf32(qa0 - __uint_as_float(ah[0]));
            ah[1] = f2tf32(qa1); al[1] = f2tf32(qa1 - __uint_as_float(ah[1]));
            ah[2] = f2tf32(qa2); al[2] = f2tf32(qa2 - __uint_as_float(ah[2]));
            ah[3] = f2tf32(qa3); al[3] = f2tf32(qa3 - __uint_as_float(ah[3]));
            #pragma unroll
            for (int nt = 0; nt < 2; nt++) {
                float2 b0 = Khl[(wg*16 + nt*8 + r) * 132 + ks*8 + c];
                float2 b1 = Khl[(wg*16 + nt*8 + r) * 132 + ks*8 + c + 4];
                uint32_t bh_[2] = { __float_as_uint(b0.x), __float_as_uint(b1.x) };
                uint32_t bl_[2] = { __float_as_uint(b0.y), __float_as_uint(b1.y) };
                mma_tf32(s[nt], ah, bh_);
                mma_tf32(s[nt], ah, bl_);
                mma_tf32(s[nt], al, bh_);
            }
        }

        // ---- causal mask (only near diagonal) ----
        if (kmin + 15 > rowmin) {
            #pragma unroll
            for (int nt = 0; nt < 2; nt++) {
                int cg = kmin + nt * 8 + 2 * c;
                if (cg     > rg0) s[nt][0] = -1e30f;
                if (cg + 1 > rg0) s[nt][1] = -1e30f;
                if (cg     > rg1) s[nt][2] = -1e30f;
                if (cg + 1 > rg1) s[nt][3] = -1e30f;
            }
        }

        // ---- online softmax (group-private) ----
        float tmax0 = fmaxf(fmaxf(s[0][0], s[0][1]), fmaxf(s[1][0], s[1][1]));
        float tmax1 = fmaxf(fmaxf(s[0][2], s[0][3]), fmaxf(s[1][2], s[1][3]));
        tmax0 = fmaxf(tmax0, __shfl_xor_sync(0xffffffffu, tmax0, 1));
        tmax0 = fmaxf(tmax0, __shfl_xor_sync(0xffffffffu, tmax0, 2));
        tmax1 = fmaxf(tmax1, __shfl_xor_sync(0xffffffffu, tmax1, 1));
        tmax1 = fmaxf(tmax1, __shfl_xor_sync(0xffffffffu, tmax1, 2));
        float mn0 = fmaxf(m0, tmax0), mn1 = fmaxf(m1, tmax1);
        float al0 = __expf(m0 - mn0), al1 = __expf(m1 - mn1);
        float ps0 = 0.f, ps1 = 0.f;
        #pragma unroll
        for (int nt = 0; nt < 2; nt++) {
            s[nt][0] = __expf(s[nt][0] - mn0);
            s[nt][1] = __expf(s[nt][1] - mn0);
            s[nt][2] = __expf(s[nt][2] - mn1);
            s[nt][3] = __expf(s[nt][3] - mn1);
            ps0 += s[nt][0] + s[nt][1];
            ps1 += s[nt][2] + s[nt][3];
        }
        ps0 += __shfl_xor_sync(0xffffffffu, ps0, 1);
        ps0 += __shfl_xor_sync(0xffffffffu, ps0, 2);
        ps1 += __shfl_xor_sync(0xffffffffu, ps1, 1);
        ps1 += __shfl_xor_sync(0xffffffffu, ps1, 2);
        l0 = l0 * al0 + ps0;  l1 = l1 * al1 + ps1;
        m0 = mn0;  m1 = mn1;
        if (__any_sync(0xffffffffu, (al0 < 1.f) | (al1 < 1.f))) {
            #pragma unroll
            for (int dt = 0; dt < 16; dt++) {
                o[dt][0] *= al0; o[dt][1] *= al0;
                o[dt][2] *= al1; o[dt][3] *= al1;
            }
        }

        // ---- O += P @ V (P C-frag -> A-frag via quad shuffles; 3-term) ----
        int sA = (lane & ~3) | (c >> 1);
        int sB = sA + 2;
        #pragma unroll
        for (int nt = 0; nt < 2; nt++) {
            float t00 = __shfl_sync(0xffffffffu, s[nt][0], sA);
            float t01 = __shfl_sync(0xffffffffu, s[nt][1], sA);
            float u00 = __shfl_sync(0xffffffffu, s[nt][0], sB);
            float u01 = __shfl_sync(0xffffffffu, s[nt][1], sB);
            float t10 = __shfl_sync(0xffffffffu, s[nt][2], sA);
            float t11 = __shfl_sync(0xffffffffu, s[nt][3], sA);
            float u10 = __shfl_sync(0xffffffffu, s[nt][2], sB);
            float u11 = __shfl_sync(0xffffffffu, s[nt][3], sB);
            float a0 = (c & 1) ? t01 : t00;
            float a2 = (c & 1) ? u01 : u00;
            float a1 = (c & 1) ? t11 : t10;
            float a3 = (c & 1) ? u11 : u10;
            uint32_t ph[4], pl[4];
            ph[0] = f2tf32(a0); pl[0] = f2tf32(a0 - __uint_as_float(ph[0]));
            ph[1] = f2tf32(a1); pl[1] = f2tf32(a1 - __uint_as_float(ph[1]));
            ph[2] = f2tf32(a2); pl[2] = f2tf32(a2 - __uint_as_float(ph[2]));
            ph[3] = f2tf32(a3); pl[3] = f2tf32(a3 - __uint_as_float(ph[3]));
            #pragma unroll
            for (int dt = 0; dt < 16; dt++) {
                float2 v0 = Vhl[(wg*16 + nt*8 + c    ) * 132 + dt*8 + r];
                float2 v1 = Vhl[(wg*16 + nt*8 + c + 4) * 132 + dt*8 + r];
                uint32_t vh_[2] = { __float_as_uint(v0.x), __float_as_uint(v1.x) };
                uint32_t vl_[2] = { __float_as_uint(v0.y), __float_as_uint(v1.y) };
                mma_tf32(o[dt], ph, vh_);
                mma_tf32(o[dt], ph, vl_);
                mma_tf32(o[dt], pl, vh_);
            }
        }
    }

    // ---- cross-group merge epilogue ----
    int lr0 = wq * 16 + r;
    __syncthreads();
    if (c == 0) {
        sm_m[wg * 64 + lr0]     = m0;  sm_l[wg * 64 + lr0]     = l0;
        sm_m[wg * 64 + lr0 + 8] = m1;  sm_l[wg * 64 + lr0 + 8] = l1;
    }
    __syncthreads();
    float mo0 = sm_m[(1 - wg) * 64 + lr0],     lo0 = sm_l[(1 - wg) * 64 + lr0];
    float mo1 = sm_m[(1 - wg) * 64 + lr0 + 8], lo1 = sm_l[(1 - wg) * 64 + lr0 + 8];
    float mg0 = fmaxf(m0, mo0), mg1 = fmaxf(m1, mo1);
    float lg0 = l0 * __expf(m0 - mg0) + lo0 * __expf(mo0 - mg0);
    float lg1 = l1 * __expf(m1 - mg1) + lo1 * __expf(mo1 - mg1);
    float sc0 = __expf(m0 - mg0) / lg0;
    float sc1 = __expf(m1 - mg1) / lg1;

    float* Obuf = Qs;                                   // Q region reused
    if (wg == 1) {
        #pragma unroll
        for (int dt = 0; dt < 16; dt++) {
            *(float2*)&Obuf[lr0 * 132 + dt*8 + 2*c]       = make_float2(o[dt][0]*sc0, o[dt][1]*sc0);
            *(float2*)&Obuf[(lr0+8) * 132 + dt*8 + 2*c]   = make_float2(o[dt][2]*sc1, o[dt][3]*sc1);
        }
    }
    __syncthreads();
    if (wg == 0) {
        float* O0 = g_attn + ((size_t)bh * NN + it * 64 + lr0    ) * DHH;
        float* O1 = g_attn + ((size_t)bh * NN + it * 64 + lr0 + 8) * DHH;
        #pragma unroll
        for (int dt = 0; dt < 16; dt++) {
            float2 b0 = *(float2*)&Obuf[lr0 * 132 + dt*8 + 2*c];
            float2 b1 = *(float2*)&Obuf[(lr0+8) * 132 + dt*8 + 2*c];
            *(float2*)&O0[dt*8 + 2*c] = make_float2(o[dt][0]*sc0 + b0.x, o[dt][1]*sc0 + b0.y);
            *(float2*)&O1[dt*8 + 2*c] = make_float2(o[dt][2]*sc1 + b1.x, o[dt][3]*sc1 + b1.y);
        }
    }
}

// ---------------- 5) memory retrieval + gate blend -> g_comb [b,n,h*d] ----------------
__global__ void retrieve_gate_k(const float* __restrict__ mem_kv,
                                const float* __restrict__ mem_norm,
                                const float* __restrict__ head_gates) {
    int bh = blockIdx.y;
    int b_ = bh >> 3, h = bh & 7;
    int t0 = blockIdx.x * 32;
    int v  = threadIdx.x;
    __shared__ float qsT[128][36];
    __shared__ float dn[32];
    __shared__ float mn[128];
    mn[v] = mem_norm[bh * DHH + v];
    const float* qf = g_qf + ((size_t)bh * NN + t0) * DHH;
    for (int i = v; i < 32 * 32; i += 128) {
        int t = i >> 5;
        int k4 = (i & 31) * 4;
        float4 qv = *(const float4*)(qf + (size_t)t * DHH + k4);
        qsT[k4+0][t] = qv.x; qsT[k4+1][t] = qv.y; qsT[k4+2][t] = qv.z; qsT[k4+3][t] = qv.w;
    }
    __syncthreads();
    if (v < 32) {
        float s = 0.f;
        #pragma unroll 8
        for (int k = 0; k < 128; k++) s += qsT[k][v] * mn[k];
        dn[v] = fmaxf(s, EPSV);
    }
    __syncthreads();
    const float* mkv = mem_kv + (size_t)bh * DHH * DHH;
    float num[32];
    #pragma unroll
    for (int t = 0; t < 32; t++) num[t] = 0.f;
    for (int k = 0; k < 128; k++) {
        float mval = mkv[k * DHH + v];
        #pragma unroll
        for (int t8 = 0; t8 < 8; t8++) {
            float4 qv = *(const float4*)&qsT[k][t8 * 4];
            num[t8*4+0] += qv.x * mval;
            num[t8*4+1] += qv.y * mval;
            num[t8*4+2] += qv.z * mval;
            num[t8*4+3] += qv.w * mval;
        }
    }
    float g = 1.f / (1.f + expf(-head_gates[h]));
    const float* at = g_attn + ((size_t)bh * NN + t0) * DHH;
    float* cb = g_comb + ((size_t)b_ * NN + t0) * DIMM + h * DHH;
    #pragma unroll 4
    for (int t = 0; t < 32; t++) {
        float mo = num[t] / dn[t];
        cb[(size_t)t * DIMM + v] = at[(size_t)t * DHH + v] * g + mo * (1.f - g);
    }
}

// ---------------- 7) delta-rule new_kv (split 4x over v-dim) ----------------
__global__ void __launch_bounds__(256) newkv_k(const float* __restrict__ mem_kv,
                                               const float* __restrict__ mem_norm,
                                               float* __restrict__ out_kv) {
    int bh    = blockIdx.x;
    int vbase = blockIdx.y * 32;
    int tid   = threadIdx.x;
    int ty = tid >> 3, tx = tid & 7;
    __shared__ float kfs[32][128];
    __shared__ float vns[32][32];
    __shared__ float mn[128];
    __shared__ float dns[32];
    if (tid < 128) mn[tid] = mem_norm[bh * DHH + tid];
    const float* mkv = mem_kv + (size_t)bh * DHH * DHH;
    const float* kfb = g_kf + (size_t)bh * NN * DHH;
    const float* vb  = g_v  + (size_t)bh * NN * DHH;
    float C[4][4];
    #pragma unroll
    for (int i = 0; i < 4; i++)
        #pragma unroll
        for (int j = 0; j < 4; j++) C[i][j] = 0.f;

    int vlane = tid & 31, tg = tid >> 5;

    for (int t0 = 0; t0 < NN; t0 += 32) {
        __syncthreads();
        #pragma unroll
        for (int i = 0; i < 4; i++) {
            int idx = tid + i * 256;
            int t = idx >> 5, kq = (idx & 31) * 4;
            *(float4*)&kfs[t][kq] = *(const float4*)(kfb + (size_t)(t0 + t) * DHH + kq);
        }
        {
            int t = tid >> 3, vq = (tid & 7) * 4;
            *(float4*)&vns[t][vq] = *(const float4*)(vb + (size_t)(t0 + t) * DHH + vbase + vq);
        }
        __syncthreads();
        if (tid < 32) {
            float s = 0.f;
            #pragma unroll 8
            for (int k = 0; k < 128; k++) {
                int kk = (k + tid) & 127;
                s += kfs[tid][kk] * mn[kk];
            }
            dns[tid] = fmaxf(s, EPSV);
        }
        __syncthreads();
        {
            float numv[4] = {0.f, 0.f, 0.f, 0.f};
            for (int k = 0; k < 128; k++) {
                float mval = mkv[k * DHH + vbase + vlane];
                #pragma unroll
                for (int j = 0; j < 4; j++) numv[j] += kfs[tg * 4 + j][k] * mval;
            }
            #pragma unroll
            for (int j = 0; j < 4; j++) vns[tg * 4 + j][vlane] -= numv[j] / dns[tg * 4 + j];
        }
        __syncthreads();
        #pragma unroll 4
        for (int t = 0; t < 32; t++) {
            float4 a = *(const float4*)&kfs[t][ty * 4];
            float4 b = *(const float4*)&vns[t][tx * 4];
            float av[4] = {a.x, a.y, a.z, a.w};
            float bv[4] = {b.x, b.y, b.z, b.w};
            #pragma unroll
            for (int i = 0; i < 4; i++)
                #pragma unroll
                for (int j = 0; j < 4; j++) C[i][j] += av[i] * bv[j];
        }
    }
    #pragma unroll
    for (int i = 0; i < 4; i++)
        #pragma unroll
        for (int j = 0; j < 4; j++) {
            int kd = ty * 4 + i, vd = vbase + tx * 4 + j;
            out_kv[(size_t)bh * DHH * DHH + kd * DHH + vd] = C[i][j] + mkv[kd * DHH + vd];
        }
}

// ---------------- 8) new_norm: two-stage parallel sum ----------------
__global__ void newnorm_part_k() {
    int bh = blockIdx.x, ch = blockIdx.y;
    int k  = threadIdx.x;
    const float* kf = g_kf + (size_t)bh * NN * DHH + (size_t)ch * 256 * DHH;
    float s = 0.f;
    #pragma unroll 8
    for (int n_ = 0; n_ < 256; n_++) s += kf[(size_t)n_ * DHH + k];
    g_pnorm[((size_t)bh * 8 + ch) * DHH + k] = s;
}
__global__ void newnorm_red_k(const float* __restrict__ mem_norm, float* __restrict__ out_norm) {
    int bh = blockIdx.x;
    int k  = threadIdx.x;
    float s = mem_norm[bh * DHH + k];
    #pragma unroll
    for (int c = 0; c < 8; c++) s += g_pnorm[((size_t)bh * 8 + c) * DHH + k];
    out_norm[bh * DHH + k] = s;
}

// ---------------- launch ----------------
extern "C" void kernel_launch(void* const* d_in, const int* in_sizes, int n_in,
                              void* d_out, int out_size) {
    (void)in_sizes; (void)n_in; (void)out_size;
    const float* x          = (const float*)d_in[0];
    const float* gamma      = (const float*)d_in[1];
    const float* w_qkv      = (const float*)d_in[2];
    const float* w_out      = (const float*)d_in[3];
    const float* head_gates = (const float*)d_in[4];
    const float* mem_kv     = (const float*)d_in[5];
    const float* mem_norm   = (const float*)d_in[6];
    float* out      = (float*)d_out;
    float* out_kv   = out + (size_t)BB * NN * DIMM;
    float* out_norm = out_kv + BB * HH * DHH * DHH;

    const int FLASH_SMEM = 25600 * 4;   // 102400 B
    cudaFuncSetAttribute(flash_tc, cudaFuncAttributeMaxDynamicSharedMemorySize, FLASH_SMEM);

    rmsnorm_k<<<BB * NN, 256>>>(x, gamma);
    sgemm_tc<<<dim3(S3 / 128, BB * NN / 128), 256>>>(0, w_qkv, nullptr);
    rope_feat_k<<<BB * HH * NN / 4, dim3(64, 4)>>>();
    flash_tc<<<dim3(NN / 64, BB * HH), 256, FLASH_SMEM>>>();
    retrieve_gate_k<<<dim3(NN / 32, BB * HH), 128>>>(mem_kv, mem_norm, head_gates);
    sgemm_tc<<<dim3(DIMM / 128, BB * NN / 128), 256>>>(1, w_out, out);
    newkv_k<<<dim3(BB * HH, 4), 256>>>(mem_kv, mem_norm, out_kv);
    newnorm_part_k<<<dim3(BB * HH, 8), 128>>>();
    newnorm_red_k<<<BB * HH, 128>>>(mem_norm, out_norm);
}

// round 9
// speedup vs baseline: 3.0025x; 1.1030x over previous
#include <cuda_runtime.h>
#include <math.h>
#include <stdint.h>

#define BB   2
#define NN   2048
#define DIMM 1024
#define HH   8
#define DHH  128
#define S3   (3*DIMM)
#define SCALE_Q 0.08838834764831845f
#define EPSV 1e-10f

// ---------------- scratch (static device globals; no allocation) ----------------
__device__ float g_xn  [BB*NN*DIMM];
__device__ float g_q   [BB*HH*NN*DHH];
__device__ float g_k   [BB*HH*NN*DHH];
__device__ float g_v   [BB*HH*NN*DHH];
__device__ float g_qr  [BB*HH*NN*DHH];
__device__ float g_qf  [BB*HH*NN*DHH];
__device__ float g_kf  [BB*HH*NN*DHH];
__device__ float g_attn[BB*HH*NN*DHH];
__device__ float g_comb[BB*NN*DIMM];
__device__ float g_pnorm[BB*HH*8*DHH];
__device__ float2 g_krhl[BB*HH*NN*DHH];   // pre-split rotated K (tf32 hi, lo)
__device__ float2 g_vhl [BB*HH*NN*DHH];   // pre-split V

// ---------------- helpers ----------------
__device__ __forceinline__ uint32_t f2tf32(float f) {
    uint32_t r;
    asm("cvt.rna.tf32.f32 %0, %1;" : "=r"(r) : "f"(f));
    return r;
}
__device__ __forceinline__ float tf32f(float f) { return __uint_as_float(f2tf32(f)); }

__device__ __forceinline__ void mma_tf32(float* d, const uint32_t* a, const uint32_t* b) {
    asm volatile(
        "mma.sync.aligned.m16n8k8.row.col.f32.tf32.tf32.f32 "
        "{%0,%1,%2,%3}, {%4,%5,%6,%7}, {%8,%9}, {%0,%1,%2,%3};\n"
        : "+f"(d[0]), "+f"(d[1]), "+f"(d[2]), "+f"(d[3])
        : "r"(a[0]), "r"(a[1]), "r"(a[2]), "r"(a[3]), "r"(b[0]), "r"(b[1]));
}

// ---------------- 1) RMSNorm ----------------
__global__ void rmsnorm_k(const float* __restrict__ x, const float* __restrict__ gamma) {
    int row = blockIdx.x;
    const float* xr = x + (size_t)row * DIMM;
    float ss = 0.f;
    for (int i = threadIdx.x; i < DIMM; i += 256) { float v = xr[i]; ss += v * v; }
    #pragma unroll
    for (int o = 16; o > 0; o >>= 1) ss += __shfl_xor_sync(0xffffffffu, ss, o);
    __shared__ float red[8];
    __shared__ float sinv;
    if ((threadIdx.x & 31) == 0) red[threadIdx.x >> 5] = ss;
    __syncthreads();
    if (threadIdx.x == 0) {
        float t = 0.f;
        #pragma unroll
        for (int i = 0; i < 8; i++) t += red[i];
        sinv = 32.0f / fmaxf(sqrtf(t), 1e-12f);
    }
    __syncthreads();
    float inv = sinv;
    float* o = g_xn + (size_t)row * DIMM;
    for (int i = threadIdx.x; i < DIMM; i += 256) o[i] = xr[i] * inv * gamma[i];
}

// ---------------- 2/6) tf32 tensor-core GEMM  C = A @ W^T ----------------
__global__ void __launch_bounds__(256) sgemm_tc(int mode, const float* __restrict__ W,
                                                float* __restrict__ outp) {
    const float* A = (mode == 0) ? g_xn : g_comb;
    const int K = DIMM;
    __shared__ uint32_t As[128][36];
    __shared__ uint32_t Bs[128][36];
    int tid  = threadIdx.x;
    int lane = tid & 31, warp = tid >> 5;
    int wm = warp >> 2, wn = warp & 3;
    int r  = lane >> 2, cc = lane & 3;

    float acc[4][4][4];
    #pragma unroll
    for (int mt = 0; mt < 4; mt++)
        #pragma unroll
        for (int nt = 0; nt < 4; nt++)
            #pragma unroll
            for (int i = 0; i < 4; i++) acc[mt][nt][i] = 0.f;

    size_t aBase = (size_t)(blockIdx.y * 128) * K;
    size_t bBase = (size_t)(blockIdx.x * 128) * K;

    for (int k0 = 0; k0 < K; k0 += 32) {
        #pragma unroll
        for (int i = 0; i < 4; i++) {
            int idx = tid + i * 256;
            int row = idx >> 3;
            int kq  = (idx & 7) * 4;
            float4 av = *(const float4*)(A + aBase + (size_t)row * K + k0 + kq);
            float4 bv = *(const float4*)(W + bBase + (size_t)row * K + k0 + kq);
            *(uint4*)&As[row][kq] = make_uint4(f2tf32(av.x), f2tf32(av.y), f2tf32(av.z), f2tf32(av.w));
            *(uint4*)&Bs[row][kq] = make_uint4(f2tf32(bv.x), f2tf32(bv.y), f2tf32(bv.z), f2tf32(bv.w));
        }
        __syncthreads();
        #pragma unroll
        for (int ks = 0; ks < 32; ks += 8) {
            uint32_t af[4][4], bf[4][2];
            #pragma unroll
            for (int mt = 0; mt < 4; mt++) {
                int m0 = wm * 64 + mt * 16;
                af[mt][0] = As[m0 + r    ][ks + cc];
                af[mt][1] = As[m0 + r + 8][ks + cc];
                af[mt][2] = As[m0 + r    ][ks + cc + 4];
                af[mt][3] = As[m0 + r + 8][ks + cc + 4];
            }
            #pragma unroll
            for (int nt = 0; nt < 4; nt++) {
                int n0 = wn * 32 + nt * 8;
                bf[nt][0] = Bs[n0 + r][ks + cc];
                bf[nt][1] = Bs[n0 + r][ks + cc + 4];
            }
            #pragma unroll
            for (int mt = 0; mt < 4; mt++)
                #pragma unroll
                for (int nt = 0; nt < 4; nt++)
                    mma_tf32(acc[mt][nt], af[mt], bf[nt]);
        }
        __syncthreads();
    }

    #pragma unroll
    for (int mt = 0; mt < 4; mt++) {
        #pragma unroll
        for (int half = 0; half < 2; half++) {
            int row = blockIdx.y * 128 + wm * 64 + mt * 16 + r + half * 8;
            #pragma unroll
            for (int nt = 0; nt < 4; nt++) {
                int col = blockIdx.x * 128 + wn * 32 + nt * 8 + 2 * cc;
                float v0 = acc[mt][nt][half * 2 + 0];
                float v1 = acc[mt][nt][half * 2 + 1];
                if (mode == 0) {
                    int b_ = row >> 11, n_ = row & (NN - 1);
                    int sel = col >> 10, rem = col & 1023;
                    int h = rem >> 7, dd = rem & 127;
                    float* dst = (sel == 0) ? g_q : ((sel == 1) ? g_k : g_v);
                    float2* p = (float2*)&dst[((size_t)(b_ * HH + h) * NN + n_) * DHH + dd];
                    *p = make_float2(v0, v1);
                } else {
                    float2* p = (float2*)&outp[(size_t)row * DIMM + col];
                    *p = make_float2(v0, v1);
                }
            }
        }
    }
}

// ---------------- 3) RoPE + elu features + tf32 hi/lo pre-split of K_rot and V ----------------
__global__ void rope_feat_k() {
    int gid = blockIdx.x * blockDim.y + threadIdx.y;  // (b*H+h)*N + n
    int p   = threadIdx.x;                            // pair index 0..63
    int n_  = gid & (NN - 1);
    size_t base = (size_t)gid * DHH;
    float inv = powf(10000.0f, -(float)(2 * p) * (1.0f / 128.0f));
    float ang = (float)n_ * inv;
    float s, c;
    sincosf(ang, &s, &c);
    float q0 = g_q[base + 2*p], q1 = g_q[base + 2*p + 1];
    float k0 = g_k[base + 2*p], k1 = g_k[base + 2*p + 1];
    float sq0 = q0 * SCALE_Q, sq1 = q1 * SCALE_Q;
    g_qr[base + 2*p]     = sq0 * c - sq1 * s;
    g_qr[base + 2*p + 1] = sq1 * c + sq0 * s;
    float kr0 = k0 * c - k1 * s;
    float kr1 = k1 * c + k0 * s;
    float h;
    h = tf32f(kr0); g_krhl[base + 2*p]     = make_float2(h, tf32f(kr0 - h));
    h = tf32f(kr1); g_krhl[base + 2*p + 1] = make_float2(h, tf32f(kr1 - h));
    float v0 = g_v[base + 2*p], v1 = g_v[base + 2*p + 1];
    h = tf32f(v0); g_vhl[base + 2*p]     = make_float2(h, tf32f(v0 - h));
    h = tf32f(v1); g_vhl[base + 2*p + 1] = make_float2(h, tf32f(v1 - h));
    g_qf[base + 2*p]     = (q0 > 0.f) ? q0 + 1.f : expf(q0);
    g_qf[base + 2*p + 1] = (q1 > 0.f) ? q1 + 1.f : expf(q1);
    g_kf[base + 2*p]     = (k0 > 0.f) ? k0 + 1.f : expf(k0);
    g_kf[base + 2*p + 1] = (k1 > 0.f) ? k1 + 1.f : expf(k1);
}

// ---------------- 4) tensor-core causal flash attention, split-K warp groups ----------------
// 2-term splits: S = qh*(kh+kl), O += ph*(vh+vl). Dropped terms = q/P tf32 rounding
// (~1e-4 rel on weights) — error budget analyzed in round notes.
__global__ void __launch_bounds__(256, 2) flash_tc() {
    extern __shared__ float sm[];
    float*  Qs   = sm;                          // 8448 floats
    float2* Khl  = (float2*)(sm + 8448);        // 8448 floats
    float2* Vhl  = (float2*)(sm + 16896);       // 8448 floats
    float*  sm_m = sm + 25344;                  // 128
    float*  sm_l = sm + 25472;                  // 128

    int bh  = blockIdx.y;
    int it  = gridDim.x - 1 - blockIdx.x;
    int tid = threadIdx.x;
    int lane = tid & 31, warp = tid >> 5;
    int wg = warp >> 2, wq = warp & 3;
    int r = lane >> 2, c = lane & 3;

    const float* Qg = g_qr + ((size_t)bh * NN + it * 64) * DHH;
    for (int i = tid; i < 64 * 32; i += 256) {
        int row = i >> 5, col4 = (i & 31) * 4;
        *(float4*)&Qs[row * 132 + col4] = *(const float4*)(Qg + (size_t)row * DHH + col4);
    }

    float o[16][4];
    #pragma unroll
    for (int dt = 0; dt < 16; dt++)
        #pragma unroll
        for (int i = 0; i < 4; i++) o[dt][i] = 0.f;
    float m0 = -1e30f, m1 = -1e30f, l0 = 0.f, l1 = 0.f;
    int rg0 = it * 64 + wq * 16 + r;
    int rg1 = rg0 + 8;
    int rowmax = it * 64 + wq * 16 + 15;
    int rowmin = it * 64 + wq * 16;
    int ntiles = 2 * it + 2;

    for (int jt = 0; jt < ntiles; jt++) {
        __syncthreads();
        const float4* Kg = (const float4*)(g_krhl + ((size_t)bh * NN + jt * 32) * DHH);
        const float4* Vg = (const float4*)(g_vhl  + ((size_t)bh * NN + jt * 32) * DHH);
        for (int i = tid; i < 2048; i += 256) {          // 32 rows x 64 float4
            int row = i >> 6, q4 = i & 63;
            ((float4*)&Khl[row * 132])[q4] = Kg[row * 64 + q4];
            ((float4*)&Vhl[row * 132])[q4] = Vg[row * 64 + q4];
        }
        __syncthreads();

        int kmin = jt * 32 + wg * 16;                    // this group's first key
        if (kmin > rowmax) continue;                     // fully masked for this warp

        // ---- S = qh @ (Kh + Kl)^T over this group's 16 keys ----
        float s[2][4];
        #pragma unroll
        for (int nt = 0; nt < 2; nt++)
            #pragma unroll
            for (int i = 0; i < 4; i++) s[nt][i] = 0.f;

        #pragma unroll 4
        for (int ks = 0; ks < 16; ks++) {
            float qa0 = Qs[(wq*16 + r    ) * 132 + ks*8 + c];
            float qa1 = Qs[(wq*16 + r + 8) * 132 + ks*8 + c];
            float qa2 = Qs[(wq*16 + r    ) * 132 + ks*8 + c + 4];
            float qa3 = Qs[(wq*16 + r + 8) * 132 + ks*8 + c + 4];
            uint32_t ah[4];
            ah[0] = f2tf32(qa0);
            ah[1] = f2tf32(qa1);
            ah[2] = f2tf32(qa2);
            ah[3] = f2tf32(qa3);
            #pragma unroll
            for (int nt = 0; nt < 2; nt++) {
                float2 b0 = Khl[(wg*16 + nt*8 + r) * 132 + ks*8 + c];
                float2 b1 = Khl[(wg*16 + nt*8 + r) * 132 + ks*8 + c + 4];
                uint32_t bh_[2] = { __float_as_uint(b0.x), __float_as_uint(b1.x) };
                uint32_t bl_[2] = { __float_as_uint(b0.y), __float_as_uint(b1.y) };
                mma_tf32(s[nt], ah, bh_);
                mma_tf32(s[nt], ah, bl_);
            }
        }

        // ---- causal mask (only near diagonal) ----
        if (kmin + 15 > rowmin) {
            #pragma unroll
            for (int nt = 0; nt < 2; nt++) {
                int cg = kmin + nt * 8 + 2 * c;
                if (cg     > rg0) s[nt][0] = -1e30f;
                if (cg + 1 > rg0) s[nt][1] = -1e30f;
                if (cg     > rg1) s[nt][2] = -1e30f;
                if (cg + 1 > rg1) s[nt][3] = -1e30f;
            }
        }

        // ---- online softmax (group-private) ----
        float tmax0 = fmaxf(fmaxf(s[0][0], s[0][1]), fmaxf(s[1][0], s[1][1]));
        float tmax1 = fmaxf(fmaxf(s[0][2], s[0][3]), fmaxf(s[1][2], s[1][3]));
        tmax0 = fmaxf(tmax0, __shfl_xor_sync(0xffffffffu, tmax0, 1));
        tmax0 = fmaxf(tmax0, __shfl_xor_sync(0xffffffffu, tmax0, 2));
        tmax1 = fmaxf(tmax1, __shfl_xor_sync(0xffffffffu, tmax1, 1));
        tmax1 = fmaxf(tmax1, __shfl_xor_sync(0xffffffffu, tmax1, 2));
        float mn0 = fmaxf(m0, tmax0), mn1 = fmaxf(m1, tmax1);
        float al0 = __expf(m0 - mn0), al1 = __expf(m1 - mn1);
        float ps0 = 0.f, ps1 = 0.f;
        #pragma unroll
        for (int nt = 0; nt < 2; nt++) {
            s[nt][0] = __expf(s[nt][0] - mn0);
            s[nt][1] = __expf(s[nt][1] - mn0);
            s[nt][2] = __expf(s[nt][2] - mn1);
            s[nt][3] = __expf(s[nt][3] - mn1);
            ps0 += s[nt][0] + s[nt][1];
            ps1 += s[nt][2] + s[nt][3];
        }
        ps0 += __shfl_xor_sync(0xffffffffu, ps0, 1);
        ps0 += __shfl_xor_sync(0xffffffffu, ps0, 2);
        ps1 += __shfl_xor_sync(0xffffffffu, ps1, 1);
        ps1 += __shfl_xor_sync(0xffffffffu, ps1, 2);
        l0 = l0 * al0 + ps0;  l1 = l1 * al1 + ps1;
        m0 = mn0;  m1 = mn1;
        if (__any_sync(0xffffffffu, (al0 < 1.f) | (al1 < 1.f))) {
            #pragma unroll
            for (int dt = 0; dt < 16; dt++) {
                o[dt][0] *= al0; o[dt][1] *= al0;
                o[dt][2] *= al1; o[dt][3] *= al1;
            }
        }

        // ---- O += ph @ (Vh + Vl) (P C-frag -> A-frag via quad shuffles) ----
        int sA = (lane & ~3) | (c >> 1);
        int sB = sA + 2;
        #pragma unroll
        for (int nt = 0; nt < 2; nt++) {
            float t00 = __shfl_sync(0xffffffffu, s[nt][0], sA);
            float t01 = __shfl_sync(0xffffffffu, s[nt][1], sA);
            float u00 = __shfl_sync(0xffffffffu, s[nt][0], sB);
            float u01 = __shfl_sync(0xffffffffu, s[nt][1], sB);
            float t10 = __shfl_sync(0xffffffffu, s[nt][2], sA);
            float t11 = __shfl_sync(0xffffffffu, s[nt][3], sA);
            float u10 = __shfl_sync(0xffffffffu, s[nt][2], sB);
            float u11 = __shfl_sync(0xffffffffu, s[nt][3], sB);
            float a0 = (c & 1) ? t01 : t00;
            float a2 = (c & 1) ? u01 : u00;
            float a1 = (c & 1) ? t11 : t10;
            float a3 = (c & 1) ? u11 : u10;
            uint32_t ph[4];
            ph[0] = f2tf32(a0);
            ph[1] = f2tf32(a1);
            ph[2] = f2tf32(a2);
            ph[3] = f2tf32(a3);
            #pragma unroll
            for (int dt = 0; dt < 16; dt++) {
                float2 v0 = Vhl[(wg*16 + nt*8 + c    ) * 132 + dt*8 + r];
                float2 v1 = Vhl[(wg*16 + nt*8 + c + 4) * 132 + dt*8 + r];
                uint32_t vh_[2] = { __float_as_uint(v0.x), __float_as_uint(v1.x) };
                uint32_t vl_[2] = { __float_as_uint(v0.y), __float_as_uint(v1.y) };
                mma_tf32(o[dt], ph, vh_);
                mma_tf32(o[dt], ph, vl_);
            }
        }
    }

    // ---- cross-group merge epilogue ----
    int lr0 = wq * 16 + r;
    __syncthreads();
    if (c == 0) {
        sm_m[wg * 64 + lr0]     = m0;  sm_l[wg * 64 + lr0]     = l0;
        sm_m[wg * 64 + lr0 + 8] = m1;  sm_l[wg * 64 + lr0 + 8] = l1;
    }
    __syncthreads();
    float mo0 = sm_m[(1 - wg) * 64 + lr0],     lo0 = sm_l[(1 - wg) * 64 + lr0];
    float mo1 = sm_m[(1 - wg) * 64 + lr0 + 8], lo1 = sm_l[(1 - wg) * 64 + lr0 + 8];
    float mg0 = fmaxf(m0, mo0), mg1 = fmaxf(m1, mo1);
    float lg0 = l0 * __expf(m0 - mg0) + lo0 * __expf(mo0 - mg0);
    float lg1 = l1 * __expf(m1 - mg1) + lo1 * __expf(mo1 - mg1);
    float sc0 = __expf(m0 - mg0) / lg0;
    float sc1 = __expf(m1 - mg1) / lg1;

    float* Obuf = Qs;
    if (wg == 1) {
        #pragma unroll
        for (int dt = 0; dt < 16; dt++) {
            *(float2*)&Obuf[lr0 * 132 + dt*8 + 2*c]       = make_float2(o[dt][0]*sc0, o[dt][1]*sc0);
            *(float2*)&Obuf[(lr0+8) * 132 + dt*8 + 2*c]   = make_float2(o[dt][2]*sc1, o[dt][3]*sc1);
        }
    }
    __syncthreads();
    if (wg == 0) {
        float* O0 = g_attn + ((size_t)bh * NN + it * 64 + lr0    ) * DHH;
        float* O1 = g_attn + ((size_t)bh * NN + it * 64 + lr0 + 8) * DHH;
        #pragma unroll
        for (int dt = 0; dt < 16; dt++) {
            float2 b0 = *(float2*)&Obuf[lr0 * 132 + dt*8 + 2*c];
            float2 b1 = *(float2*)&Obuf[(lr0+8) * 132 + dt*8 + 2*c];
            *(float2*)&O0[dt*8 + 2*c] = make_float2(o[dt][0]*sc0 + b0.x, o[dt][1]*sc0 + b0.y);
            *(float2*)&O1[dt*8 + 2*c] = make_float2(o[dt][2]*sc1 + b1.x, o[dt][3]*sc1 + b1.y);
        }
    }
}

// ---------------- 5) memory retrieval + gate blend -> g_comb [b,n,h*d] ----------------
__global__ void retrieve_gate_k(const float* __restrict__ mem_kv,
                                const float* __restrict__ mem_norm,
                                const float* __restrict__ head_gates) {
    int bh = blockIdx.y;
    int b_ = bh >> 3, h = bh & 7;
    int t0 = blockIdx.x * 32;
    int v  = threadIdx.x;
    __shared__ float qsT[128][36];
    __shared__ float dn[32];
    __shared__ float mn[128];
    mn[v] = mem_norm[bh * DHH + v];
    const float* qf = g_qf + ((size_t)bh * NN + t0) * DHH;
    for (int i = v; i < 32 * 32; i += 128) {
        int t = i >> 5;
        int k4 = (i & 31) * 4;
        float4 qv = *(const float4*)(qf + (size_t)t * DHH + k4);
        qsT[k4+0][t] = qv.x; qsT[k4+1][t] = qv.y; qsT[k4+2][t] = qv.z; qsT[k4+3][t] = qv.w;
    }
    __syncthreads();
    if (v < 32) {
        float s = 0.f;
        #pragma unroll 8
        for (int k = 0; k < 128; k++) s += qsT[k][v] * mn[k];
        dn[v] = fmaxf(s, EPSV);
    }
    __syncthreads();
    const float* mkv = mem_kv + (size_t)bh * DHH * DHH;
    float num[32];
    #pragma unroll
    for (int t = 0; t < 32; t++) num[t] = 0.f;
    for (int k = 0; k < 128; k++) {
        float mval = mkv[k * DHH + v];
        #pragma unroll
        for (int t8 = 0; t8 < 8; t8++) {
            float4 qv = *(const float4*)&qsT[k][t8 * 4];
            num[t8*4+0] += qv.x * mval;
            num[t8*4+1] += qv.y * mval;
            num[t8*4+2] += qv.z * mval;
            num[t8*4+3] += qv.w * mval;
        }
    }
    float g = 1.f / (1.f + expf(-head_gates[h]));
    const float* at = g_attn + ((size_t)bh * NN + t0) * DHH;
    float* cb = g_comb + ((size_t)b_ * NN + t0) * DIMM + h * DHH;
    #pragma unroll 4
    for (int t = 0; t < 32; t++) {
        float mo = num[t] / dn[t];
        cb[(size_t)t * DIMM + v] = at[(size_t)t * DHH + v] * g + mo * (1.f - g);
    }
}

// ---------------- 7) delta-rule new_kv (split 4x over v-dim) ----------------
__global__ void __launch_bounds__(256) newkv_k(const float* __restrict__ mem_kv,
                                               const float* __restrict__ mem_norm,
                                               float* __restrict__ out_kv) {
    int bh    = blockIdx.x;
    int vbase = blockIdx.y * 32;
    int tid   = threadIdx.x;
    int ty = tid >> 3, tx = tid & 7;
    __shared__ float kfs[32][128];
    __shared__ float vns[32][32];
    __shared__ float mn[128];
    __shared__ float dns[32];
    if (tid < 128) mn[tid] = mem_norm[bh * DHH + tid];
    const float* mkv = mem_kv + (size_t)bh * DHH * DHH;
    const float* kfb = g_kf + (size_t)bh * NN * DHH;
    const float* vb  = g_v  + (size_t)bh * NN * DHH;
    float C[4][4];
    #pragma unroll
    for (int i = 0; i < 4; i++)
        #pragma unroll
        for (int j = 0; j < 4; j++) C[i][j] = 0.f;

    int vlane = tid & 31, tg = tid >> 5;

    for (int t0 = 0; t0 < NN; t0 += 32) {
        __syncthreads();
        #pragma unroll
        for (int i = 0; i < 4; i++) {
            int idx = tid + i * 256;
            int t = idx >> 5, kq = (idx & 31) * 4;
            *(float4*)&kfs[t][kq] = *(const float4*)(kfb + (size_t)(t0 + t) * DHH + kq);
        }
        {
            int t = tid >> 3, vq = (tid & 7) * 4;
            *(float4*)&vns[t][vq] = *(const float4*)(vb + (size_t)(t0 + t) * DHH + vbase + vq);
        }
        __syncthreads();
        if (tid < 32) {
            float s = 0.f;
            #pragma unroll 8
            for (int k = 0; k < 128; k++) {
                int kk = (k + tid) & 127;
                s += kfs[tid][kk] * mn[kk];
            }
            dns[tid] = fmaxf(s, EPSV);
        }
        __syncthreads();
        {
            float numv[4] = {0.f, 0.f, 0.f, 0.f};
            for (int k = 0; k < 128; k++) {
                float mval = mkv[k * DHH + vbase + vlane];
                #pragma unroll
                for (int j = 0; j < 4; j++) numv[j] += kfs[tg * 4 + j][k] * mval;
            }
            #pragma unroll
            for (int j = 0; j < 4; j++) vns[tg * 4 + j][vlane] -= numv[j] / dns[tg * 4 + j];
        }
        __syncthreads();
        #pragma unroll 4
        for (int t = 0; t < 32; t++) {
            float4 a = *(const float4*)&kfs[t][ty * 4];
            float4 b = *(const float4*)&vns[t][tx * 4];
            float av[4] = {a.x, a.y, a.z, a.w};
            float bv[4] = {b.x, b.y, b.z, b.w};
            #pragma unroll
            for (int i = 0; i < 4; i++)
                #pragma unroll
                for (int j = 0; j < 4; j++) C[i][j] += av[i] * bv[j];
        }
    }
    #pragma unroll
    for (int i = 0; i < 4; i++)
        #pragma unroll
        for (int j = 0; j < 4; j++) {
            int kd = ty * 4 + i, vd = vbase + tx * 4 + j;
            out_kv[(size_t)bh * DHH * DHH + kd * DHH + vd] = C[i][j] + mkv[kd * DHH + vd];
        }
}

// ---------------- 8) new_norm: two-stage parallel sum ----------------
__global__ void newnorm_part_k() {
    int bh = blockIdx.x, ch = blockIdx.y;
    int k  = threadIdx.x;
    const float* kf = g_kf + (size_t)bh * NN * DHH + (size_t)ch * 256 * DHH;
    float s = 0.f;
    #pragma unroll 8
    for (int n_ = 0; n_ < 256; n_++) s += kf[(size_t)n_ * DHH + k];
    g_pnorm[((size_t)bh * 8 + ch) * DHH + k] = s;
}
__global__ void newnorm_red_k(const float* __restrict__ mem_norm, float* __restrict__ out_norm) {
    int bh = blockIdx.x;
    int k  = threadIdx.x;
    float s = mem_norm[bh * DHH + k];
    #pragma unroll
    for (int c = 0; c < 8; c++) s += g_pnorm[((size_t)bh * 8 + c) * DHH + k];
    out_norm[bh * DHH + k] = s;
}

// ---------------- launch ----------------
extern "C" void kernel_launch(void* const* d_in, const int* in_sizes, int n_in,
                              void* d_out, int out_size) {
    (void)in_sizes; (void)n_in; (void)out_size;
    const float* x          = (const float*)d_in[0];
    const float* gamma      = (const float*)d_in[1];
    const float* w_qkv      = (const float*)d_in[2];
    const float* w_out      = (const float*)d_in[3];
    const float* head_gates = (const float*)d_in[4];
    const float* mem_kv     = (const float*)d_in[5];
    const float* mem_norm   = (const float*)d_in[6];
    float* out      = (float*)d_out;
    float* out_kv   = out + (size_t)BB * NN * DIMM;
    float* out_norm = out_kv + BB * HH * DHH * DHH;

    const int FLASH_SMEM = 25600 * 4;   // 102400 B
    cudaFuncSetAttribute(flash_tc, cudaFuncAttributeMaxDynamicSharedMemorySize, FLASH_SMEM);

    rmsnorm_k<<<BB * NN, 256>>>(x, gamma);
    sgemm_tc<<<dim3(S3 / 128, BB * NN / 128), 256>>>(0, w_qkv, nullptr);
    rope_feat_k<<<BB * HH * NN / 4, dim3(64, 4)>>>();
    flash_tc<<<dim3(NN / 64, BB * HH), 256, FLASH_SMEM>>>();
    retrieve_gate_k<<<dim3(NN / 32, BB * HH), 128>>>(mem_kv, mem_norm, head_gates);
    sgemm_tc<<<dim3(DIMM / 128, BB * NN / 128), 256>>>(1, w_out, out);
    newkv_k<<<dim3(BB * HH, 4), 256>>>(mem_kv, mem_norm, out_kv);
    newnorm_part_k<<<dim3(BB * HH, 8), 128>>>();
    newnorm_red_k<<<BB * HH, 128>>>(mem_norm, out_norm);
}

// round 11
// speedup vs baseline: 3.0198x; 1.0058x over previous
#include <cuda_runtime.h>
#include <math.h>
#include <stdint.h>

#define BB   2
#define NN   2048
#define DIMM 1024
#define HH   8
#define DHH  128
#define S3   (3*DIMM)
#define SCALE_Q 0.08838834764831845f
#define EPSV 1e-10f

// ---------------- scratch (static device globals; no allocation) ----------------
__device__ float g_xn  [BB*NN*DIMM];
__device__ float g_q   [BB*HH*NN*DHH];
__device__ float g_k   [BB*HH*NN*DHH];
__device__ float g_v   [BB*HH*NN*DHH];
__device__ float g_qr  [BB*HH*NN*DHH];
__device__ float g_qf  [BB*HH*NN*DHH];
__device__ float g_kf  [BB*HH*NN*DHH];
__device__ float g_attn[BB*HH*NN*DHH];
__device__ float g_comb[BB*NN*DIMM];
__device__ float g_pnorm[BB*HH*8*DHH];
__device__ float2 g_krhl[BB*HH*NN*DHH];   // pre-split rotated K (tf32 hi, lo)
__device__ float2 g_vhl [BB*HH*NN*DHH];   // pre-split V

// ---------------- helpers ----------------
__device__ __forceinline__ uint32_t f2tf32(float f) {
    uint32_t r;
    asm("cvt.rna.tf32.f32 %0, %1;" : "=r"(r) : "f"(f));
    return r;
}
__device__ __forceinline__ float tf32f(float f) { return __uint_as_float(f2tf32(f)); }

__device__ __forceinline__ void mma_tf32(float* d, const uint32_t* a, const uint32_t* b) {
    asm volatile(
        "mma.sync.aligned.m16n8k8.row.col.f32.tf32.tf32.f32 "
        "{%0,%1,%2,%3}, {%4,%5,%6,%7}, {%8,%9}, {%0,%1,%2,%3};\n"
        : "+f"(d[0]), "+f"(d[1]), "+f"(d[2]), "+f"(d[3])
        : "r"(a[0]), "r"(a[1]), "r"(a[2]), "r"(a[3]), "r"(b[0]), "r"(b[1]));
}

// ---------------- 1) RMSNorm ----------------
__global__ void rmsnorm_k(const float* __restrict__ x, const float* __restrict__ gamma) {
    int row = blockIdx.x;
    const float* xr = x + (size_t)row * DIMM;
    float ss = 0.f;
    for (int i = threadIdx.x; i < DIMM; i += 256) { float v = xr[i]; ss += v * v; }
    #pragma unroll
    for (int o = 16; o > 0; o >>= 1) ss += __shfl_xor_sync(0xffffffffu, ss, o);
    __shared__ float red[8];
    __shared__ float sinv;
    if ((threadIdx.x & 31) == 0) red[threadIdx.x >> 5] = ss;
    __syncthreads();
    if (threadIdx.x == 0) {
        float t = 0.f;
        #pragma unroll
        for (int i = 0; i < 8; i++) t += red[i];
        sinv = 32.0f / fmaxf(sqrtf(t), 1e-12f);
    }
    __syncthreads();
    float inv = sinv;
    float* o = g_xn + (size_t)row * DIMM;
    for (int i = threadIdx.x; i < DIMM; i += 256) o[i] = xr[i] * inv * gamma[i];
}

// ---------------- 2/6) tf32 tensor-core GEMM, 2-stage pipelined ----------------
// C = A @ W^T. Block tile 128x128, kt=32, double-buffered smem, 1 sync/iter.
// smem: As[2][128][36] + Bs[2][128][36] = 73728 B dynamic.
#define AS(b, r, c) smem_u[(b) * 4608 + (r) * 36 + (c)]
#define BS(b, r, c) smem_u[9216 + (b) * 4608 + (r) * 36 + (c)]
__global__ void __launch_bounds__(256) sgemm_tc(int mode, const float* __restrict__ W,
                                                float* __restrict__ outp) {
    extern __shared__ uint32_t smem_u[];
    const float* A = (mode == 0) ? g_xn : g_comb;
    const int K = DIMM;
    int tid  = threadIdx.x;
    int lane = tid & 31, warp = tid >> 5;
    int wm = warp >> 2, wn = warp & 3;
    int r  = lane >> 2, cc = lane & 3;
    int rbase = tid >> 3;                 // 0..31
    int kq    = (tid & 7) * 4;            // 0,4,..,28

    float acc[4][4][4];
    #pragma unroll
    for (int mt = 0; mt < 4; mt++)
        #pragma unroll
        for (int nt = 0; nt < 4; nt++)
            #pragma unroll
            for (int i = 0; i < 4; i++) acc[mt][nt][i] = 0.f;

    size_t aBase = (size_t)(blockIdx.y * 128) * K;
    size_t bBase = (size_t)(blockIdx.x * 128) * K;

    float4 avr[4], bvr[4];
    #pragma unroll
    for (int i = 0; i < 4; i++) {
        int row = rbase + 32 * i;
        avr[i] = *(const float4*)(A + aBase + (size_t)row * K + kq);
        bvr[i] = *(const float4*)(W + bBase + (size_t)row * K + kq);
    }
    #pragma unroll
    for (int i = 0; i < 4; i++) {
        int row = rbase + 32 * i;
        *(uint4*)&AS(0, row, kq) = make_uint4(f2tf32(avr[i].x), f2tf32(avr[i].y), f2tf32(avr[i].z), f2tf32(avr[i].w));
        *(uint4*)&BS(0, row, kq) = make_uint4(f2tf32(bvr[i].x), f2tf32(bvr[i].y), f2tf32(bvr[i].z), f2tf32(bvr[i].w));
    }
    __syncthreads();

    for (int kt = 0; kt < 32; kt++) {
        int cur = kt & 1;
        if (kt < 31) {                     // issue next tile's loads early
            int k0 = (kt + 1) * 32;
            #pragma unroll
            for (int i = 0; i < 4; i++) {
                int row = rbase + 32 * i;
                avr[i] = *(const float4*)(A + aBase + (size_t)row * K + k0 + kq);
                bvr[i] = *(const float4*)(W + bBase + (size_t)row * K + k0 + kq);
            }
        }
        #pragma unroll
        for (int ks = 0; ks < 32; ks += 8) {
            uint32_t af[4][4], bf[4][2];
            #pragma unroll
            for (int mt = 0; mt < 4; mt++) {
                int m0 = wm * 64 + mt * 16;
                af[mt][0] = AS(cur, m0 + r,     ks + cc);
                af[mt][1] = AS(cur, m0 + r + 8, ks + cc);
                af[mt][2] = AS(cur, m0 + r,     ks + cc + 4);
                af[mt][3] = AS(cur, m0 + r + 8, ks + cc + 4);
            }
            #pragma unroll
            for (int nt = 0; nt < 4; nt++) {
                int n0 = wn * 32 + nt * 8;
                bf[nt][0] = BS(cur, n0 + r, ks + cc);
                bf[nt][1] = BS(cur, n0 + r, ks + cc + 4);
            }
            #pragma unroll
            for (int mt = 0; mt < 4; mt++)
                #pragma unroll
                for (int nt = 0; nt < 4; nt++)
                    mma_tf32(acc[mt][nt], af[mt], bf[nt]);
        }
        if (kt < 31) {
            #pragma unroll
            for (int i = 0; i < 4; i++) {
                int row = rbase + 32 * i;
                *(uint4*)&AS(cur ^ 1, row, kq) = make_uint4(f2tf32(avr[i].x), f2tf32(avr[i].y), f2tf32(avr[i].z), f2tf32(avr[i].w));
                *(uint4*)&BS(cur ^ 1, row, kq) = make_uint4(f2tf32(bvr[i].x), f2tf32(bvr[i].y), f2tf32(bvr[i].z), f2tf32(bvr[i].w));
            }
            __syncthreads();
        }
    }

    #pragma unroll
    for (int mt = 0; mt < 4; mt++) {
        #pragma unroll
        for (int half = 0; half < 2; half++) {
            int row = blockIdx.y * 128 + wm * 64 + mt * 16 + r + half * 8;
            #pragma unroll
            for (int nt = 0; nt < 4; nt++) {
                int col = blockIdx.x * 128 + wn * 32 + nt * 8 + 2 * cc;
                float v0 = acc[mt][nt][half * 2 + 0];
                float v1 = acc[mt][nt][half * 2 + 1];
                if (mode == 0) {
                    int b_ = row >> 11, n_ = row & (NN - 1);
                    int sel = col >> 10, rem = col & 1023;
                    int h = rem >> 7, dd = rem & 127;
                    float* dst = (sel == 0) ? g_q : ((sel == 1) ? g_k : g_v);
                    float2* p = (float2*)&dst[((size_t)(b_ * HH + h) * NN + n_) * DHH + dd];
                    *p = make_float2(v0, v1);
                } else {
                    float2* p = (float2*)&outp[(size_t)row * DIMM + col];
                    *p = make_float2(v0, v1);
                }
            }
        }
    }
}

// ---------------- 3) RoPE + elu features + tf32 hi/lo pre-split of K_rot and V ----------------
__global__ void rope_feat_k() {
    int gid = blockIdx.x * blockDim.y + threadIdx.y;  // (b*H+h)*N + n
    int p   = threadIdx.x;                            // pair index 0..63
    int n_  = gid & (NN - 1);
    size_t base = (size_t)gid * DHH;
    float inv = powf(10000.0f, -(float)(2 * p) * (1.0f / 128.0f));
    float ang = (float)n_ * inv;
    float s, c;
    sincosf(ang, &s, &c);
    float q0 = g_q[base + 2*p], q1 = g_q[base + 2*p + 1];
    float k0 = g_k[base + 2*p], k1 = g_k[base + 2*p + 1];
    float sq0 = q0 * SCALE_Q, sq1 = q1 * SCALE_Q;
    g_qr[base + 2*p]     = sq0 * c - sq1 * s;
    g_qr[base + 2*p + 1] = sq1 * c + sq0 * s;
    float kr0 = k0 * c - k1 * s;
    float kr1 = k1 * c + k0 * s;
    float h;
    h = tf32f(kr0); g_krhl[base + 2*p]     = make_float2(h, tf32f(kr0 - h));
    h = tf32f(kr1); g_krhl[base + 2*p + 1] = make_float2(h, tf32f(kr1 - h));
    float v0 = g_v[base + 2*p], v1 = g_v[base + 2*p + 1];
    h = tf32f(v0); g_vhl[base + 2*p]     = make_float2(h, tf32f(v0 - h));
    h = tf32f(v1); g_vhl[base + 2*p + 1] = make_float2(h, tf32f(v1 - h));
    g_qf[base + 2*p]     = (q0 > 0.f) ? q0 + 1.f : expf(q0);
    g_qf[base + 2*p + 1] = (q1 > 0.f) ? q1 + 1.f : expf(q1);
    g_kf[base + 2*p]     = (k0 > 0.f) ? k0 + 1.f : expf(k0);
    g_kf[base + 2*p + 1] = (k1 > 0.f) ? k1 + 1.f : expf(k1);
}

// ---------------- 4) tensor-core causal flash attention, split-K warp groups ----------------
// 2-term splits: S = qh*(kh+kl), O += ph*(vh+vl).
__global__ void __launch_bounds__(256, 2) flash_tc() {
    extern __shared__ float sm[];
    float*  Qs   = sm;                          // 8448 floats
    float2* Khl  = (float2*)(sm + 8448);        // 8448 floats
    float2* Vhl  = (float2*)(sm + 16896);       // 8448 floats
    float*  sm_m = sm + 25344;                  // 128
    float*  sm_l = sm + 25472;                  // 128

    int bh  = blockIdx.y;
    int it  = gridDim.x - 1 - blockIdx.x;
    int tid = threadIdx.x;
    int lane = tid & 31, warp = tid >> 5;
    int wg = warp >> 2, wq = warp & 3;
    int r = lane >> 2, c = lane & 3;

    const float* Qg = g_qr + ((size_t)bh * NN + it * 64) * DHH;
    for (int i = tid; i < 64 * 32; i += 256) {
        int row = i >> 5, col4 = (i & 31) * 4;
        *(float4*)&Qs[row * 132 + col4] = *(const float4*)(Qg + (size_t)row * DHH + col4);
    }

    float o[16][4];
    #pragma unroll
    for (int dt = 0; dt < 16; dt++)
        #pragma unroll
        for (int i = 0; i < 4; i++) o[dt][i] = 0.f;
    float m0 = -1e30f, m1 = -1e30f, l0 = 0.f, l1 = 0.f;
    int rg0 = it * 64 + wq * 16 + r;
    int rg1 = rg0 + 8;
    int rowmax = it * 64 + wq * 16 + 15;
    int rowmin = it * 64 + wq * 16;
    int ntiles = 2 * it + 2;

    for (int jt = 0; jt < ntiles; jt++) {
        __syncthreads();
        const float4* Kg = (const float4*)(g_krhl + ((size_t)bh * NN + jt * 32) * DHH);
        const float4* Vg = (const float4*)(g_vhl  + ((size_t)bh * NN + jt * 32) * DHH);
        for (int i = tid; i < 2048; i += 256) {          // 32 rows x 64 float4
            int row = i >> 6, q4 = i & 63;
            ((float4*)&Khl[row * 132])[q4] = Kg[row * 64 + q4];
            ((float4*)&Vhl[row * 132])[q4] = Vg[row * 64 + q4];
        }
        __syncthreads();

        int kmin = jt * 32 + wg * 16;
        if (kmin > rowmax) continue;

        float s[2][4];
        #pragma unroll
        for (int nt = 0; nt < 2; nt++)
            #pragma unroll
            for (int i = 0; i < 4; i++) s[nt][i] = 0.f;

        #pragma unroll 4
        for (int ks = 0; ks < 16; ks++) {
            float qa0 = Qs[(wq*16 + r    ) * 132 + ks*8 + c];
            float qa1 = Qs[(wq*16 + r + 8) * 132 + ks*8 + c];
            float qa2 = Qs[(wq*16 + r    ) * 132 + ks*8 + c + 4];
            float qa3 = Qs[(wq*16 + r + 8) * 132 + ks*8 + c + 4];
            uint32_t ah[4];
            ah[0] = f2tf32(qa0);
            ah[1] = f2tf32(qa1);
            ah[2] = f2tf32(qa2);
            ah[3] = f2tf32(qa3);
            #pragma unroll
            for (int nt = 0; nt < 2; nt++) {
                float2 b0 = Khl[(wg*16 + nt*8 + r) * 132 + ks*8 + c];
                float2 b1 = Khl[(wg*16 + nt*8 + r) * 132 + ks*8 + c + 4];
                uint32_t bh_[2] = { __float_as_uint(b0.x), __float_as_uint(b1.x) };
                uint32_t bl_[2] = { __float_as_uint(b0.y), __float_as_uint(b1.y) };
                mma_tf32(s[nt], ah, bh_);
                mma_tf32(s[nt], ah, bl_);
            }
        }

        if (kmin + 15 > rowmin) {
            #pragma unroll
            for (int nt = 0; nt < 2; nt++) {
                int cg = kmin + nt * 8 + 2 * c;
                if (cg     > rg0) s[nt][0] = -1e30f;
                if (cg + 1 > rg0) s[nt][1] = -1e30f;
                if (cg     > rg1) s[nt][2] = -1e30f;
                if (cg + 1 > rg1) s[nt][3] = -1e30f;
            }
        }

        float tmax0 = fmaxf(fmaxf(s[0][0], s[0][1]), fmaxf(s[1][0], s[1][1]));
        float tmax1 = fmaxf(fmaxf(s[0][2], s[0][3]), fmaxf(s[1][2], s[1][3]));
        tmax0 = fmaxf(tmax0, __shfl_xor_sync(0xffffffffu, tmax0, 1));
        tmax0 = fmaxf(tmax0, __shfl_xor_sync(0xffffffffu, tmax0, 2));
        tmax1 = fmaxf(tmax1, __shfl_xor_sync(0xffffffffu, tmax1, 1));
        tmax1 = fmaxf(tmax1, __shfl_xor_sync(0xffffffffu, tmax1, 2));
        float mn0 = fmaxf(m0, tmax0), mn1 = fmaxf(m1, tmax1);
        float al0 = __expf(m0 - mn0), al1 = __expf(m1 - mn1);
        float ps0 = 0.f, ps1 = 0.f;
        #pragma unroll
        for (int nt = 0; nt < 2; nt++) {
            s[nt][0] = __expf(s[nt][0] - mn0);
            s[nt][1] = __expf(s[nt][1] - mn0);
            s[nt][2] = __expf(s[nt][2] - mn1);
            s[nt][3] = __expf(s[nt][3] - mn1);
            ps0 += s[nt][0] + s[nt][1];
            ps1 += s[nt][2] + s[nt][3];
        }
        ps0 += __shfl_xor_sync(0xffffffffu, ps0, 1);
        ps0 += __shfl_xor_sync(0xffffffffu, ps0, 2);
        ps1 += __shfl_xor_sync(0xffffffffu, ps1, 1);
        ps1 += __shfl_xor_sync(0xffffffffu, ps1, 2);
        l0 = l0 * al0 + ps0;  l1 = l1 * al1 + ps1;
        m0 = mn0;  m1 = mn1;
        if (__any_sync(0xffffffffu, (al0 < 1.f) | (al1 < 1.f))) {
            #pragma unroll
            for (int dt = 0; dt < 16; dt++) {
                o[dt][0] *= al0; o[dt][1] *= al0;
                o[dt][2] *= al1; o[dt][3] *= al1;
            }
        }

        int sA = (lane & ~3) | (c >> 1);
        int sB = sA + 2;
        #pragma unroll
        for (int nt = 0; nt < 2; nt++) {
            float t00 = __shfl_sync(0xffffffffu, s[nt][0], sA);
            float t01 = __shfl_sync(0xffffffffu, s[nt][1], sA);
            float u00 = __shfl_sync(0xffffffffu, s[nt][0], sB);
            float u01 = __shfl_sync(0xffffffffu, s[nt][1], sB);
            float t10 = __shfl_sync(0xffffffffu, s[nt][2], sA);
            float t11 = __shfl_sync(0xffffffffu, s[nt][3], sA);
            float u10 = __shfl_sync(0xffffffffu, s[nt][2], sB);
            float u11 = __shfl_sync(0xffffffffu, s[nt][3], sB);
            float a0 = (c & 1) ? t01 : t00;
            float a2 = (c & 1) ? u01 : u00;
            float a1 = (c & 1) ? t11 : t10;
            float a3 = (c & 1) ? u11 : u10;
            uint32_t ph[4];
            ph[0] = f2tf32(a0);
            ph[1] = f2tf32(a1);
            ph[2] = f2tf32(a2);
            ph[3] = f2tf32(a3);
            #pragma unroll
            for (int dt = 0; dt < 16; dt++) {
                float2 v0 = Vhl[(wg*16 + nt*8 + c    ) * 132 + dt*8 + r];
                float2 v1 = Vhl[(wg*16 + nt*8 + c + 4) * 132 + dt*8 + r];
                uint32_t vh_[2] = { __float_as_uint(v0.x), __float_as_uint(v1.x) };
                uint32_t vl_[2] = { __float_as_uint(v0.y), __float_as_uint(v1.y) };
                mma_tf32(o[dt], ph, vh_);
                mma_tf32(o[dt], ph, vl_);
            }
        }
    }

    int lr0 = wq * 16 + r;
    __syncthreads();
    if (c == 0) {
        sm_m[wg * 64 + lr0]     = m0;  sm_l[wg * 64 + lr0]     = l0;
        sm_m[wg * 64 + lr0 + 8] = m1;  sm_l[wg * 64 + lr0 + 8] = l1;
    }
    __syncthreads();
    float mo0 = sm_m[(1 - wg) * 64 + lr0],     lo0 = sm_l[(1 - wg) * 64 + lr0];
    float mo1 = sm_m[(1 - wg) * 64 + lr0 + 8], lo1 = sm_l[(1 - wg) * 64 + lr0 + 8];
    float mg0 = fmaxf(m0, mo0), mg1 = fmaxf(m1, mo1);
    float lg0 = l0 * __expf(m0 - mg0) + lo0 * __expf(mo0 - mg0);
    float lg1 = l1 * __expf(m1 - mg1) + lo1 * __expf(mo1 - mg1);
    float sc0 = __expf(m0 - mg0) / lg0;
    float sc1 = __expf(m1 - mg1) / lg1;

    float* Obuf = Qs;
    if (wg == 1) {
        #pragma unroll
        for (int dt = 0; dt < 16; dt++) {
            *(float2*)&Obuf[lr0 * 132 + dt*8 + 2*c]       = make_float2(o[dt][0]*sc0, o[dt][1]*sc0);
            *(float2*)&Obuf[(lr0+8) * 132 + dt*8 + 2*c]   = make_float2(o[dt][2]*sc1, o[dt][3]*sc1);
        }
    }
    __syncthreads();
    if (wg == 0) {
        float* O0 = g_attn + ((size_t)bh * NN + it * 64 + lr0    ) * DHH;
        float* O1 = g_attn + ((size_t)bh * NN + it * 64 + lr0 + 8) * DHH;
        #pragma unroll
        for (int dt = 0; dt < 16; dt++) {
            float2 b0 = *(float2*)&Obuf[lr0 * 132 + dt*8 + 2*c];
            float2 b1 = *(float2*)&Obuf[(lr0+8) * 132 + dt*8 + 2*c];
            *(float2*)&O0[dt*8 + 2*c] = make_float2(o[dt][0]*sc0 + b0.x, o[dt][1]*sc0 + b0.y);
            *(float2*)&O1[dt*8 + 2*c] = make_float2(o[dt][2]*sc1 + b1.x, o[dt][3]*sc1 + b1.y);
        }
    }
}

// ---------------- 5) memory retrieval + gate blend -> g_comb [b,n,h*d] ----------------
__global__ void retrieve_gate_k(const float* __restrict__ mem_kv,
                                const float* __restrict__ mem_norm,
                                const float* __restrict__ head_gates) {
    int bh = blockIdx.y;
    int b_ = bh >> 3, h = bh & 7;
    int t0 = blockIdx.x * 32;
    int v  = threadIdx.x;
    __shared__ float qsT[128][36];
    __shared__ float dn[32];
    __shared__ float mn[128];
    mn[v] = mem_norm[bh * DHH + v];
    const float* qf = g_qf + ((size_t)bh * NN + t0) * DHH;
    for (int i = v; i < 32 * 32; i += 128) {
        int t = i >> 5;
        int k4 = (i & 31) * 4;
        float4 qv = *(const float4*)(qf + (size_t)t * DHH + k4);
        qsT[k4+0][t] = qv.x; qsT[k4+1][t] = qv.y; qsT[k4+2][t] = qv.z; qsT[k4+3][t] = qv.w;
    }
    __syncthreads();
    if (v < 32) {
        float s = 0.f;
        #pragma unroll 8
        for (int k = 0; k < 128; k++) s += qsT[k][v] * mn[k];
        dn[v] = fmaxf(s, EPSV);
    }
    __syncthreads();
    const float* mkv = mem_kv + (size_t)bh * DHH * DHH;
    float num[32];
    #pragma unroll
    for (int t = 0; t < 32; t++) num[t] = 0.f;
    for (int k = 0; k < 128; k++) {
        float mval = mkv[k * DHH + v];
        #pragma unroll
        for (int t8 = 0; t8 < 8; t8++) {
            float4 qv = *(const float4*)&qsT[k][t8 * 4];
            num[t8*4+0] += qv.x * mval;
            num[t8*4+1] += qv.y * mval;
            num[t8*4+2] += qv.z * mval;
            num[t8*4+3] += qv.w * mval;
        }
    }
    float g = 1.f / (1.f + expf(-head_gates[h]));
    const float* at = g_attn + ((size_t)bh * NN + t0) * DHH;
    float* cb = g_comb + ((size_t)b_ * NN + t0) * DIMM + h * DHH;
    #pragma unroll 4
    for (int t = 0; t < 32; t++) {
        float mo = num[t] / dn[t];
        cb[(size_t)t * DIMM + v] = at[(size_t)t * DHH + v] * g + mo * (1.f - g);
    }
}

// ---------------- 7) delta-rule new_kv (split 4x over v-dim) ----------------
__global__ void __launch_bounds__(256) newkv_k(const float* __restrict__ mem_kv,
                                               const float* __restrict__ mem_norm,
                                               float* __restrict__ out_kv) {
    int bh    = blockIdx.x;
    int vbase = blockIdx.y * 32;
    int tid   = threadIdx.x;
    int ty = tid >> 3, tx = tid & 7;
    __shared__ float kfs[32][128];
    __shared__ float vns[32][32];
    __shared__ float mn[128];
    __shared__ float dns[32];
    if (tid < 128) mn[tid] = mem_norm[bh * DHH + tid];
    const float* mkv = mem_kv + (size_t)bh * DHH * DHH;
    const float* kfb = g_kf + (size_t)bh * NN * DHH;
    const float* vb  = g_v  + (size_t)bh * NN * DHH;
    float C[4][4];
    #pragma unroll
    for (int i = 0; i < 4; i++)
        #pragma unroll
        for (int j = 0; j < 4; j++) C[i][j] = 0.f;

    int vlane = tid & 31, tg = tid >> 5;

    for (int t0 = 0; t0 < NN; t0 += 32) {
        __syncthreads();
        #pragma unroll
        for (int i = 0; i < 4; i++) {
            int idx = tid + i * 256;
            int t = idx >> 5, kq = (idx & 31) * 4;
            *(float4*)&kfs[t][kq] = *(const float4*)(kfb + (size_t)(t0 + t) * DHH + kq);
        }
        {
            int t = tid >> 3, vq = (tid & 7) * 4;
            *(float4*)&vns[t][vq] = *(const float4*)(vb + (size_t)(t0 + t) * DHH + vbase + vq);
        }
        __syncthreads();
        if (tid < 32) {
            float s = 0.f;
            #pragma unroll 8
            for (int k = 0; k < 128; k++) {
                int kk = (k + tid) & 127;
                s += kfs[tid][kk] * mn[kk];
            }
            dns[tid] = fmaxf(s, EPSV);
        }
        __syncthreads();
        {
            float numv[4] = {0.f, 0.f, 0.f, 0.f};
            for (int k = 0; k < 128; k++) {
                float mval = mkv[k * DHH + vbase + vlane];
                #pragma unroll
                for (int j = 0; j < 4; j++) numv[j] += kfs[tg * 4 + j][k] * mval;
            }
            #pragma unroll
            for (int j = 0; j < 4; j++) vns[tg * 4 + j][vlane] -= numv[j] / dns[tg * 4 + j];
        }
        __syncthreads();
        #pragma unroll 4
        for (int t = 0; t < 32; t++) {
            float4 a = *(const float4*)&kfs[t][ty * 4];
            float4 b = *(const float4*)&vns[t][tx * 4];
            float av[4] = {a.x, a.y, a.z, a.w};
            float bv[4] = {b.x, b.y, b.z, b.w};
            #pragma unroll
            for (int i = 0; i < 4; i++)
                #pragma unroll
                for (int j = 0; j < 4; j++) C[i][j] += av[i] * bv[j];
        }
    }
    #pragma unroll
    for (int i = 0; i < 4; i++)
        #pragma unroll
        for (int j = 0; j < 4; j++) {
            int kd = ty * 4 + i, vd = vbase + tx * 4 + j;
            out_kv[(size_t)bh * DHH * DHH + kd * DHH + vd] = C[i][j] + mkv[kd * DHH + vd];
        }
}

// ---------------- 8) new_norm: two-stage parallel sum ----------------
__global__ void newnorm_part_k() {
    int bh = blockIdx.x, ch = blockIdx.y;
    int k  = threadIdx.x;
    const float* kf = g_kf + (size_t)bh * NN * DHH + (size_t)ch * 256 * DHH;
    float s = 0.f;
    #pragma unroll 8
    for (int n_ = 0; n_ < 256; n_++) s += kf[(size_t)n_ * DHH + k];
    g_pnorm[((size_t)bh * 8 + ch) * DHH + k] = s;
}
__global__ void newnorm_red_k(const float* __restrict__ mem_norm, float* __restrict__ out_norm) {
    int bh = blockIdx.x;
    int k  = threadIdx.x;
    float s = mem_norm[bh * DHH + k];
    #pragma unroll
    for (int c = 0; c < 8; c++) s += g_pnorm[((size_t)bh * 8 + c) * DHH + k];
    out_norm[bh * DHH + k] = s;
}

// ---------------- launch ----------------
extern "C" void kernel_launch(void* const* d_in, const int* in_sizes, int n_in,
                              void* d_out, int out_size) {
    (void)in_sizes; (void)n_in; (void)out_size;
    const float* x          = (const float*)d_in[0];
    const float* gamma      = (const float*)d_in[1];
    const float* w_qkv      = (const float*)d_in[2];
    const float* w_out      = (const float*)d_in[3];
    const float* head_gates = (const float*)d_in[4];
    const float* mem_kv     = (const float*)d_in[5];
    const float* mem_norm   = (const float*)d_in[6];
    float* out      = (float*)d_out;
    float* out_kv   = out + (size_t)BB * NN * DIMM;
    float* out_norm = out_kv + BB * HH * DHH * DHH;

    const int FLASH_SMEM = 25600 * 4;     // 102400 B
    const int GEMM_SMEM  = 4 * 4608 * 4;  // 73728 B
    cudaFuncSetAttribute(flash_tc, cudaFuncAttributeMaxDynamicSharedMemorySize, FLASH_SMEM);
    cudaFuncSetAttribute(sgemm_tc, cudaFuncAttributeMaxDynamicSharedMemorySize, GEMM_SMEM);

    rmsnorm_k<<<BB * NN, 256>>>(x, gamma);
    sgemm_tc<<<dim3(S3 / 128, BB * NN / 128), 256, GEMM_SMEM>>>(0, w_qkv, nullptr);
    rope_feat_k<<<BB * HH * NN / 4, dim3(64, 4)>>>();
    flash_tc<<<dim3(NN / 64, BB * HH), 256, FLASH_SMEM>>>();
    retrieve_gate_k<<<dim3(NN / 32, BB * HH), 128>>>(mem_kv, mem_norm, head_gates);
    sgemm_tc<<<dim3(DIMM / 128, BB * NN / 128), 256, GEMM_SMEM>>>(1, w_out, out);
    newkv_k<<<dim3(BB * HH, 4), 256>>>(mem_kv, mem_norm, out_kv);
    newnorm_part_k<<<dim3(BB * HH, 8), 128>>>();
    newnorm_red_k<<<BB * HH, 128>>>(mem_norm, out_norm);
}

// round 12
// speedup vs baseline: 3.1068x; 1.0288x over previous
#include <cuda_runtime.h>
#include <math.h>
#include <stdint.h>

#define BB   2
#define NN   2048
#define DIMM 1024
#define HH   8
#define DHH  128
#define S3   (3*DIMM)
#define SCALE_Q 0.08838834764831845f
#define EPSV 1e-10f

// ---------------- scratch (static device globals; no allocation) ----------------
__device__ float g_xn  [BB*NN*DIMM];          // tf32-rounded
__device__ float g_q   [BB*HH*NN*DHH];
__device__ float g_k   [BB*HH*NN*DHH];
__device__ float g_v   [BB*HH*NN*DHH];
__device__ float g_qr  [BB*HH*NN*DHH];
__device__ float g_qf  [BB*HH*NN*DHH];
__device__ float g_kf  [BB*HH*NN*DHH];
__device__ float g_attn[BB*HH*NN*DHH];
__device__ float g_comb[BB*NN*DIMM];          // tf32-rounded
__device__ float g_pnorm[BB*HH*8*DHH];
__device__ float2 g_krhl[BB*HH*NN*DHH];       // pre-split rotated K (tf32 hi, lo)
__device__ float2 g_vhl [BB*HH*NN*DHH];       // pre-split V
__device__ uint32_t g_wqt[S3*DIMM];           // tf32 w_qkv
__device__ uint32_t g_wot[DIMM*DIMM];         // tf32 w_out

// ---------------- helpers ----------------
__device__ __forceinline__ uint32_t f2tf32(float f) {
    uint32_t r;
    asm("cvt.rna.tf32.f32 %0, %1;" : "=r"(r) : "f"(f));
    return r;
}
__device__ __forceinline__ float tf32f(float f) { return __uint_as_float(f2tf32(f)); }

__device__ __forceinline__ void mma_tf32(float* d, const uint32_t* a, const uint32_t* b) {
    asm volatile(
        "mma.sync.aligned.m16n8k8.row.col.f32.tf32.tf32.f32 "
        "{%0,%1,%2,%3}, {%4,%5,%6,%7}, {%8,%9}, {%0,%1,%2,%3};\n"
        : "+f"(d[0]), "+f"(d[1]), "+f"(d[2]), "+f"(d[3])
        : "r"(a[0]), "r"(a[1]), "r"(a[2]), "r"(a[3]), "r"(b[0]), "r"(b[1]));
}
__device__ __forceinline__ void ldsm4(uint32_t* r, uint32_t addr) {
    asm volatile("ldmatrix.sync.aligned.m8n8.x4.shared.b16 {%0,%1,%2,%3}, [%4];"
                 : "=r"(r[0]), "=r"(r[1]), "=r"(r[2]), "=r"(r[3]) : "r"(addr));
}
__device__ __forceinline__ uint32_t smem_u32(const void* p) {
    uint32_t a;
    asm("{ .reg .u64 t; cvta.to.shared.u64 t, %1; cvt.u32.u64 %0, t; }" : "=r"(a) : "l"(p));
    return a;
}
#define CPA16(dst, src) asm volatile("cp.async.cg.shared.global [%0], [%1], 16;" :: "r"(dst), "l"(src))

// ---------------- 0) weight tf32 pre-convert ----------------
__global__ void wcvt_k(const float* __restrict__ w, uint32_t* __restrict__ o) {
    int i = blockIdx.x * 256 + threadIdx.x;
    float4 v = ((const float4*)w)[i];
    ((uint4*)o)[i] = make_uint4(f2tf32(v.x), f2tf32(v.y), f2tf32(v.z), f2tf32(v.w));
}

// ---------------- 1) RMSNorm (stores tf32-rounded; consumed only by GEMM) ----------------
__global__ void rmsnorm_k(const float* __restrict__ x, const float* __restrict__ gamma) {
    int row = blockIdx.x;
    const float* xr = x + (size_t)row * DIMM;
    float ss = 0.f;
    for (int i = threadIdx.x; i < DIMM; i += 256) { float v = xr[i]; ss += v * v; }
    #pragma unroll
    for (int o = 16; o > 0; o >>= 1) ss += __shfl_xor_sync(0xffffffffu, ss, o);
    __shared__ float red[8];
    __shared__ float sinv;
    if ((threadIdx.x & 31) == 0) red[threadIdx.x >> 5] = ss;
    __syncthreads();
    if (threadIdx.x == 0) {
        float t = 0.f;
        #pragma unroll
        for (int i = 0; i < 8; i++) t += red[i];
        sinv = 32.0f / fmaxf(sqrtf(t), 1e-12f);
    }
    __syncthreads();
    float inv = sinv;
    float* o = g_xn + (size_t)row * DIMM;
    for (int i = threadIdx.x; i < DIMM; i += 256) o[i] = tf32f(xr[i] * inv * gamma[i]);
}

// ---------------- 2/6) tf32 TC GEMM: cp.async + ldmatrix, double-buffered ----------------
// Inputs already tf32-rounded. smem As[2][128][36] + Bs[2][128][36] = 73728 B.
__global__ void __launch_bounds__(256) sgemm_tc(int mode, float* __restrict__ outp) {
    extern __shared__ uint32_t smem_u[];
    const uint32_t* A = (mode == 0) ? (const uint32_t*)g_xn : (const uint32_t*)g_comb;
    const uint32_t* B = (mode == 0) ? g_wqt : g_wot;
    const int K = DIMM;
    int tid  = threadIdx.x;
    int lane = tid & 31, warp = tid >> 5;
    int wm = warp >> 2, wn = warp & 3;
    int r  = lane >> 2, cc = lane & 3;
    int rbase = tid >> 3;                 // 0..31
    int kq    = (tid & 7) * 4;            // element offset, 16B granules

    uint32_t sbase = smem_u32(smem_u);
    // ldmatrix per-lane tile offsets (bytes). A tiles: t&1 -> row+8, t>>1 -> col+4.
    uint32_t aoff = ((lane & 7) + (((lane >> 3) & 1) << 3)) * 144 + ((lane >> 4) & 1) * 16;
    // B tiles: t>>1 -> row+8, t&1 -> col+4.
    uint32_t boff = ((lane & 7) + (((lane >> 4) & 1) << 3)) * 144 + ((lane >> 3) & 1) * 16;

    float acc[4][4][4];
    #pragma unroll
    for (int mt = 0; mt < 4; mt++)
        #pragma unroll
        for (int nt = 0; nt < 4; nt++)
            #pragma unroll
            for (int i = 0; i < 4; i++) acc[mt][nt][i] = 0.f;

    size_t aBase = (size_t)(blockIdx.y * 128) * K;
    size_t bBase = (size_t)(blockIdx.x * 128) * K;

    // per-thread cp.async smem dst offsets (bytes), A rows rbase+32i
    uint32_t dstA0 = sbase + (rbase * 36 + kq) * 4;
    uint32_t dstB0 = sbase + 36864 + (rbase * 36 + kq) * 4;

    // prologue: stage 0
    #pragma unroll
    for (int i = 0; i < 4; i++) {
        int row = rbase + 32 * i;
        CPA16(dstA0 + i * (32 * 144), A + aBase + (size_t)row * K + kq);
        CPA16(dstB0 + i * (32 * 144), B + bBase + (size_t)row * K + kq);
    }
    asm volatile("cp.async.commit_group;");

    for (int kt = 0; kt < 32; kt++) {
        int cur = kt & 1;
        asm volatile("cp.async.wait_group 0;");
        __syncthreads();                   // visibility + all readers of next buffer done
        if (kt < 31) {
            int k0 = (kt + 1) * 32;
            uint32_t bufo = ((kt + 1) & 1) * 18432;
            #pragma unroll
            for (int i = 0; i < 4; i++) {
                int row = rbase + 32 * i;
                CPA16(dstA0 + bufo + i * (32 * 144), A + aBase + (size_t)row * K + k0 + kq);
                CPA16(dstB0 + bufo + i * (32 * 144), B + bBase + (size_t)row * K + k0 + kq);
            }
            asm volatile("cp.async.commit_group;");
        }
        uint32_t abase_s = sbase + cur * 18432 + aoff + (wm * 64) * 144;
        uint32_t bbase_s = sbase + 36864 + cur * 18432 + boff + (wn * 32) * 144;
        #pragma unroll
        for (int ks = 0; ks < 32; ks += 8) {
            uint32_t af[4][4], bf01[4], bf23[4];
            #pragma unroll
            for (int mt = 0; mt < 4; mt++)
                ldsm4(af[mt], abase_s + mt * (16 * 144) + ks * 4);
            ldsm4(bf01, bbase_s + ks * 4);                    // nt0,nt1
            ldsm4(bf23, bbase_s + 16 * 144 + ks * 4);         // nt2,nt3
            #pragma unroll
            for (int mt = 0; mt < 4; mt++) {
                mma_tf32(acc[mt][0], af[mt], &bf01[0]);
                mma_tf32(acc[mt][1], af[mt], &bf01[2]);
                mma_tf32(acc[mt][2], af[mt], &bf23[0]);
                mma_tf32(acc[mt][3], af[mt], &bf23[2]);
            }
        }
    }

    #pragma unroll
    for (int mt = 0; mt < 4; mt++) {
        #pragma unroll
        for (int half = 0; half < 2; half++) {
            int row = blockIdx.y * 128 + wm * 64 + mt * 16 + r + half * 8;
            #pragma unroll
            for (int nt = 0; nt < 4; nt++) {
                int col = blockIdx.x * 128 + wn * 32 + nt * 8 + 2 * cc;
                float v0 = acc[mt][nt][half * 2 + 0];
                float v1 = acc[mt][nt][half * 2 + 1];
                if (mode == 0) {
                    int b_ = row >> 11, n_ = row & (NN - 1);
                    int sel = col >> 10, rem = col & 1023;
                    int h = rem >> 7, dd = rem & 127;
                    float* dst = (sel == 0) ? g_q : ((sel == 1) ? g_k : g_v);
                    float2* p = (float2*)&dst[((size_t)(b_ * HH + h) * NN + n_) * DHH + dd];
                    *p = make_float2(v0, v1);
                } else {
                    float2* p = (float2*)&outp[(size_t)row * DIMM + col];
                    *p = make_float2(v0, v1);
                }
            }
        }
    }
}

// ---------------- 3) RoPE + elu features + tf32 hi/lo pre-split of K_rot and V ----------------
__global__ void rope_feat_k() {
    int gid = blockIdx.x * blockDim.y + threadIdx.y;
    int p   = threadIdx.x;
    int n_  = gid & (NN - 1);
    size_t base = (size_t)gid * DHH;
    float inv = powf(10000.0f, -(float)(2 * p) * (1.0f / 128.0f));
    float ang = (float)n_ * inv;
    float s, c;
    sincosf(ang, &s, &c);
    float q0 = g_q[base + 2*p], q1 = g_q[base + 2*p + 1];
    float k0 = g_k[base + 2*p], k1 = g_k[base + 2*p + 1];
    float sq0 = q0 * SCALE_Q, sq1 = q1 * SCALE_Q;
    g_qr[base + 2*p]     = sq0 * c - sq1 * s;
    g_qr[base + 2*p + 1] = sq1 * c + sq0 * s;
    float kr0 = k0 * c - k1 * s;
    float kr1 = k1 * c + k0 * s;
    float h;
    h = tf32f(kr0); g_krhl[base + 2*p]     = make_float2(h, tf32f(kr0 - h));
    h = tf32f(kr1); g_krhl[base + 2*p + 1] = make_float2(h, tf32f(kr1 - h));
    float v0 = g_v[base + 2*p], v1 = g_v[base + 2*p + 1];
    h = tf32f(v0); g_vhl[base + 2*p]     = make_float2(h, tf32f(v0 - h));
    h = tf32f(v1); g_vhl[base + 2*p + 1] = make_float2(h, tf32f(v1 - h));
    g_qf[base + 2*p]     = (q0 > 0.f) ? q0 + 1.f : expf(q0);
    g_qf[base + 2*p + 1] = (q1 > 0.f) ? q1 + 1.f : expf(q1);
    g_kf[base + 2*p]     = (k0 > 0.f) ? k0 + 1.f : expf(k0);
    g_kf[base + 2*p + 1] = (k1 > 0.f) ? k1 + 1.f : expf(k1);
}

// ---------------- 4) tensor-core causal flash attention (unchanged control) ----------------
__global__ void __launch_bounds__(256, 2) flash_tc() {
    extern __shared__ float sm[];
    float*  Qs   = sm;
    float2* Khl  = (float2*)(sm + 8448);
    float2* Vhl  = (float2*)(sm + 16896);
    float*  sm_m = sm + 25344;
    float*  sm_l = sm + 25472;

    int bh  = blockIdx.y;
    int it  = gridDim.x - 1 - blockIdx.x;
    int tid = threadIdx.x;
    int lane = tid & 31, warp = tid >> 5;
    int wg = warp >> 2, wq = warp & 3;
    int r = lane >> 2, c = lane & 3;

    const float* Qg = g_qr + ((size_t)bh * NN + it * 64) * DHH;
    for (int i = tid; i < 64 * 32; i += 256) {
        int row = i >> 5, col4 = (i & 31) * 4;
        *(float4*)&Qs[row * 132 + col4] = *(const float4*)(Qg + (size_t)row * DHH + col4);
    }

    float o[16][4];
    #pragma unroll
    for (int dt = 0; dt < 16; dt++)
        #pragma unroll
        for (int i = 0; i < 4; i++) o[dt][i] = 0.f;
    float m0 = -1e30f, m1 = -1e30f, l0 = 0.f, l1 = 0.f;
    int rg0 = it * 64 + wq * 16 + r;
    int rg1 = rg0 + 8;
    int rowmax = it * 64 + wq * 16 + 15;
    int rowmin = it * 64 + wq * 16;
    int ntiles = 2 * it + 2;

    for (int jt = 0; jt < ntiles; jt++) {
        __syncthreads();
        const float4* Kg = (const float4*)(g_krhl + ((size_t)bh * NN + jt * 32) * DHH);
        const float4* Vg = (const float4*)(g_vhl  + ((size_t)bh * NN + jt * 32) * DHH);
        for (int i = tid; i < 2048; i += 256) {
            int row = i >> 6, q4 = i & 63;
            ((float4*)&Khl[row * 132])[q4] = Kg[row * 64 + q4];
            ((float4*)&Vhl[row * 132])[q4] = Vg[row * 64 + q4];
        }
        __syncthreads();

        int kmin = jt * 32 + wg * 16;
        if (kmin > rowmax) continue;

        float s[2][4];
        #pragma unroll
        for (int nt = 0; nt < 2; nt++)
            #pragma unroll
            for (int i = 0; i < 4; i++) s[nt][i] = 0.f;

        #pragma unroll 4
        for (int ks = 0; ks < 16; ks++) {
            float qa0 = Qs[(wq*16 + r    ) * 132 + ks*8 + c];
            float qa1 = Qs[(wq*16 + r + 8) * 132 + ks*8 + c];
            float qa2 = Qs[(wq*16 + r    ) * 132 + ks*8 + c + 4];
            float qa3 = Qs[(wq*16 + r + 8) * 132 + ks*8 + c + 4];
            uint32_t ah[4];
            ah[0] = f2tf32(qa0);
            ah[1] = f2tf32(qa1);
            ah[2] = f2tf32(qa2);
            ah[3] = f2tf32(qa3);
            #pragma unroll
            for (int nt = 0; nt < 2; nt++) {
                float2 b0 = Khl[(wg*16 + nt*8 + r) * 132 + ks*8 + c];
                float2 b1 = Khl[(wg*16 + nt*8 + r) * 132 + ks*8 + c + 4];
                uint32_t bh_[2] = { __float_as_uint(b0.x), __float_as_uint(b1.x) };
                uint32_t bl_[2] = { __float_as_uint(b0.y), __float_as_uint(b1.y) };
                mma_tf32(s[nt], ah, bh_);
                mma_tf32(s[nt], ah, bl_);
            }
        }

        if (kmin + 15 > rowmin) {
            #pragma unroll
            for (int nt = 0; nt < 2; nt++) {
                int cg = kmin + nt * 8 + 2 * c;
                if (cg     > rg0) s[nt][0] = -1e30f;
                if (cg + 1 > rg0) s[nt][1] = -1e30f;
                if (cg     > rg1) s[nt][2] = -1e30f;
                if (cg + 1 > rg1) s[nt][3] = -1e30f;
            }
        }

        float tmax0 = fmaxf(fmaxf(s[0][0], s[0][1]), fmaxf(s[1][0], s[1][1]));
        float tmax1 = fmaxf(fmaxf(s[0][2], s[0][3]), fmaxf(s[1][2], s[1][3]));
        tmax0 = fmaxf(tmax0, __shfl_xor_sync(0xffffffffu, tmax0, 1));
        tmax0 = fmaxf(tmax0, __shfl_xor_sync(0xffffffffu, tmax0, 2));
        tmax1 = fmaxf(tmax1, __shfl_xor_sync(0xffffffffu, tmax1, 1));
        tmax1 = fmaxf(tmax1, __shfl_xor_sync(0xffffffffu, tmax1, 2));
        float mn0 = fmaxf(m0, tmax0), mn1 = fmaxf(m1, tmax1);
        float al0 = __expf(m0 - mn0), al1 = __expf(m1 - mn1);
        float ps0 = 0.f, ps1 = 0.f;
        #pragma unroll
        for (int nt = 0; nt < 2; nt++) {
            s[nt][0] = __expf(s[nt][0] - mn0);
            s[nt][1] = __expf(s[nt][1] - mn0);
            s[nt][2] = __expf(s[nt][2] - mn1);
            s[nt][3] = __expf(s[nt][3] - mn1);
            ps0 += s[nt][0] + s[nt][1];
            ps1 += s[nt][2] + s[nt][3];
        }
        ps0 += __shfl_xor_sync(0xffffffffu, ps0, 1);
        ps0 += __shfl_xor_sync(0xffffffffu, ps0, 2);
        ps1 += __shfl_xor_sync(0xffffffffu, ps1, 1);
        ps1 += __shfl_xor_sync(0xffffffffu, ps1, 2);
        l0 = l0 * al0 + ps0;  l1 = l1 * al1 + ps1;
        m0 = mn0;  m1 = mn1;
        if (__any_sync(0xffffffffu, (al0 < 1.f) | (al1 < 1.f))) {
            #pragma unroll
            for (int dt = 0; dt < 16; dt++) {
                o[dt][0] *= al0; o[dt][1] *= al0;
                o[dt][2] *= al1; o[dt][3] *= al1;
            }
        }

        int sA = (lane & ~3) | (c >> 1);
        int sB = sA + 2;
        #pragma unroll
        for (int nt = 0; nt < 2; nt++) {
            float t00 = __shfl_sync(0xffffffffu, s[nt][0], sA);
            float t01 = __shfl_sync(0xffffffffu, s[nt][1], sA);
            float u00 = __shfl_sync(0xffffffffu, s[nt][0], sB);
            float u01 = __shfl_sync(0xffffffffu, s[nt][1], sB);
            float t10 = __shfl_sync(0xffffffffu, s[nt][2], sA);
            float t11 = __shfl_sync(0xffffffffu, s[nt][3], sA);
            float u10 = __shfl_sync(0xffffffffu, s[nt][2], sB);
            float u11 = __shfl_sync(0xffffffffu, s[nt][3], sB);
            float a0 = (c & 1) ? t01 : t00;
            float a2 = (c & 1) ? u01 : u00;
            float a1 = (c & 1) ? t11 : t10;
            float a3 = (c & 1) ? u11 : u10;
            uint32_t ph[4];
            ph[0] = f2tf32(a0);
            ph[1] = f2tf32(a1);
            ph[2] = f2tf32(a2);
            ph[3] = f2tf32(a3);
            #pragma unroll
            for (int dt = 0; dt < 16; dt++) {
                float2 v0 = Vhl[(wg*16 + nt*8 + c    ) * 132 + dt*8 + r];
                float2 v1 = Vhl[(wg*16 + nt*8 + c + 4) * 132 + dt*8 + r];
                uint32_t vh_[2] = { __float_as_uint(v0.x), __float_as_uint(v1.x) };
                uint32_t vl_[2] = { __float_as_uint(v0.y), __float_as_uint(v1.y) };
                mma_tf32(o[dt], ph, vh_);
                mma_tf32(o[dt], ph, vl_);
            }
        }
    }

    int lr0 = wq * 16 + r;
    __syncthreads();
    if (c == 0) {
        sm_m[wg * 64 + lr0]     = m0;  sm_l[wg * 64 + lr0]     = l0;
        sm_m[wg * 64 + lr0 + 8] = m1;  sm_l[wg * 64 + lr0 + 8] = l1;
    }
    __syncthreads();
    float mo0 = sm_m[(1 - wg) * 64 + lr0],     lo0 = sm_l[(1 - wg) * 64 + lr0];
    float mo1 = sm_m[(1 - wg) * 64 + lr0 + 8], lo1 = sm_l[(1 - wg) * 64 + lr0 + 8];
    float mg0 = fmaxf(m0, mo0), mg1 = fmaxf(m1, mo1);
    float lg0 = l0 * __expf(m0 - mg0) + lo0 * __expf(mo0 - mg0);
    float lg1 = l1 * __expf(m1 - mg1) + lo1 * __expf(mo1 - mg1);
    float sc0 = __expf(m0 - mg0) / lg0;
    float sc1 = __expf(m1 - mg1) / lg1;

    float* Obuf = Qs;
    if (wg == 1) {
        #pragma unroll
        for (int dt = 0; dt < 16; dt++) {
            *(float2*)&Obuf[lr0 * 132 + dt*8 + 2*c]       = make_float2(o[dt][0]*sc0, o[dt][1]*sc0);
            *(float2*)&Obuf[(lr0+8) * 132 + dt*8 + 2*c]   = make_float2(o[dt][2]*sc1, o[dt][3]*sc1);
        }
    }
    __syncthreads();
    if (wg == 0) {
        float* O0 = g_attn + ((size_t)bh * NN + it * 64 + lr0    ) * DHH;
        float* O1 = g_attn + ((size_t)bh * NN + it * 64 + lr0 + 8) * DHH;
        #pragma unroll
        for (int dt = 0; dt < 16; dt++) {
            float2 b0 = *(float2*)&Obuf[lr0 * 132 + dt*8 + 2*c];
            float2 b1 = *(float2*)&Obuf[(lr0+8) * 132 + dt*8 + 2*c];
            *(float2*)&O0[dt*8 + 2*c] = make_float2(o[dt][0]*sc0 + b0.x, o[dt][1]*sc0 + b0.y);
            *(float2*)&O1[dt*8 + 2*c] = make_float2(o[dt][2]*sc1 + b1.x, o[dt][3]*sc1 + b1.y);
        }
    }
}

// ---------------- 5) memory retrieval + gate blend (stores tf32-rounded) ----------------
__global__ void retrieve_gate_k(const float* __restrict__ mem_kv,
                                const float* __restrict__ mem_norm,
                                const float* __restrict__ head_gates) {
    int bh = blockIdx.y;
    int b_ = bh >> 3, h = bh & 7;
    int t0 = blockIdx.x * 32;
    int v  = threadIdx.x;
    __shared__ float qsT[128][36];
    __shared__ float dn[32];
    __shared__ float mn[128];
    mn[v] = mem_norm[bh * DHH + v];
    const float* qf = g_qf + ((size_t)bh * NN + t0) * DHH;
    for (int i = v; i < 32 * 32; i += 128) {
        int t = i >> 5;
        int k4 = (i & 31) * 4;
        float4 qv = *(const float4*)(qf + (size_t)t * DHH + k4);
        qsT[k4+0][t] = qv.x; qsT[k4+1][t] = qv.y; qsT[k4+2][t] = qv.z; qsT[k4+3][t] = qv.w;
    }
    __syncthreads();
    if (v < 32) {
        float s = 0.f;
        #pragma unroll 8
        for (int k = 0; k < 128; k++) s += qsT[k][v] * mn[k];
        dn[v] = fmaxf(s, EPSV);
    }
    __syncthreads();
    const float* mkv = mem_kv + (size_t)bh * DHH * DHH;
    float num[32];
    #pragma unroll
    for (int t = 0; t < 32; t++) num[t] = 0.f;
    for (int k = 0; k < 128; k++) {
        float mval = mkv[k * DHH + v];
        #pragma unroll
        for (int t8 = 0; t8 < 8; t8++) {
            float4 qv = *(const float4*)&qsT[k][t8 * 4];
            num[t8*4+0] += qv.x * mval;
            num[t8*4+1] += qv.y * mval;
            num[t8*4+2] += qv.z * mval;
            num[t8*4+3] += qv.w * mval;
        }
    }
    float g = 1.f / (1.f + expf(-head_gates[h]));
    const float* at = g_attn + ((size_t)bh * NN + t0) * DHH;
    float* cb = g_comb + ((size_t)b_ * NN + t0) * DIMM + h * DHH;
    #pragma unroll 4
    for (int t = 0; t < 32; t++) {
        float mo = num[t] / dn[t];
        cb[(size_t)t * DIMM + v] = tf32f(at[(size_t)t * DHH + v] * g + mo * (1.f - g));
    }
}

// ---------------- 7) delta-rule new_kv (split 4x over v-dim) ----------------
__global__ void __launch_bounds__(256) newkv_k(const float* __restrict__ mem_kv,
                                               const float* __restrict__ mem_norm,
                                               float* __restrict__ out_kv) {
    int bh    = blockIdx.x;
    int vbase = blockIdx.y * 32;
    int tid   = threadIdx.x;
    int ty = tid >> 3, tx = tid & 7;
    __shared__ float kfs[32][128];
    __shared__ float vns[32][32];
    __shared__ float mn[128];
    __shared__ float dns[32];
    if (tid < 128) mn[tid] = mem_norm[bh * DHH + tid];
    const float* mkv = mem_kv + (size_t)bh * DHH * DHH;
    const float* kfb = g_kf + (size_t)bh * NN * DHH;
    const float* vb  = g_v  + (size_t)bh * NN * DHH;
    float C[4][4];
    #pragma unroll
    for (int i = 0; i < 4; i++)
        #pragma unroll
        for (int j = 0; j < 4; j++) C[i][j] = 0.f;

    int vlane = tid & 31, tg = tid >> 5;

    for (int t0 = 0; t0 < NN; t0 += 32) {
        __syncthreads();
        #pragma unroll
        for (int i = 0; i < 4; i++) {
            int idx = tid + i * 256;
            int t = idx >> 5, kq = (idx & 31) * 4;
            *(float4*)&kfs[t][kq] = *(const float4*)(kfb + (size_t)(t0 + t) * DHH + kq);
        }
        {
            int t = tid >> 3, vq = (tid & 7) * 4;
            *(float4*)&vns[t][vq] = *(const float4*)(vb + (size_t)(t0 + t) * DHH + vbase + vq);
        }
        __syncthreads();
        if (tid < 32) {
            float s = 0.f;
            #pragma unroll 8
            for (int k = 0; k < 128; k++) {
                int kk = (k + tid) & 127;
                s += kfs[tid][kk] * mn[kk];
            }
            dns[tid] = fmaxf(s, EPSV);
        }
        __syncthreads();
        {
            float numv[4] = {0.f, 0.f, 0.f, 0.f};
            for (int k = 0; k < 128; k++) {
                float mval = mkv[k * DHH + vbase + vlane];
                #pragma unroll
                for (int j = 0; j < 4; j++) numv[j] += kfs[tg * 4 + j][k] * mval;
            }
            #pragma unroll
            for (int j = 0; j < 4; j++) vns[tg * 4 + j][vlane] -= numv[j] / dns[tg * 4 + j];
        }
        __syncthreads();
        #pragma unroll 4
        for (int t = 0; t < 32; t++) {
            float4 a = *(const float4*)&kfs[t][ty * 4];
            float4 b = *(const float4*)&vns[t][tx * 4];
            float av[4] = {a.x, a.y, a.z, a.w};
            float bv[4] = {b.x, b.y, b.z, b.w};
            #pragma unroll
            for (int i = 0; i < 4; i++)
                #pragma unroll
                for (int j = 0; j < 4; j++) C[i][j] += av[i] * bv[j];
        }
    }
    #pragma unroll
    for (int i = 0; i < 4; i++)
        #pragma unroll
        for (int j = 0; j < 4; j++) {
            int kd = ty * 4 + i, vd = vbase + tx * 4 + j;
            out_kv[(size_t)bh * DHH * DHH + kd * DHH + vd] = C[i][j] + mkv[kd * DHH + vd];
        }
}

// ---------------- 8) new_norm: two-stage parallel sum ----------------
__global__ void newnorm_part_k() {
    int bh = blockIdx.x, ch = blockIdx.y;
    int k  = threadIdx.x;
    const float* kf = g_kf + (size_t)bh * NN * DHH + (size_t)ch * 256 * DHH;
    float s = 0.f;
    #pragma unroll 8
    for (int n_ = 0; n_ < 256; n_++) s += kf[(size_t)n_ * DHH + k];
    g_pnorm[((size_t)bh * 8 + ch) * DHH + k] = s;
}
__global__ void newnorm_red_k(const float* __restrict__ mem_norm, float* __restrict__ out_norm) {
    int bh = blockIdx.x;
    int k  = threadIdx.x;
    float s = mem_norm[bh * DHH + k];
    #pragma unroll
    for (int c = 0; c < 8; c++) s += g_pnorm[((size_t)bh * 8 + c) * DHH + k];
    out_norm[bh * DHH + k] = s;
}

// ---------------- launch ----------------
extern "C" void kernel_launch(void* const* d_in, const int* in_sizes, int n_in,
                              void* d_out, int out_size) {
    (void)in_sizes; (void)n_in; (void)out_size;
    const float* x          = (const float*)d_in[0];
    const float* gamma      = (const float*)d_in[1];
    const float* w_qkv      = (const float*)d_in[2];
    const float* w_out      = (const float*)d_in[3];
    const float* head_gates = (const float*)d_in[4];
    const float* mem_kv     = (const float*)d_in[5];
    const float* mem_norm   = (const float*)d_in[6];
    float* out      = (float*)d_out;
    float* out_kv   = out + (size_t)BB * NN * DIMM;
    float* out_norm = out_kv + BB * HH * DHH * DHH;

    const int FLASH_SMEM = 25600 * 4;     // 102400 B
    const int GEMM_SMEM  = 4 * 4608 * 4;  // 73728 B
    cudaFuncSetAttribute(flash_tc, cudaFuncAttributeMaxDynamicSharedMemorySize, FLASH_SMEM);
    cudaFuncSetAttribute(sgemm_tc, cudaFuncAttributeMaxDynamicSharedMemorySize, GEMM_SMEM);

    uint32_t* wq_t; cudaGetSymbolAddress((void**)&wq_t, g_wqt);
    uint32_t* wo_t; cudaGetSymbolAddress((void**)&wo_t, g_wot);

    wcvt_k<<<S3 * DIMM / 1024, 256>>>(w_qkv, wq_t);
    wcvt_k<<<DIMM * DIMM / 1024, 256>>>(w_out, wo_t);
    rmsnorm_k<<<BB * NN, 256>>>(x, gamma);
    sgemm_tc<<<dim3(S3 / 128, BB * NN / 128), 256, GEMM_SMEM>>>(0, nullptr);
    rope_feat_k<<<BB * HH * NN / 4, dim3(64, 4)>>>();
    flash_tc<<<dim3(NN / 64, BB * HH), 256, FLASH_SMEM>>>();
    retrieve_gate_k<<<dim3(NN / 32, BB * HH), 128>>>(mem_kv, mem_norm, head_gates);
    sgemm_tc<<<dim3(DIMM / 128, BB * NN / 128), 256, GEMM_SMEM>>>(1, out);
    newkv_k<<<dim3(BB * HH, 4), 256>>>(mem_kv, mem_norm, out_kv);
    newnorm_part_k<<<dim3(BB * HH, 8), 128>>>();
    newnorm_red_k<<<BB * HH, 128>>>(mem_norm, out_norm);
}

// round 14
// speedup vs baseline: 4.4117x; 1.4200x over previous
#include <cuda_runtime.h>
#include <math.h>
#include <stdint.h>

#define BB   2
#define NN   2048
#define DIMM 1024
#define HH   8
#define DHH  128
#define S3   (3*DIMM)
#define SCALE_Q 0.08838834764831845f
#define EPSV 1e-10f

// ---------------- scratch (static device globals; no allocation) ----------------
__device__ float g_xn  [BB*NN*DIMM];          // tf32-rounded
__device__ float g_q   [BB*HH*NN*DHH];
__device__ float g_k   [BB*HH*NN*DHH];
__device__ float g_v   [BB*HH*NN*DHH];
__device__ float g_qr  [BB*HH*NN*DHH];
__device__ float g_qf  [BB*HH*NN*DHH];
__device__ float g_kf  [BB*HH*NN*DHH];
__device__ float g_attn[BB*HH*NN*DHH];
__device__ float g_comb[BB*NN*DIMM];          // tf32-rounded
__device__ float g_pnorm[BB*HH*8*DHH];
__device__ float2 g_krhl[BB*HH*NN*DHH];       // pre-split rotated K (tf32 hi, lo)
__device__ float  g_vt  [BB*HH*NN*DHH];       // tf32-rounded V
__device__ float  g_ckv [BB*HH*4*DHH*DHH];    // newkv partials
__device__ uint32_t g_wqt[S3*DIMM];           // tf32 w_qkv
__device__ uint32_t g_wot[DIMM*DIMM];         // tf32 w_out

// ---------------- helpers ----------------
__device__ __forceinline__ uint32_t f2tf32(float f) {
    uint32_t r;
    asm("cvt.rna.tf32.f32 %0, %1;" : "=r"(r) : "f"(f));
    return r;
}
__device__ __forceinline__ float tf32f(float f) { return __uint_as_float(f2tf32(f)); }

__device__ __forceinline__ void mma_tf32(float* d, const uint32_t* a, const uint32_t* b) {
    asm volatile(
        "mma.sync.aligned.m16n8k8.row.col.f32.tf32.tf32.f32 "
        "{%0,%1,%2,%3}, {%4,%5,%6,%7}, {%8,%9}, {%0,%1,%2,%3};\n"
        : "+f"(d[0]), "+f"(d[1]), "+f"(d[2]), "+f"(d[3])
        : "r"(a[0]), "r"(a[1]), "r"(a[2]), "r"(a[3]), "r"(b[0]), "r"(b[1]));
}
__device__ __forceinline__ void ldsm4(uint32_t* r, uint32_t addr) {
    asm volatile("ldmatrix.sync.aligned.m8n8.x4.shared.b16 {%0,%1,%2,%3}, [%4];"
                 : "=r"(r[0]), "=r"(r[1]), "=r"(r[2]), "=r"(r[3]) : "r"(addr));
}
__device__ __forceinline__ uint32_t smem_u32(const void* p) {
    uint32_t a;
    asm("{ .reg .u64 t; cvta.to.shared.u64 t, %1; cvt.u32.u64 %0, t; }" : "=r"(a) : "l"(p));
    return a;
}
#define CPA16(dst, src) asm volatile("cp.async.cg.shared.global [%0], [%1], 16;" :: "r"(dst), "l"(src))

// ---------------- 0) weight tf32 pre-convert ----------------
__global__ void wcvt_k(const float* __restrict__ w, uint32_t* __restrict__ o) {
    int i = blockIdx.x * 256 + threadIdx.x;
    float4 v = ((const float4*)w)[i];
    ((uint4*)o)[i] = make_uint4(f2tf32(v.x), f2tf32(v.y), f2tf32(v.z), f2tf32(v.w));
}

// ---------------- 1) RMSNorm (stores tf32-rounded) ----------------
__global__ void rmsnorm_k(const float* __restrict__ x, const float* __restrict__ gamma) {
    int row = blockIdx.x;
    const float* xr = x + (size_t)row * DIMM;
    float ss = 0.f;
    for (int i = threadIdx.x; i < DIMM; i += 256) { float v = xr[i]; ss += v * v; }
    #pragma unroll
    for (int o = 16; o > 0; o >>= 1) ss += __shfl_xor_sync(0xffffffffu, ss, o);
    __shared__ float red[8];
    __shared__ float sinv;
    if ((threadIdx.x & 31) == 0) red[threadIdx.x >> 5] = ss;
    __syncthreads();
    if (threadIdx.x == 0) {
        float t = 0.f;
        #pragma unroll
        for (int i = 0; i < 8; i++) t += red[i];
        sinv = 32.0f / fmaxf(sqrtf(t), 1e-12f);
    }
    __syncthreads();
    float inv = sinv;
    float* o = g_xn + (size_t)row * DIMM;
    for (int i = threadIdx.x; i < DIMM; i += 256) o[i] = tf32f(xr[i] * inv * gamma[i]);
}

// ---------------- 2/6) tf32 TC GEMM: cp.async + ldmatrix, double-buffered ----------------
__global__ void __launch_bounds__(256) sgemm_tc(int mode, float* __restrict__ outp) {
    extern __shared__ uint32_t smem_u[];
    const uint32_t* A = (mode == 0) ? (const uint32_t*)g_xn : (const uint32_t*)g_comb;
    const uint32_t* B = (mode == 0) ? g_wqt : g_wot;
    const int K = DIMM;
    int tid  = threadIdx.x;
    int lane = tid & 31, warp = tid >> 5;
    int wm = warp >> 2, wn = warp & 3;
    int r  = lane >> 2, cc = lane & 3;
    int rbase = tid >> 3;
    int kq    = (tid & 7) * 4;

    uint32_t sbase = smem_u32(smem_u);
    uint32_t aoff = ((lane & 7) + (((lane >> 3) & 1) << 3)) * 144 + ((lane >> 4) & 1) * 16;
    uint32_t boff = ((lane & 7) + (((lane >> 4) & 1) << 3)) * 144 + ((lane >> 3) & 1) * 16;

    float acc[4][4][4];
    #pragma unroll
    for (int mt = 0; mt < 4; mt++)
        #pragma unroll
        for (int nt = 0; nt < 4; nt++)
            #pragma unroll
            for (int i = 0; i < 4; i++) acc[mt][nt][i] = 0.f;

    size_t aBase = (size_t)(blockIdx.y * 128) * K;
    size_t bBase = (size_t)(blockIdx.x * 128) * K;

    uint32_t dstA0 = sbase + (rbase * 36 + kq) * 4;
    uint32_t dstB0 = sbase + 36864 + (rbase * 36 + kq) * 4;

    #pragma unroll
    for (int i = 0; i < 4; i++) {
        int row = rbase + 32 * i;
        CPA16(dstA0 + i * (32 * 144), A + aBase + (size_t)row * K + kq);
        CPA16(dstB0 + i * (32 * 144), B + bBase + (size_t)row * K + kq);
    }
    asm volatile("cp.async.commit_group;");

    for (int kt = 0; kt < 32; kt++) {
        int cur = kt & 1;
        asm volatile("cp.async.wait_group 0;");
        __syncthreads();
        if (kt < 31) {
            int k0 = (kt + 1) * 32;
            uint32_t bufo = ((kt + 1) & 1) * 18432;
            #pragma unroll
            for (int i = 0; i < 4; i++) {
                int row = rbase + 32 * i;
                CPA16(dstA0 + bufo + i * (32 * 144), A + aBase + (size_t)row * K + k0 + kq);
                CPA16(dstB0 + bufo + i * (32 * 144), B + bBase + (size_t)row * K + k0 + kq);
            }
            asm volatile("cp.async.commit_group;");
        }
        uint32_t abase_s = sbase + cur * 18432 + aoff + (wm * 64) * 144;
        uint32_t bbase_s = sbase + 36864 + cur * 18432 + boff + (wn * 32) * 144;
        #pragma unroll
        for (int ks = 0; ks < 32; ks += 8) {
            uint32_t af[4][4], bf01[4], bf23[4];
            #pragma unroll
            for (int mt = 0; mt < 4; mt++)
                ldsm4(af[mt], abase_s + mt * (16 * 144) + ks * 4);
            ldsm4(bf01, bbase_s + ks * 4);
            ldsm4(bf23, bbase_s + 16 * 144 + ks * 4);
            #pragma unroll
            for (int mt = 0; mt < 4; mt++) {
                mma_tf32(acc[mt][0], af[mt], &bf01[0]);
                mma_tf32(acc[mt][1], af[mt], &bf01[2]);
                mma_tf32(acc[mt][2], af[mt], &bf23[0]);
                mma_tf32(acc[mt][3], af[mt], &bf23[2]);
            }
        }
    }

    #pragma unroll
    for (int mt = 0; mt < 4; mt++) {
        #pragma unroll
        for (int half = 0; half < 2; half++) {
            int row = blockIdx.y * 128 + wm * 64 + mt * 16 + r + half * 8;
            #pragma unroll
            for (int nt = 0; nt < 4; nt++) {
                int col = blockIdx.x * 128 + wn * 32 + nt * 8 + 2 * cc;
                float v0 = acc[mt][nt][half * 2 + 0];
                float v1 = acc[mt][nt][half * 2 + 1];
                if (mode == 0) {
                    int b_ = row >> 11, n_ = row & (NN - 1);
                    int sel = col >> 10, rem = col & 1023;
                    int h = rem >> 7, dd = rem & 127;
                    float* dst = (sel == 0) ? g_q : ((sel == 1) ? g_k : g_v);
                    float2* p = (float2*)&dst[((size_t)(b_ * HH + h) * NN + n_) * DHH + dd];
                    *p = make_float2(v0, v1);
                } else {
                    float2* p = (float2*)&outp[(size_t)row * DIMM + col];
                    *p = make_float2(v0, v1);
                }
            }
        }
    }
}

// ---------------- 3) RoPE + elu features + tf32 splits (K hi/lo, V plain) ----------------
__global__ void rope_feat_k() {
    int gid = blockIdx.x * blockDim.y + threadIdx.y;
    int p   = threadIdx.x;
    int n_  = gid & (NN - 1);
    size_t base = (size_t)gid * DHH;
    float inv = powf(10000.0f, -(float)(2 * p) * (1.0f / 128.0f));
    float ang = (float)n_ * inv;
    float s, c;
    sincosf(ang, &s, &c);
    float q0 = g_q[base + 2*p], q1 = g_q[base + 2*p + 1];
    float k0 = g_k[base + 2*p], k1 = g_k[base + 2*p + 1];
    float sq0 = q0 * SCALE_Q, sq1 = q1 * SCALE_Q;
    g_qr[base + 2*p]     = sq0 * c - sq1 * s;
    g_qr[base + 2*p + 1] = sq1 * c + sq0 * s;
    float kr0 = k0 * c - k1 * s;
    float kr1 = k1 * c + k0 * s;
    float h;
    h = tf32f(kr0); g_krhl[base + 2*p]     = make_float2(h, tf32f(kr0 - h));
    h = tf32f(kr1); g_krhl[base + 2*p + 1] = make_float2(h, tf32f(kr1 - h));
    g_vt[base + 2*p]     = tf32f(g_v[base + 2*p]);
    g_vt[base + 2*p + 1] = tf32f(g_v[base + 2*p + 1]);
    g_qf[base + 2*p]     = (q0 > 0.f) ? q0 + 1.f : expf(q0);
    g_qf[base + 2*p + 1] = (q1 > 0.f) ? q1 + 1.f : expf(q1);
    g_kf[base + 2*p]     = (k0 > 0.f) ? k0 + 1.f : expf(k0);
    g_kf[base + 2*p + 1] = (k1 > 0.f) ? k1 + 1.f : expf(k1);
}

// ---------------- 4) TC causal flash attention: K 2-term, V 1-term ----------------
// smem: Qs [64][132] | Khl float2 [32][132] | Vs [32][136] | m,l. 86016 B.
__global__ void __launch_bounds__(256, 2) flash_tc() {
    extern __shared__ float sm[];
    float*  Qs   = sm;                          // 8448
    float2* Khl  = (float2*)(sm + 8448);        // 8448 floats
    float*  Vs   = sm + 16896;                  // 4352
    float*  sm_m = sm + 21248;                  // 128
    float*  sm_l = sm + 21376;                  // 128

    int bh  = blockIdx.y;
    int it  = gridDim.x - 1 - blockIdx.x;
    int tid = threadIdx.x;
    int lane = tid & 31, warp = tid >> 5;
    int wg = warp >> 2, wq = warp & 3;
    int r = lane >> 2, c = lane & 3;

    const float* Qg = g_qr + ((size_t)bh * NN + it * 64) * DHH;
    for (int i = tid; i < 64 * 32; i += 256) {
        int row = i >> 5, col4 = (i & 31) * 4;
        *(float4*)&Qs[row * 132 + col4] = *(const float4*)(Qg + (size_t)row * DHH + col4);
    }

    float o[16][4];
    #pragma unroll
    for (int dt = 0; dt < 16; dt++)
        #pragma unroll
        for (int i = 0; i < 4; i++) o[dt][i] = 0.f;
    float m0 = -1e30f, m1 = -1e30f, l0 = 0.f, l1 = 0.f;
    int rg0 = it * 64 + wq * 16 + r;
    int rg1 = rg0 + 8;
    int rowmax = it * 64 + wq * 16 + 15;
    int rowmin = it * 64 + wq * 16;
    int ntiles = 2 * it + 2;

    for (int jt = 0; jt < ntiles; jt++) {
        __syncthreads();
        const float4* Kg = (const float4*)(g_krhl + ((size_t)bh * NN + jt * 32) * DHH);
        const float4* Vg = (const float4*)(g_vt   + ((size_t)bh * NN + jt * 32) * DHH);
        for (int i = tid; i < 2048; i += 256) {
            int row = i >> 6, q4 = i & 63;
            ((float4*)&Khl[row * 132])[q4] = Kg[row * 64 + q4];
            if (i < 1024) {
                int vr = i >> 5, vq = i & 31;
                ((float4*)&Vs[vr * 136])[vq] = Vg[vr * 32 + vq];
            }
        }
        __syncthreads();

        int kmin = jt * 32 + wg * 16;
        if (kmin > rowmax) continue;

        float s[2][4];
        #pragma unroll
        for (int nt = 0; nt < 2; nt++)
            #pragma unroll
            for (int i = 0; i < 4; i++) s[nt][i] = 0.f;

        #pragma unroll 4
        for (int ks = 0; ks < 16; ks++) {
            float qa0 = Qs[(wq*16 + r    ) * 132 + ks*8 + c];
            float qa1 = Qs[(wq*16 + r + 8) * 132 + ks*8 + c];
            float qa2 = Qs[(wq*16 + r    ) * 132 + ks*8 + c + 4];
            float qa3 = Qs[(wq*16 + r + 8) * 132 + ks*8 + c + 4];
            uint32_t ah[4];
            ah[0] = f2tf32(qa0);
            ah[1] = f2tf32(qa1);
            ah[2] = f2tf32(qa2);
            ah[3] = f2tf32(qa3);
            #pragma unroll
            for (int nt = 0; nt < 2; nt++) {
                float2 b0 = Khl[(wg*16 + nt*8 + r) * 132 + ks*8 + c];
                float2 b1 = Khl[(wg*16 + nt*8 + r) * 132 + ks*8 + c + 4];
                uint32_t bh_[2] = { __float_as_uint(b0.x), __float_as_uint(b1.x) };
                uint32_t bl_[2] = { __float_as_uint(b0.y), __float_as_uint(b1.y) };
                mma_tf32(s[nt], ah, bh_);
                mma_tf32(s[nt], ah, bl_);
            }
        }

        if (kmin + 15 > rowmin) {
            #pragma unroll
            for (int nt = 0; nt < 2; nt++) {
                int cg = kmin + nt * 8 + 2 * c;
                if (cg     > rg0) s[nt][0] = -1e30f;
                if (cg + 1 > rg0) s[nt][1] = -1e30f;
                if (cg     > rg1) s[nt][2] = -1e30f;
                if (cg + 1 > rg1) s[nt][3] = -1e30f;
            }
        }

        float tmax0 = fmaxf(fmaxf(s[0][0], s[0][1]), fmaxf(s[1][0], s[1][1]));
        float tmax1 = fmaxf(fmaxf(s[0][2], s[0][3]), fmaxf(s[1][2], s[1][3]));
        tmax0 = fmaxf(tmax0, __shfl_xor_sync(0xffffffffu, tmax0, 1));
        tmax0 = fmaxf(tmax0, __shfl_xor_sync(0xffffffffu, tmax0, 2));
        tmax1 = fmaxf(tmax1, __shfl_xor_sync(0xffffffffu, tmax1, 1));
        tmax1 = fmaxf(tmax1, __shfl_xor_sync(0xffffffffu, tmax1, 2));
        float mn0 = fmaxf(m0, tmax0), mn1 = fmaxf(m1, tmax1);
        float al0 = __expf(m0 - mn0), al1 = __expf(m1 - mn1);
        float ps0 = 0.f, ps1 = 0.f;
        #pragma unroll
        for (int nt = 0; nt < 2; nt++) {
            s[nt][0] = __expf(s[nt][0] - mn0);
            s[nt][1] = __expf(s[nt][1] - mn0);
            s[nt][2] = __expf(s[nt][2] - mn1);
            s[nt][3] = __expf(s[nt][3] - mn1);
            ps0 += s[nt][0] + s[nt][1];
            ps1 += s[nt][2] + s[nt][3];
        }
        ps0 += __shfl_xor_sync(0xffffffffu, ps0, 1);
        ps0 += __shfl_xor_sync(0xffffffffu, ps0, 2);
        ps1 += __shfl_xor_sync(0xffffffffu, ps1, 1);
        ps1 += __shfl_xor_sync(0xffffffffu, ps1, 2);
        l0 = l0 * al0 + ps0;  l1 = l1 * al1 + ps1;
        m0 = mn0;  m1 = mn1;
        if (__any_sync(0xffffffffu, (al0 < 1.f) | (al1 < 1.f))) {
            #pragma unroll
            for (int dt = 0; dt < 16; dt++) {
                o[dt][0] *= al0; o[dt][1] *= al0;
                o[dt][2] *= al1; o[dt][3] *= al1;
            }
        }

        int sA = (lane & ~3) | (c >> 1);
        int sB = sA + 2;
        #pragma unroll
        for (int nt = 0; nt < 2; nt++) {
            float t00 = __shfl_sync(0xffffffffu, s[nt][0], sA);
            float t01 = __shfl_sync(0xffffffffu, s[nt][1], sA);
            float u00 = __shfl_sync(0xffffffffu, s[nt][0], sB);
            float u01 = __shfl_sync(0xffffffffu, s[nt][1], sB);
            float t10 = __shfl_sync(0xffffffffu, s[nt][2], sA);
            float t11 = __shfl_sync(0xffffffffu, s[nt][3], sA);
            float u10 = __shfl_sync(0xffffffffu, s[nt][2], sB);
            float u11 = __shfl_sync(0xffffffffu, s[nt][3], sB);
            float a0 = (c & 1) ? t01 : t00;
            float a2 = (c & 1) ? u01 : u00;
            float a1 = (c & 1) ? t11 : t10;
            float a3 = (c & 1) ? u11 : u10;
            uint32_t ph[4];
            ph[0] = f2tf32(a0);
            ph[1] = f2tf32(a1);
            ph[2] = f2tf32(a2);
            ph[3] = f2tf32(a3);
            #pragma unroll
            for (int dt = 0; dt < 16; dt++) {
                float v0 = Vs[(wg*16 + nt*8 + c    ) * 136 + dt*8 + r];
                float v1 = Vs[(wg*16 + nt*8 + c + 4) * 136 + dt*8 + r];
                uint32_t vh_[2] = { __float_as_uint(v0), __float_as_uint(v1) };
                mma_tf32(o[dt], ph, vh_);
            }
        }
    }

    int lr0 = wq * 16 + r;
    __syncthreads();
    if (c == 0) {
        sm_m[wg * 64 + lr0]     = m0;  sm_l[wg * 64 + lr0]     = l0;
        sm_m[wg * 64 + lr0 + 8] = m1;  sm_l[wg * 64 + lr0 + 8] = l1;
    }
    __syncthreads();
    float mo0 = sm_m[(1 - wg) * 64 + lr0],     lo0 = sm_l[(1 - wg) * 64 + lr0];
    float mo1 = sm_m[(1 - wg) * 64 + lr0 + 8], lo1 = sm_l[(1 - wg) * 64 + lr0 + 8];
    float mg0 = fmaxf(m0, mo0), mg1 = fmaxf(m1, mo1);
    float lg0 = l0 * __expf(m0 - mg0) + lo0 * __expf(mo0 - mg0);
    float lg1 = l1 * __expf(m1 - mg1) + lo1 * __expf(mo1 - mg1);
    float sc0 = __expf(m0 - mg0) / lg0;
    float sc1 = __expf(m1 - mg1) / lg1;

    float* Obuf = Qs;
    if (wg == 1) {
        #pragma unroll
        for (int dt = 0; dt < 16; dt++) {
            *(float2*)&Obuf[lr0 * 132 + dt*8 + 2*c]       = make_float2(o[dt][0]*sc0, o[dt][1]*sc0);
            *(float2*)&Obuf[(lr0+8) * 132 + dt*8 + 2*c]   = make_float2(o[dt][2]*sc1, o[dt][3]*sc1);
        }
    }
    __syncthreads();
    if (wg == 0) {
        float* O0 = g_attn + ((size_t)bh * NN + it * 64 + lr0    ) * DHH;
        float* O1 = g_attn + ((size_t)bh * NN + it * 64 + lr0 + 8) * DHH;
        #pragma unroll
        for (int dt = 0; dt < 16; dt++) {
            float2 b0 = *(float2*)&Obuf[lr0 * 132 + dt*8 + 2*c];
            float2 b1 = *(float2*)&Obuf[(lr0+8) * 132 + dt*8 + 2*c];
            *(float2*)&O0[dt*8 + 2*c] = make_float2(o[dt][0]*sc0 + b0.x, o[dt][1]*sc0 + b0.y);
            *(float2*)&O1[dt*8 + 2*c] = make_float2(o[dt][2]*sc1 + b1.x, o[dt][3]*sc1 + b1.y);
        }
    }
}

// ---------------- 5) memory retrieval + gate blend (stores tf32-rounded) ----------------
__global__ void retrieve_gate_k(const float* __restrict__ mem_kv,
                                const float* __restrict__ mem_norm,
                                const float* __restrict__ head_gates) {
    int bh = blockIdx.y;
    int b_ = bh >> 3, h = bh & 7;
    int t0 = blockIdx.x * 32;
    int v  = threadIdx.x;
    __shared__ float qsT[128][36];
    __shared__ float dn[32];
    __shared__ float mn[128];
    mn[v] = mem_norm[bh * DHH + v];
    const float* qf = g_qf + ((size_t)bh * NN + t0) * DHH;
    for (int i = v; i < 32 * 32; i += 128) {
        int t = i >> 5;
        int k4 = (i & 31) * 4;
        float4 qv = *(const float4*)(qf + (size_t)t * DHH + k4);
        qsT[k4+0][t] = qv.x; qsT[k4+1][t] = qv.y; qsT[k4+2][t] = qv.z; qsT[k4+3][t] = qv.w;
    }
    __syncthreads();
    if (v < 32) {
        float s = 0.f;
        #pragma unroll 8
        for (int k = 0; k < 128; k++) s += qsT[k][v] * mn[k];
        dn[v] = fmaxf(s, EPSV);
    }
    __syncthreads();
    const float* mkv = mem_kv + (size_t)bh * DHH * DHH;
    float num[32];
    #pragma unroll
    for (int t = 0; t < 32; t++) num[t] = 0.f;
    for (int k = 0; k < 128; k++) {
        float mval = mkv[k * DHH + v];
        #pragma unroll
        for (int t8 = 0; t8 < 8; t8++) {
            float4 qv = *(const float4*)&qsT[k][t8 * 4];
            num[t8*4+0] += qv.x * mval;
            num[t8*4+1] += qv.y * mval;
            num[t8*4+2] += qv.z * mval;
            num[t8*4+3] += qv.w * mval;
        }
    }
    float g = 1.f / (1.f + expf(-head_gates[h]));
    const float* at = g_attn + ((size_t)bh * NN + t0) * DHH;
    float* cb = g_comb + ((size_t)b_ * NN + t0) * DIMM + h * DHH;
    #pragma unroll 4
    for (int t = 0; t < 32; t++) {
        float mo = num[t] / dn[t];
        cb[(size_t)t * DIMM + v] = tf32f(at[(size_t)t * DHH + v] * g + mo * (1.f - g));
    }
}

// ---------------- 7a) delta-rule new_kv partials (split tokens 4x, v-dim 4x) ----------------
__global__ void __launch_bounds__(256) newkv_part_k(const float* __restrict__ mem_kv,
                                                    const float* __restrict__ mem_norm) {
    int bh    = blockIdx.x;
    int vbase = blockIdx.y * 32;
    int tch   = blockIdx.z;
    int tid   = threadIdx.x;
    int ty = tid >> 3, tx = tid & 7;
    __shared__ float kfs[32][128];
    __shared__ float vns[32][32];
    __shared__ float mn[128];
    __shared__ float dns[32];
    if (tid < 128) mn[tid] = mem_norm[bh * DHH + tid];
    const float* mkv = mem_kv + (size_t)bh * DHH * DHH;
    const float* kfb = g_kf + (size_t)bh * NN * DHH;
    const float* vb  = g_v  + (size_t)bh * NN * DHH;
    float C[4][4];
    #pragma unroll
    for (int i = 0; i < 4; i++)
        #pragma unroll
        for (int j = 0; j < 4; j++) C[i][j] = 0.f;

    int vlane = tid & 31, tg = tid >> 5;
    int tstart = tch * 512;

    for (int t0 = tstart; t0 < tstart + 512; t0 += 32) {
        __syncthreads();
        #pragma unroll
        for (int i = 0; i < 4; i++) {
            int idx = tid + i * 256;
            int t = idx >> 5, kq = (idx & 31) * 4;
            *(float4*)&kfs[t][kq] = *(const float4*)(kfb + (size_t)(t0 + t) * DHH + kq);
        }
        {
            int t = tid >> 3, vq = (tid & 7) * 4;
            *(float4*)&vns[t][vq] = *(const float4*)(vb + (size_t)(t0 + t) * DHH + vbase + vq);
        }
        __syncthreads();
        if (tid < 32) {
            float s = 0.f;
            #pragma unroll 8
            for (int k = 0; k < 128; k++) {
                int kk = (k + tid) & 127;
                s += kfs[tid][kk] * mn[kk];
            }
            dns[tid] = fmaxf(s, EPSV);
        }
        __syncthreads();
        {
            float numv[4] = {0.f, 0.f, 0.f, 0.f};
            for (int k = 0; k < 128; k++) {
                float mval = mkv[k * DHH + vbase + vlane];
                #pragma unroll
                for (int j = 0; j < 4; j++) numv[j] += kfs[tg * 4 + j][k] * mval;
            }
            #pragma unroll
            for (int j = 0; j < 4; j++) vns[tg * 4 + j][vlane] -= numv[j] / dns[tg * 4 + j];
        }
        __syncthreads();
        #pragma unroll 4
        for (int t = 0; t < 32; t++) {
            float4 a = *(const float4*)&kfs[t][ty * 4];
            float4 b = *(const float4*)&vns[t][tx * 4];
            float av[4] = {a.x, a.y, a.z, a.w};
            float bv[4] = {b.x, b.y, b.z, b.w};
            #pragma unroll
            for (int i = 0; i < 4; i++)
                #pragma unroll
                for (int j = 0; j < 4; j++) C[i][j] += av[i] * bv[j];
        }
    }
    #pragma unroll
    for (int i = 0; i < 4; i++)
        #pragma unroll
        for (int j = 0; j < 4; j++) {
            int kd = ty * 4 + i, vd = vbase + tx * 4 + j;
            g_ckv[(((size_t)bh * 4 + tch) * DHH + kd) * DHH + vd] = C[i][j];
        }
}

// ---------------- 7b) new_kv reduce ----------------
__global__ void newkv_red_k(const float* __restrict__ mem_kv, float* __restrict__ out_kv) {
    int bh = blockIdx.x;
    const float4* mk = (const float4*)(mem_kv + (size_t)bh * DHH * DHH);
    float4* ok = (float4*)(out_kv + (size_t)bh * DHH * DHH);
    for (int i = threadIdx.x; i < DHH * DHH / 4; i += 256) {
        float4 s = mk[i];
        #pragma unroll
        for (int c = 0; c < 4; c++) {
            float4 p = ((const float4*)(g_ckv + ((size_t)bh * 4 + c) * DHH * DHH))[i];
            s.x += p.x; s.y += p.y; s.z += p.z; s.w += p.w;
        }
        ok[i] = s;
    }
}

// ---------------- 8) new_norm: two-stage parallel sum ----------------
__global__ void newnorm_part_k() {
    int bh = blockIdx.x, ch = blockIdx.y;
    int k  = threadIdx.x;
    const float* kf = g_kf + (size_t)bh * NN * DHH + (size_t)ch * 256 * DHH;
    float s = 0.f;
    #pragma unroll 8
    for (int n_ = 0; n_ < 256; n_++) s += kf[(size_t)n_ * DHH + k];
    g_pnorm[((size_t)bh * 8 + ch) * DHH + k] = s;
}
__global__ void newnorm_red_k(const float* __restrict__ mem_norm, float* __restrict__ out_norm) {
    int bh = blockIdx.x;
    int k  = threadIdx.x;
    float s = mem_norm[bh * DHH + k];
    #pragma unroll
    for (int c = 0; c < 8; c++) s += g_pnorm[((size_t)bh * 8 + c) * DHH + k];
    out_norm[bh * DHH + k] = s;
}

// ---------------- launch ----------------
extern "C" void kernel_launch(void* const* d_in, const int* in_sizes, int n_in,
                              void* d_out, int out_size) {
    (void)in_sizes; (void)n_in; (void)out_size;
    const float* x          = (const float*)d_in[0];
    const float* gamma      = (const float*)d_in[1];
    const float* w_qkv      = (const float*)d_in[2];
    const float* w_out      = (const float*)d_in[3];
    const float* head_gates = (const float*)d_in[4];
    const float* mem_kv     = (const float*)d_in[5];
    const float* mem_norm   = (const float*)d_in[6];
    float* out      = (float*)d_out;
    float* out_kv   = out + (size_t)BB * NN * DIMM;
    float* out_norm = out_kv + BB * HH * DHH * DHH;

    const int FLASH_SMEM = 21504 * 4;     // 86016 B
    const int GEMM_SMEM  = 4 * 4608 * 4;  // 73728 B
    cudaFuncSetAttribute(flash_tc, cudaFuncAttributeMaxDynamicSharedMemorySize, FLASH_SMEM);
    cudaFuncSetAttribute(sgemm_tc, cudaFuncAttributeMaxDynamicSharedMemorySize, GEMM_SMEM);

    uint32_t* wq_t; cudaGetSymbolAddress((void**)&wq_t, g_wqt);
    uint32_t* wo_t; cudaGetSymbolAddress((void**)&wo_t, g_wot);

    wcvt_k<<<S3 * DIMM / 1024, 256>>>(w_qkv, wq_t);
    wcvt_k<<<DIMM * DIMM / 1024, 256>>>(w_out, wo_t);
    rmsnorm_k<<<BB * NN, 256>>>(x, gamma);
    sgemm_tc<<<dim3(S3 / 128, BB * NN / 128), 256, GEMM_SMEM>>>(0, nullptr);
    rope_feat_k<<<BB * HH * NN / 4, dim3(64, 4)>>>();
    flash_tc<<<dim3(NN / 64, BB * HH), 256, FLASH_SMEM>>>();
    retrieve_gate_k<<<dim3(NN / 32, BB * HH), 128>>>(mem_kv, mem_norm, head_gates);
    sgemm_tc<<<dim3(DIMM / 128, BB * NN / 128), 256, GEMM_SMEM>>>(1, out);
    newkv_part_k<<<dim3(BB * HH, 4, 4), 256>>>(mem_kv, mem_norm);
    newkv_red_k<<<BB * HH, 256>>>(mem_kv, out_kv);
    newnorm_part_k<<<dim3(BB * HH, 8), 128>>>();
    newnorm_red_k<<<BB * HH, 128>>>(mem_norm, out_norm);
}

// round 15
// speedup vs baseline: 4.5639x; 1.0345x over previous
#include <cuda_runtime.h>
#include <math.h>
#include <stdint.h>

#define BB   2
#define NN   2048
#define DIMM 1024
#define HH   8
#define DHH  128
#define S3   (3*DIMM)
#define SCALE_Q 0.08838834764831845f
#define EPSV 1e-10f

// ---------------- scratch (static device globals; no allocation) ----------------
__device__ float g_xn  [BB*NN*DIMM];          // tf32-rounded
__device__ float g_q   [BB*HH*NN*DHH];
__device__ float g_k   [BB*HH*NN*DHH];
__device__ float g_v   [BB*HH*NN*DHH];
__device__ float g_qr  [BB*HH*NN*DHH];        // tf32-rounded rotated Q
__device__ float g_qf  [BB*HH*NN*DHH];
__device__ float g_kf  [BB*HH*NN*DHH];
__device__ float g_attn[BB*HH*NN*DHH];
__device__ float g_comb[BB*NN*DIMM];          // tf32-rounded
__device__ float g_pnorm[BB*HH*8*DHH];
__device__ float g_krh [BB*HH*NN*DHH];        // rotated K tf32 hi
__device__ float g_krl [BB*HH*NN*DHH];        // rotated K tf32 lo
__device__ float g_vt  [BB*HH*NN*DHH];        // tf32-rounded V
__device__ float g_ckv [BB*HH*4*DHH*DHH];     // newkv partials
__device__ uint32_t g_wqt[S3*DIMM];           // tf32 w_qkv
__device__ uint32_t g_wot[DIMM*DIMM];         // tf32 w_out

// ---------------- helpers ----------------
__device__ __forceinline__ uint32_t f2tf32(float f) {
    uint32_t r;
    asm("cvt.rna.tf32.f32 %0, %1;" : "=r"(r) : "f"(f));
    return r;
}
__device__ __forceinline__ float tf32f(float f) { return __uint_as_float(f2tf32(f)); }

__device__ __forceinline__ void mma_tf32(float* d, const uint32_t* a, const uint32_t* b) {
    asm volatile(
        "mma.sync.aligned.m16n8k8.row.col.f32.tf32.tf32.f32 "
        "{%0,%1,%2,%3}, {%4,%5,%6,%7}, {%8,%9}, {%0,%1,%2,%3};\n"
        : "+f"(d[0]), "+f"(d[1]), "+f"(d[2]), "+f"(d[3])
        : "r"(a[0]), "r"(a[1]), "r"(a[2]), "r"(a[3]), "r"(b[0]), "r"(b[1]));
}
__device__ __forceinline__ void ldsm4(uint32_t* r, uint32_t addr) {
    asm volatile("ldmatrix.sync.aligned.m8n8.x4.shared.b16 {%0,%1,%2,%3}, [%4];"
                 : "=r"(r[0]), "=r"(r[1]), "=r"(r[2]), "=r"(r[3]) : "r"(addr));
}
__device__ __forceinline__ uint32_t smem_u32(const void* p) {
    uint32_t a;
    asm("{ .reg .u64 t; cvta.to.shared.u64 t, %1; cvt.u32.u64 %0, t; }" : "=r"(a) : "l"(p));
    return a;
}
#define CPA16(dst, src) asm volatile("cp.async.cg.shared.global [%0], [%1], 16;" :: "r"(dst), "l"(src))

// ---------------- 0) weight tf32 pre-convert ----------------
__global__ void wcvt_k(const float* __restrict__ w, uint32_t* __restrict__ o) {
    int i = blockIdx.x * 256 + threadIdx.x;
    float4 v = ((const float4*)w)[i];
    ((uint4*)o)[i] = make_uint4(f2tf32(v.x), f2tf32(v.y), f2tf32(v.z), f2tf32(v.w));
}

// ---------------- 1) RMSNorm (stores tf32-rounded) ----------------
__global__ void rmsnorm_k(const float* __restrict__ x, const float* __restrict__ gamma) {
    int row = blockIdx.x;
    const float* xr = x + (size_t)row * DIMM;
    float ss = 0.f;
    for (int i = threadIdx.x; i < DIMM; i += 256) { float v = xr[i]; ss += v * v; }
    #pragma unroll
    for (int o = 16; o > 0; o >>= 1) ss += __shfl_xor_sync(0xffffffffu, ss, o);
    __shared__ float red[8];
    __shared__ float sinv;
    if ((threadIdx.x & 31) == 0) red[threadIdx.x >> 5] = ss;
    __syncthreads();
    if (threadIdx.x == 0) {
        float t = 0.f;
        #pragma unroll
        for (int i = 0; i < 8; i++) t += red[i];
        sinv = 32.0f / fmaxf(sqrtf(t), 1e-12f);
    }
    __syncthreads();
    float inv = sinv;
    float* o = g_xn + (size_t)row * DIMM;
    for (int i = threadIdx.x; i < DIMM; i += 256) o[i] = tf32f(xr[i] * inv * gamma[i]);
}

// ---------------- 2/6) tf32 TC GEMM: cp.async + ldmatrix, double-buffered ----------------
__global__ void __launch_bounds__(256) sgemm_tc(int mode, float* __restrict__ outp) {
    extern __shared__ uint32_t smem_u[];
    const uint32_t* A = (mode == 0) ? (const uint32_t*)g_xn : (const uint32_t*)g_comb;
    const uint32_t* B = (mode == 0) ? g_wqt : g_wot;
    const int K = DIMM;
    int tid  = threadIdx.x;
    int lane = tid & 31, warp = tid >> 5;
    int wm = warp >> 2, wn = warp & 3;
    int r  = lane >> 2, cc = lane & 3;
    int rbase = tid >> 3;
    int kq    = (tid & 7) * 4;

    uint32_t sbase = smem_u32(smem_u);
    uint32_t aoff = ((lane & 7) + (((lane >> 3) & 1) << 3)) * 144 + ((lane >> 4) & 1) * 16;
    uint32_t boff = ((lane & 7) + (((lane >> 4) & 1) << 3)) * 144 + ((lane >> 3) & 1) * 16;

    float acc[4][4][4];
    #pragma unroll
    for (int mt = 0; mt < 4; mt++)
        #pragma unroll
        for (int nt = 0; nt < 4; nt++)
            #pragma unroll
            for (int i = 0; i < 4; i++) acc[mt][nt][i] = 0.f;

    size_t aBase = (size_t)(blockIdx.y * 128) * K;
    size_t bBase = (size_t)(blockIdx.x * 128) * K;

    uint32_t dstA0 = sbase + (rbase * 36 + kq) * 4;
    uint32_t dstB0 = sbase + 36864 + (rbase * 36 + kq) * 4;

    #pragma unroll
    for (int i = 0; i < 4; i++) {
        int row = rbase + 32 * i;
        CPA16(dstA0 + i * (32 * 144), A + aBase + (size_t)row * K + kq);
        CPA16(dstB0 + i * (32 * 144), B + bBase + (size_t)row * K + kq);
    }
    asm volatile("cp.async.commit_group;");

    for (int kt = 0; kt < 32; kt++) {
        int cur = kt & 1;
        asm volatile("cp.async.wait_group 0;");
        __syncthreads();
        if (kt < 31) {
            int k0 = (kt + 1) * 32;
            uint32_t bufo = ((kt + 1) & 1) * 18432;
            #pragma unroll
            for (int i = 0; i < 4; i++) {
                int row = rbase + 32 * i;
                CPA16(dstA0 + bufo + i * (32 * 144), A + aBase + (size_t)row * K + k0 + kq);
                CPA16(dstB0 + bufo + i * (32 * 144), B + bBase + (size_t)row * K + k0 + kq);
            }
            asm volatile("cp.async.commit_group;");
        }
        uint32_t abase_s = sbase + cur * 18432 + aoff + (wm * 64) * 144;
        uint32_t bbase_s = sbase + 36864 + cur * 18432 + boff + (wn * 32) * 144;
        #pragma unroll
        for (int ks = 0; ks < 32; ks += 8) {
            uint32_t af[4][4], bf01[4], bf23[4];
            #pragma unroll
            for (int mt = 0; mt < 4; mt++)
                ldsm4(af[mt], abase_s + mt * (16 * 144) + ks * 4);
            ldsm4(bf01, bbase_s + ks * 4);
            ldsm4(bf23, bbase_s + 16 * 144 + ks * 4);
            #pragma unroll
            for (int mt = 0; mt < 4; mt++) {
                mma_tf32(acc[mt][0], af[mt], &bf01[0]);
                mma_tf32(acc[mt][1], af[mt], &bf01[2]);
                mma_tf32(acc[mt][2], af[mt], &bf23[0]);
                mma_tf32(acc[mt][3], af[mt], &bf23[2]);
            }
        }
    }

    #pragma unroll
    for (int mt = 0; mt < 4; mt++) {
        #pragma unroll
        for (int half = 0; half < 2; half++) {
            int row = blockIdx.y * 128 + wm * 64 + mt * 16 + r + half * 8;
            #pragma unroll
            for (int nt = 0; nt < 4; nt++) {
                int col = blockIdx.x * 128 + wn * 32 + nt * 8 + 2 * cc;
                float v0 = acc[mt][nt][half * 2 + 0];
                float v1 = acc[mt][nt][half * 2 + 1];
                if (mode == 0) {
                    int b_ = row >> 11, n_ = row & (NN - 1);
                    int sel = col >> 10, rem = col & 1023;
                    int h = rem >> 7, dd = rem & 127;
                    float* dst = (sel == 0) ? g_q : ((sel == 1) ? g_k : g_v);
                    float2* p = (float2*)&dst[((size_t)(b_ * HH + h) * NN + n_) * DHH + dd];
                    *p = make_float2(v0, v1);
                } else {
                    float2* p = (float2*)&outp[(size_t)row * DIMM + col];
                    *p = make_float2(v0, v1);
                }
            }
        }
    }
}

// ---------------- 3) RoPE + elu features; Q/K/V flash-ready formats ----------------
__global__ void rope_feat_k() {
    int gid = blockIdx.x * blockDim.y + threadIdx.y;
    int p   = threadIdx.x;
    int n_  = gid & (NN - 1);
    size_t base = (size_t)gid * DHH;
    float inv = powf(10000.0f, -(float)(2 * p) * (1.0f / 128.0f));
    float ang = (float)n_ * inv;
    float s, c;
    sincosf(ang, &s, &c);
    float q0 = g_q[base + 2*p], q1 = g_q[base + 2*p + 1];
    float k0 = g_k[base + 2*p], k1 = g_k[base + 2*p + 1];
    float sq0 = q0 * SCALE_Q, sq1 = q1 * SCALE_Q;
    g_qr[base + 2*p]     = tf32f(sq0 * c - sq1 * s);   // tf32-rounded (flash uses q hi only)
    g_qr[base + 2*p + 1] = tf32f(sq1 * c + sq0 * s);
    float kr0 = k0 * c - k1 * s;
    float kr1 = k1 * c + k0 * s;
    float h;
    h = tf32f(kr0); g_krh[base + 2*p]     = h; g_krl[base + 2*p]     = tf32f(kr0 - h);
    h = tf32f(kr1); g_krh[base + 2*p + 1] = h; g_krl[base + 2*p + 1] = tf32f(kr1 - h);
    g_vt[base + 2*p]     = tf32f(g_v[base + 2*p]);
    g_vt[base + 2*p + 1] = tf32f(g_v[base + 2*p + 1]);
    g_qf[base + 2*p]     = (q0 > 0.f) ? q0 + 1.f : expf(q0);
    g_qf[base + 2*p + 1] = (q1 > 0.f) ? q1 + 1.f : expf(q1);
    g_kf[base + 2*p]     = (k0 > 0.f) ? k0 + 1.f : expf(k0);
    g_kf[base + 2*p + 1] = (k1 > 0.f) ? k1 + 1.f : expf(k1);
}

// ---------------- 4) TC causal flash attention: ldmatrix Q/K paths ----------------
// smem floats: Qs[64][132] | Kh[32][132] | Kl[32][132] | Vs[32][136] | m,l. 86016 B.
__global__ void __launch_bounds__(256, 2) flash_tc() {
    extern __shared__ float sm[];
    float* Qs   = sm;                           // 8448
    float* Kh   = sm + 8448;                    // 4224
    float* Kl   = sm + 12672;                   // 4224
    float* Vs   = sm + 16896;                   // 4352
    float* sm_m = sm + 21248;                   // 128
    float* sm_l = sm + 21376;                   // 128

    int bh  = blockIdx.y;
    int it  = gridDim.x - 1 - blockIdx.x;
    int tid = threadIdx.x;
    int lane = tid & 31, warp = tid >> 5;
    int wg = warp >> 2, wq = warp & 3;
    int r = lane >> 2, c = lane & 3;

    uint32_t sbase = smem_u32(sm);
    // ldmatrix lane offsets for stride-132 rows (528 B)
    uint32_t aoffA = ((lane & 7) + (((lane >> 3) & 1) << 3)) * 528 + ((lane >> 4) & 1) * 16;
    uint32_t boffB = ((lane & 7) + (((lane >> 4) & 1) << 3)) * 528 + ((lane >> 3) & 1) * 16;
    uint32_t qb  = sbase + aoffA + (wq * 16) * 528;
    uint32_t khb = sbase + 8448 * 4  + boffB + (wg * 16) * 528;
    uint32_t klb = sbase + 12672 * 4 + boffB + (wg * 16) * 528;

    const float* Qg = g_qr + ((size_t)bh * NN + it * 64) * DHH;
    for (int i = tid; i < 64 * 32; i += 256) {
        int row = i >> 5, col4 = (i & 31) * 4;
        *(float4*)&Qs[row * 132 + col4] = *(const float4*)(Qg + (size_t)row * DHH + col4);
    }

    float o[16][4];
    #pragma unroll
    for (int dt = 0; dt < 16; dt++)
        #pragma unroll
        for (int i = 0; i < 4; i++) o[dt][i] = 0.f;
    float m0 = -1e30f, m1 = -1e30f, l0 = 0.f, l1 = 0.f;
    int rg0 = it * 64 + wq * 16 + r;
    int rg1 = rg0 + 8;
    int rowmax = it * 64 + wq * 16 + 15;
    int rowmin = it * 64 + wq * 16;
    int ntiles = 2 * it + 2;

    for (int jt = 0; jt < ntiles; jt++) {
        __syncthreads();
        const float4* Kgh = (const float4*)(g_krh + ((size_t)bh * NN + jt * 32) * DHH);
        const float4* Kgl = (const float4*)(g_krl + ((size_t)bh * NN + jt * 32) * DHH);
        const float4* Vg  = (const float4*)(g_vt  + ((size_t)bh * NN + jt * 32) * DHH);
        for (int i = tid; i < 1024; i += 256) {          // 32 rows x 32 float4 each
            int row = i >> 5, q4 = i & 31;
            ((float4*)&Kh[row * 132])[q4] = Kgh[row * 32 + q4];
            ((float4*)&Kl[row * 132])[q4] = Kgl[row * 32 + q4];
            ((float4*)&Vs[row * 136])[q4] = Vg [row * 32 + q4];
        }
        __syncthreads();

        int kmin = jt * 32 + wg * 16;
        if (kmin > rowmax) continue;

        float s[2][4];
        #pragma unroll
        for (int nt = 0; nt < 2; nt++)
            #pragma unroll
            for (int i = 0; i < 4; i++) s[nt][i] = 0.f;

        #pragma unroll 4
        for (int ks = 0; ks < 16; ks++) {
            uint32_t af[4], bh4[4], bl4[4];
            ldsm4(af,  qb  + ks * 32);
            ldsm4(bh4, khb + ks * 32);
            ldsm4(bl4, klb + ks * 32);
            mma_tf32(s[0], af, &bh4[0]);
            mma_tf32(s[0], af, &bl4[0]);
            mma_tf32(s[1], af, &bh4[2]);
            mma_tf32(s[1], af, &bl4[2]);
        }

        if (kmin + 15 > rowmin) {
            #pragma unroll
            for (int nt = 0; nt < 2; nt++) {
                int cg = kmin + nt * 8 + 2 * c;
                if (cg     > rg0) s[nt][0] = -1e30f;
                if (cg + 1 > rg0) s[nt][1] = -1e30f;
                if (cg     > rg1) s[nt][2] = -1e30f;
                if (cg + 1 > rg1) s[nt][3] = -1e30f;
            }
        }

        float tmax0 = fmaxf(fmaxf(s[0][0], s[0][1]), fmaxf(s[1][0], s[1][1]));
        float tmax1 = fmaxf(fmaxf(s[0][2], s[0][3]), fmaxf(s[1][2], s[1][3]));
        tmax0 = fmaxf(tmax0, __shfl_xor_sync(0xffffffffu, tmax0, 1));
        tmax0 = fmaxf(tmax0, __shfl_xor_sync(0xffffffffu, tmax0, 2));
        tmax1 = fmaxf(tmax1, __shfl_xor_sync(0xffffffffu, tmax1, 1));
        tmax1 = fmaxf(tmax1, __shfl_xor_sync(0xffffffffu, tmax1, 2));
        float mn0 = fmaxf(m0, tmax0), mn1 = fmaxf(m1, tmax1);
        float al0 = __expf(m0 - mn0), al1 = __expf(m1 - mn1);
        float ps0 = 0.f, ps1 = 0.f;
        #pragma unroll
        for (int nt = 0; nt < 2; nt++) {
            s[nt][0] = __expf(s[nt][0] - mn0);
            s[nt][1] = __expf(s[nt][1] - mn0);
            s[nt][2] = __expf(s[nt][2] - mn1);
            s[nt][3] = __expf(s[nt][3] - mn1);
            ps0 += s[nt][0] + s[nt][1];
            ps1 += s[nt][2] + s[nt][3];
        }
        ps0 += __shfl_xor_sync(0xffffffffu, ps0, 1);
        ps0 += __shfl_xor_sync(0xffffffffu, ps0, 2);
        ps1 += __shfl_xor_sync(0xffffffffu, ps1, 1);
        ps1 += __shfl_xor_sync(0xffffffffu, ps1, 2);
        l0 = l0 * al0 + ps0;  l1 = l1 * al1 + ps1;
        m0 = mn0;  m1 = mn1;
        if (__any_sync(0xffffffffu, (al0 < 1.f) | (al1 < 1.f))) {
            #pragma unroll
            for (int dt = 0; dt < 16; dt++) {
                o[dt][0] *= al0; o[dt][1] *= al0;
                o[dt][2] *= al1; o[dt][3] *= al1;
            }
        }

        int sA = (lane & ~3) | (c >> 1);
        int sB = sA + 2;
        #pragma unroll
        for (int nt = 0; nt < 2; nt++) {
            float t00 = __shfl_sync(0xffffffffu, s[nt][0], sA);
            float t01 = __shfl_sync(0xffffffffu, s[nt][1], sA);
            float u00 = __shfl_sync(0xffffffffu, s[nt][0], sB);
            float u01 = __shfl_sync(0xffffffffu, s[nt][1], sB);
            float t10 = __shfl_sync(0xffffffffu, s[nt][2], sA);
            float t11 = __shfl_sync(0xffffffffu, s[nt][3], sA);
            float u10 = __shfl_sync(0xffffffffu, s[nt][2], sB);
            float u11 = __shfl_sync(0xffffffffu, s[nt][3], sB);
            float a0 = (c & 1) ? t01 : t00;
            float a2 = (c & 1) ? u01 : u00;
            float a1 = (c & 1) ? t11 : t10;
            float a3 = (c & 1) ? u11 : u10;
            uint32_t ph[4];
            ph[0] = f2tf32(a0);
            ph[1] = f2tf32(a1);
            ph[2] = f2tf32(a2);
            ph[3] = f2tf32(a3);
            #pragma unroll
            for (int dt = 0; dt < 16; dt++) {
                float v0 = Vs[(wg*16 + nt*8 + c    ) * 136 + dt*8 + r];
                float v1 = Vs[(wg*16 + nt*8 + c + 4) * 136 + dt*8 + r];
                uint32_t vh_[2] = { __float_as_uint(v0), __float_as_uint(v1) };
                mma_tf32(o[dt], ph, vh_);
            }
        }
    }

    int lr0 = wq * 16 + r;
    __syncthreads();
    if (c == 0) {
        sm_m[wg * 64 + lr0]     = m0;  sm_l[wg * 64 + lr0]     = l0;
        sm_m[wg * 64 + lr0 + 8] = m1;  sm_l[wg * 64 + lr0 + 8] = l1;
    }
    __syncthreads();
    float mo0 = sm_m[(1 - wg) * 64 + lr0],     lo0 = sm_l[(1 - wg) * 64 + lr0];
    float mo1 = sm_m[(1 - wg) * 64 + lr0 + 8], lo1 = sm_l[(1 - wg) * 64 + lr0 + 8];
    float mg0 = fmaxf(m0, mo0), mg1 = fmaxf(m1, mo1);
    float lg0 = l0 * __expf(m0 - mg0) + lo0 * __expf(mo0 - mg0);
    float lg1 = l1 * __expf(m1 - mg1) + lo1 * __expf(mo1 - mg1);
    float sc0 = __expf(m0 - mg0) / lg0;
    float sc1 = __expf(m1 - mg1) / lg1;

    float* Obuf = Qs;
    if (wg == 1) {
        #pragma unroll
        for (int dt = 0; dt < 16; dt++) {
            *(float2*)&Obuf[lr0 * 132 + dt*8 + 2*c]       = make_float2(o[dt][0]*sc0, o[dt][1]*sc0);
            *(float2*)&Obuf[(lr0+8) * 132 + dt*8 + 2*c]   = make_float2(o[dt][2]*sc1, o[dt][3]*sc1);
        }
    }
    __syncthreads();
    if (wg == 0) {
        float* O0 = g_attn + ((size_t)bh * NN + it * 64 + lr0    ) * DHH;
        float* O1 = g_attn + ((size_t)bh * NN + it * 64 + lr0 + 8) * DHH;
        #pragma unroll
        for (int dt = 0; dt < 16; dt++) {
            float2 b0 = *(float2*)&Obuf[lr0 * 132 + dt*8 + 2*c];
            float2 b1 = *(float2*)&Obuf[(lr0+8) * 132 + dt*8 + 2*c];
            *(float2*)&O0[dt*8 + 2*c] = make_float2(o[dt][0]*sc0 + b0.x, o[dt][1]*sc0 + b0.y);
            *(float2*)&O1[dt*8 + 2*c] = make_float2(o[dt][2]*sc1 + b1.x, o[dt][3]*sc1 + b1.y);
        }
    }
}

// ---------------- 5) memory retrieval + gate blend (stores tf32-rounded) ----------------
__global__ void retrieve_gate_k(const float* __restrict__ mem_kv,
                                const float* __restrict__ mem_norm,
                                const float* __restrict__ head_gates) {
    int bh = blockIdx.y;
    int b_ = bh >> 3, h = bh & 7;
    int t0 = blockIdx.x * 32;
    int v  = threadIdx.x;
    __shared__ float qsT[128][36];
    __shared__ float dn[32];
    __shared__ float mn[128];
    mn[v] = mem_norm[bh * DHH + v];
    const float* qf = g_qf + ((size_t)bh * NN + t0) * DHH;
    for (int i = v; i < 32 * 32; i += 128) {
        int t = i >> 5;
        int k4 = (i & 31) * 4;
        float4 qv = *(const float4*)(qf + (size_t)t * DHH + k4);
        qsT[k4+0][t] = qv.x; qsT[k4+1][t] = qv.y; qsT[k4+2][t] = qv.z; qsT[k4+3][t] = qv.w;
    }
    __syncthreads();
    if (v < 32) {
        float s = 0.f;
        #pragma unroll 8
        for (int k = 0; k < 128; k++) s += qsT[k][v] * mn[k];
        dn[v] = fmaxf(s, EPSV);
    }
    __syncthreads();
    const float* mkv = mem_kv + (size_t)bh * DHH * DHH;
    float num[32];
    #pragma unroll
    for (int t = 0; t < 32; t++) num[t] = 0.f;
    for (int k = 0; k < 128; k++) {
        float mval = mkv[k * DHH + v];
        #pragma unroll
        for (int t8 = 0; t8 < 8; t8++) {
            float4 qv = *(const float4*)&qsT[k][t8 * 4];
            num[t8*4+0] += qv.x * mval;
            num[t8*4+1] += qv.y * mval;
            num[t8*4+2] += qv.z * mval;
            num[t8*4+3] += qv.w * mval;
        }
    }
    float g = 1.f / (1.f + expf(-head_gates[h]));
    const float* at = g_attn + ((size_t)bh * NN + t0) * DHH;
    float* cb = g_comb + ((size_t)b_ * NN + t0) * DIMM + h * DHH;
    #pragma unroll 4
    for (int t = 0; t < 32; t++) {
        float mo = num[t] / dn[t];
        cb[(size_t)t * DIMM + v] = tf32f(at[(size_t)t * DHH + v] * g + mo * (1.f - g));
    }
}

// ---------------- 7a) delta-rule new_kv partials (split tokens 4x, v-dim 4x) ----------------
__global__ void __launch_bounds__(256) newkv_part_k(const float* __restrict__ mem_kv,
                                                    const float* __restrict__ mem_norm) {
    int bh    = blockIdx.x;
    int vbase = blockIdx.y * 32;
    int tch   = blockIdx.z;
    int tid   = threadIdx.x;
    int ty = tid >> 3, tx = tid & 7;
    __shared__ float kfs[32][128];
    __shared__ float vns[32][32];
    __shared__ float mn[128];
    __shared__ float dns[32];
    if (tid < 128) mn[tid] = mem_norm[bh * DHH + tid];
    const float* mkv = mem_kv + (size_t)bh * DHH * DHH;
    const float* kfb = g_kf + (size_t)bh * NN * DHH;
    const float* vb  = g_v  + (size_t)bh * NN * DHH;
    float C[4][4];
    #pragma unroll
    for (int i = 0; i < 4; i++)
        #pragma unroll
        for (int j = 0; j < 4; j++) C[i][j] = 0.f;

    int vlane = tid & 31, tg = tid >> 5;
    int tstart = tch * 512;

    for (int t0 = tstart; t0 < tstart + 512; t0 += 32) {
        __syncthreads();
        #pragma unroll
        for (int i = 0; i < 4; i++) {
            int idx = tid + i * 256;
            int t = idx >> 5, kq = (idx & 31) * 4;
            *(float4*)&kfs[t][kq] = *(const float4*)(kfb + (size_t)(t0 + t) * DHH + kq);
        }
        {
            int t = tid >> 3, vq = (tid & 7) * 4;
            *(float4*)&vns[t][vq] = *(const float4*)(vb + (size_t)(t0 + t) * DHH + vbase + vq);
        }
        __syncthreads();
        if (tid < 32) {
            float s = 0.f;
            #pragma unroll 8
            for (int k = 0; k < 128; k++) {
                int kk = (k + tid) & 127;
                s += kfs[tid][kk] * mn[kk];
            }
            dns[tid] = fmaxf(s, EPSV);
        }
        __syncthreads();
        {
            float numv[4] = {0.f, 0.f, 0.f, 0.f};
            for (int k = 0; k < 128; k++) {
                float mval = mkv[k * DHH + vbase + vlane];
                #pragma unroll
                for (int j = 0; j < 4; j++) numv[j] += kfs[tg * 4 + j][k] * mval;
            }
            #pragma unroll
            for (int j = 0; j < 4; j++) vns[tg * 4 + j][vlane] -= numv[j] / dns[tg * 4 + j];
        }
        __syncthreads();
        #pragma unroll 4
        for (int t = 0; t < 32; t++) {
            float4 a = *(const float4*)&kfs[t][ty * 4];
            float4 b = *(const float4*)&vns[t][tx * 4];
            float av[4] = {a.x, a.y, a.z, a.w};
            float bv[4] = {b.x, b.y, b.z, b.w};
            #pragma unroll
            for (int i = 0; i < 4; i++)
                #pragma unroll
                for (int j = 0; j < 4; j++) C[i][j] += av[i] * bv[j];
        }
    }
    #pragma unroll
    for (int i = 0; i < 4; i++)
        #pragma unroll
        for (int j = 0; j < 4; j++) {
            int kd = ty * 4 + i, vd = vbase + tx * 4 + j;
            g_ckv[(((size_t)bh * 4 + tch) * DHH + kd) * DHH + vd] = C[i][j];
        }
}

// ---------------- 7b) new_kv reduce ----------------
__global__ void newkv_red_k(const float* __restrict__ mem_kv, float* __restrict__ out_kv) {
    int bh = blockIdx.x;
    const float4* mk = (const float4*)(mem_kv + (size_t)bh * DHH * DHH);
    float4* ok = (float4*)(out_kv + (size_t)bh * DHH * DHH);
    for (int i = threadIdx.x; i < DHH * DHH / 4; i += 256) {
        float4 s = mk[i];
        #pragma unroll
        for (int c = 0; c < 4; c++) {
            float4 p = ((const float4*)(g_ckv + ((size_t)bh * 4 + c) * DHH * DHH))[i];
            s.x += p.x; s.y += p.y; s.z += p.z; s.w += p.w;
        }
        ok[i] = s;
    }
}

// ---------------- 8) new_norm: two-stage parallel sum ----------------
__global__ void newnorm_part_k() {
    int bh = blockIdx.x, ch = blockIdx.y;
    int k  = threadIdx.x;
    const float* kf = g_kf + (size_t)bh * NN * DHH + (size_t)ch * 256 * DHH;
    float s = 0.f;
    #pragma unroll 8
    for (int n_ = 0; n_ < 256; n_++) s += kf[(size_t)n_ * DHH + k];
    g_pnorm[((size_t)bh * 8 + ch) * DHH + k] = s;
}
__global__ void newnorm_red_k(const float* __restrict__ mem_norm, float* __restrict__ out_norm) {
    int bh = blockIdx.x;
    int k  = threadIdx.x;
    float s = mem_norm[bh * DHH + k];
    #pragma unroll
    for (int c = 0; c < 8; c++) s += g_pnorm[((size_t)bh * 8 + c) * DHH + k];
    out_norm[bh * DHH + k] = s;
}

// ---------------- launch ----------------
extern "C" void kernel_launch(void* const* d_in, const int* in_sizes, int n_in,
                              void* d_out, int out_size) {
    (void)in_sizes; (void)n_in; (void)out_size;
    const float* x          = (const float*)d_in[0];
    const float* gamma      = (const float*)d_in[1];
    const float* w_qkv      = (const float*)d_in[2];
    const float* w_out      = (const float*)d_in[3];
    const float* head_gates = (const float*)d_in[4];
    const float* mem_kv     = (const float*)d_in[5];
    const float* mem_norm   = (const float*)d_in[6];
    float* out      = (float*)d_out;
    float* out_kv   = out + (size_t)BB * NN * DIMM;
    float* out_norm = out_kv + BB * HH * DHH * DHH;

    const int FLASH_SMEM = 21504 * 4;     // 86016 B
    const int GEMM_SMEM  = 4 * 4608 * 4;  // 73728 B
    cudaFuncSetAttribute(flash_tc, cudaFuncAttributeMaxDynamicSharedMemorySize, FLASH_SMEM);
    cudaFuncSetAttribute(sgemm_tc, cudaFuncAttributeMaxDynamicSharedMemorySize, GEMM_SMEM);

    uint32_t* wq_t; cudaGetSymbolAddress((void**)&wq_t, g_wqt);
    uint32_t* wo_t; cudaGetSymbolAddress((void**)&wo_t, g_wot);

    wcvt_k<<<S3 * DIMM / 1024, 256>>>(w_qkv, wq_t);
    wcvt_k<<<DIMM * DIMM / 1024, 256>>>(w_out, wo_t);
    rmsnorm_k<<<BB * NN, 256>>>(x, gamma);
    sgemm_tc<<<dim3(S3 / 128, BB * NN / 128), 256, GEMM_SMEM>>>(0, nullptr);
    rope_feat_k<<<BB * HH * NN / 4, dim3(64, 4)>>>();
    flash_tc<<<dim3(NN / 64, BB * HH), 256, FLASH_SMEM>>>();
    retrieve_gate_k<<<dim3(NN / 32, BB * HH), 128>>>(mem_kv, mem_norm, head_gates);
    sgemm_tc<<<dim3(DIMM / 128, BB * NN / 128), 256, GEMM_SMEM>>>(1, out);
    newkv_part_k<<<dim3(BB * HH, 4, 4), 256>>>(mem_kv, mem_norm);
    newkv_red_k<<<BB * HH, 256>>>(mem_kv, out_kv);
    newnorm_part_k<<<dim3(BB * HH, 8), 128>>>();
    newnorm_red_k<<<BB * HH, 128>>>(mem_norm, out_norm);
}

// round 16
// speedup vs baseline: 4.8095x; 1.0538x over previous
#include <cuda_runtime.h>
#include <math.h>
#include <stdint.h>

#define BB   2
#define NN   2048
#define DIMM 1024
#define HH   8
#define DHH  128
#define S3   (3*DIMM)
#define SCALE_Q 0.08838834764831845f
#define EPSV 1e-10f

// ---------------- scratch (static device globals; no allocation) ----------------
__device__ float g_xn  [BB*NN*DIMM];          // tf32-rounded
__device__ float g_q   [BB*HH*NN*DHH];
__device__ float g_k   [BB*HH*NN*DHH];
__device__ float g_v   [BB*HH*NN*DHH];
__device__ float g_qr  [BB*HH*NN*DHH];        // tf32-rounded rotated Q
__device__ float g_qf  [BB*HH*NN*DHH];
__device__ float g_kf  [BB*HH*NN*DHH];
__device__ float g_attn[BB*HH*NN*DHH];
__device__ float g_comb[BB*NN*DIMM];          // tf32-rounded
__device__ float g_pnorm[BB*HH*8*DHH];
__device__ float g_krh [BB*HH*NN*DHH];        // rotated K tf32 hi
__device__ float g_krl [BB*HH*NN*DHH];        // rotated K tf32 lo
__device__ float g_vt  [BB*HH*NN*DHH];        // tf32-rounded V [bh][n][d]
__device__ float g_vtT [BB*HH*DHH*NN];        // tf32-rounded V transposed [bh][d][n]
__device__ float g_ckv [BB*HH*4*DHH*DHH];     // newkv partials
__device__ uint32_t g_wqt[S3*DIMM];           // tf32 w_qkv
__device__ uint32_t g_wot[DIMM*DIMM];         // tf32 w_out

// ---------------- helpers ----------------
__device__ __forceinline__ uint32_t f2tf32(float f) {
    uint32_t r;
    asm("cvt.rna.tf32.f32 %0, %1;" : "=r"(r) : "f"(f));
    return r;
}
__device__ __forceinline__ float tf32f(float f) { return __uint_as_float(f2tf32(f)); }

__device__ __forceinline__ void mma_tf32(float* d, const uint32_t* a, const uint32_t* b) {
    asm volatile(
        "mma.sync.aligned.m16n8k8.row.col.f32.tf32.tf32.f32 "
        "{%0,%1,%2,%3}, {%4,%5,%6,%7}, {%8,%9}, {%0,%1,%2,%3};\n"
        : "+f"(d[0]), "+f"(d[1]), "+f"(d[2]), "+f"(d[3])
        : "r"(a[0]), "r"(a[1]), "r"(a[2]), "r"(a[3]), "r"(b[0]), "r"(b[1]));
}
__device__ __forceinline__ void ldsm4(uint32_t* r, uint32_t addr) {
    asm volatile("ldmatrix.sync.aligned.m8n8.x4.shared.b16 {%0,%1,%2,%3}, [%4];"
                 : "=r"(r[0]), "=r"(r[1]), "=r"(r[2]), "=r"(r[3]) : "r"(addr));
}
__device__ __forceinline__ uint32_t smem_u32(const void* p) {
    uint32_t a;
    asm("{ .reg .u64 t; cvta.to.shared.u64 t, %1; cvt.u32.u64 %0, t; }" : "=r"(a) : "l"(p));
    return a;
}
#define CPA16(dst, src) asm volatile("cp.async.cg.shared.global [%0], [%1], 16;" :: "r"(dst), "l"(src))

// ---------------- 0) weight tf32 pre-convert ----------------
__global__ void wcvt_k(const float* __restrict__ w, uint32_t* __restrict__ o) {
    int i = blockIdx.x * 256 + threadIdx.x;
    float4 v = ((const float4*)w)[i];
    ((uint4*)o)[i] = make_uint4(f2tf32(v.x), f2tf32(v.y), f2tf32(v.z), f2tf32(v.w));
}

// ---------------- 1) RMSNorm (stores tf32-rounded) ----------------
__global__ void rmsnorm_k(const float* __restrict__ x, const float* __restrict__ gamma) {
    int row = blockIdx.x;
    const float* xr = x + (size_t)row * DIMM;
    float ss = 0.f;
    for (int i = threadIdx.x; i < DIMM; i += 256) { float v = xr[i]; ss += v * v; }
    #pragma unroll
    for (int o = 16; o > 0; o >>= 1) ss += __shfl_xor_sync(0xffffffffu, ss, o);
    __shared__ float red[8];
    __shared__ float sinv;
    if ((threadIdx.x & 31) == 0) red[threadIdx.x >> 5] = ss;
    __syncthreads();
    if (threadIdx.x == 0) {
        float t = 0.f;
        #pragma unroll
        for (int i = 0; i < 8; i++) t += red[i];
        sinv = 32.0f / fmaxf(sqrtf(t), 1e-12f);
    }
    __syncthreads();
    float inv = sinv;
    float* o = g_xn + (size_t)row * DIMM;
    for (int i = threadIdx.x; i < DIMM; i += 256) o[i] = tf32f(xr[i] * inv * gamma[i]);
}

// ---------------- 2/6) tf32 TC GEMM: cp.async + ldmatrix, double-buffered ----------------
__global__ void __launch_bounds__(256) sgemm_tc(int mode, float* __restrict__ outp) {
    extern __shared__ uint32_t smem_u[];
    const uint32_t* A = (mode == 0) ? (const uint32_t*)g_xn : (const uint32_t*)g_comb;
    const uint32_t* B = (mode == 0) ? g_wqt : g_wot;
    const int K = DIMM;
    int tid  = threadIdx.x;
    int lane = tid & 31, warp = tid >> 5;
    int wm = warp >> 2, wn = warp & 3;
    int r  = lane >> 2, cc = lane & 3;
    int rbase = tid >> 3;
    int kq    = (tid & 7) * 4;

    uint32_t sbase = smem_u32(smem_u);
    uint32_t aoff = ((lane & 7) + (((lane >> 3) & 1) << 3)) * 144 + ((lane >> 4) & 1) * 16;
    uint32_t boff = ((lane & 7) + (((lane >> 4) & 1) << 3)) * 144 + ((lane >> 3) & 1) * 16;

    float acc[4][4][4];
    #pragma unroll
    for (int mt = 0; mt < 4; mt++)
        #pragma unroll
        for (int nt = 0; nt < 4; nt++)
            #pragma unroll
            for (int i = 0; i < 4; i++) acc[mt][nt][i] = 0.f;

    size_t aBase = (size_t)(blockIdx.y * 128) * K;
    size_t bBase = (size_t)(blockIdx.x * 128) * K;

    uint32_t dstA0 = sbase + (rbase * 36 + kq) * 4;
    uint32_t dstB0 = sbase + 36864 + (rbase * 36 + kq) * 4;

    #pragma unroll
    for (int i = 0; i < 4; i++) {
        int row = rbase + 32 * i;
        CPA16(dstA0 + i * (32 * 144), A + aBase + (size_t)row * K + kq);
        CPA16(dstB0 + i * (32 * 144), B + bBase + (size_t)row * K + kq);
    }
    asm volatile("cp.async.commit_group;");

    for (int kt = 0; kt < 32; kt++) {
        int cur = kt & 1;
        asm volatile("cp.async.wait_group 0;");
        __syncthreads();
        if (kt < 31) {
            int k0 = (kt + 1) * 32;
            uint32_t bufo = ((kt + 1) & 1) * 18432;
            #pragma unroll
            for (int i = 0; i < 4; i++) {
                int row = rbase + 32 * i;
                CPA16(dstA0 + bufo + i * (32 * 144), A + aBase + (size_t)row * K + k0 + kq);
                CPA16(dstB0 + bufo + i * (32 * 144), B + bBase + (size_t)row * K + k0 + kq);
            }
            asm volatile("cp.async.commit_group;");
        }
        uint32_t abase_s = sbase + cur * 18432 + aoff + (wm * 64) * 144;
        uint32_t bbase_s = sbase + 36864 + cur * 18432 + boff + (wn * 32) * 144;
        #pragma unroll
        for (int ks = 0; ks < 32; ks += 8) {
            uint32_t af[4][4], bf01[4], bf23[4];
            #pragma unroll
            for (int mt = 0; mt < 4; mt++)
                ldsm4(af[mt], abase_s + mt * (16 * 144) + ks * 4);
            ldsm4(bf01, bbase_s + ks * 4);
            ldsm4(bf23, bbase_s + 16 * 144 + ks * 4);
            #pragma unroll
            for (int mt = 0; mt < 4; mt++) {
                mma_tf32(acc[mt][0], af[mt], &bf01[0]);
                mma_tf32(acc[mt][1], af[mt], &bf01[2]);
                mma_tf32(acc[mt][2], af[mt], &bf23[0]);
                mma_tf32(acc[mt][3], af[mt], &bf23[2]);
            }
        }
    }

    #pragma unroll
    for (int mt = 0; mt < 4; mt++) {
        #pragma unroll
        for (int half = 0; half < 2; half++) {
            int row = blockIdx.y * 128 + wm * 64 + mt * 16 + r + half * 8;
            #pragma unroll
            for (int nt = 0; nt < 4; nt++) {
                int col = blockIdx.x * 128 + wn * 32 + nt * 8 + 2 * cc;
                float v0 = acc[mt][nt][half * 2 + 0];
                float v1 = acc[mt][nt][half * 2 + 1];
                if (mode == 0) {
                    int b_ = row >> 11, n_ = row & (NN - 1);
                    int sel = col >> 10, rem = col & 1023;
                    int h = rem >> 7, dd = rem & 127;
                    float* dst = (sel == 0) ? g_q : ((sel == 1) ? g_k : g_v);
                    float2* p = (float2*)&dst[((size_t)(b_ * HH + h) * NN + n_) * DHH + dd];
                    *p = make_float2(v0, v1);
                } else {
                    float2* p = (float2*)&outp[(size_t)row * DIMM + col];
                    *p = make_float2(v0, v1);
                }
            }
        }
    }
}

// ---------------- 3) RoPE + elu features; Q/K/V flash-ready formats ----------------
__global__ void rope_feat_k() {
    int gid = blockIdx.x * blockDim.y + threadIdx.y;
    int p   = threadIdx.x;
    int n_  = gid & (NN - 1);
    size_t base = (size_t)gid * DHH;
    float inv = powf(10000.0f, -(float)(2 * p) * (1.0f / 128.0f));
    float ang = (float)n_ * inv;
    float s, c;
    sincosf(ang, &s, &c);
    float q0 = g_q[base + 2*p], q1 = g_q[base + 2*p + 1];
    float k0 = g_k[base + 2*p], k1 = g_k[base + 2*p + 1];
    float sq0 = q0 * SCALE_Q, sq1 = q1 * SCALE_Q;
    g_qr[base + 2*p]     = tf32f(sq0 * c - sq1 * s);
    g_qr[base + 2*p + 1] = tf32f(sq1 * c + sq0 * s);
    float kr0 = k0 * c - k1 * s;
    float kr1 = k1 * c + k0 * s;
    float h;
    h = tf32f(kr0); g_krh[base + 2*p]     = h; g_krl[base + 2*p]     = tf32f(kr0 - h);
    h = tf32f(kr1); g_krh[base + 2*p + 1] = h; g_krl[base + 2*p + 1] = tf32f(kr1 - h);
    g_vt[base + 2*p]     = tf32f(g_v[base + 2*p]);
    g_vt[base + 2*p + 1] = tf32f(g_v[base + 2*p + 1]);
    g_qf[base + 2*p]     = (q0 > 0.f) ? q0 + 1.f : expf(q0);
    g_qf[base + 2*p + 1] = (q1 > 0.f) ? q1 + 1.f : expf(q1);
    g_kf[base + 2*p]     = (k0 > 0.f) ? k0 + 1.f : expf(k0);
    g_kf[base + 2*p + 1] = (k1 > 0.f) ? k1 + 1.f : expf(k1);
}

// ---------------- 3b) V transpose: [bh][n][d] -> [bh][d][n] ----------------
__global__ void vtrans_k() {
    __shared__ float ts[32][33];
    int bh = blockIdx.z;
    int n0 = blockIdx.x * 32, d0 = blockIdx.y * 32;
    int tx = threadIdx.x, ty = threadIdx.y;            // 32 x 8
    const float* src = g_vt + ((size_t)bh * NN + n0) * DHH + d0;
    #pragma unroll
    for (int i = ty; i < 32; i += 8) ts[i][tx] = src[(size_t)i * DHH + tx];   // ts[n][d]
    __syncthreads();
    float* dst = g_vtT + ((size_t)bh * DHH + d0) * NN + n0;
    #pragma unroll
    for (int i = ty; i < 32; i += 8) dst[(size_t)i * NN + tx] = ts[tx][i];    // row=d, col=n
}

// ---------------- 4) TC causal flash attention: full-ldmatrix Q/K/V ----------------
// smem floats: Qs[64][132] | Kh[32][132] | Kl[32][132] | VsT[128][36] | m,l. 87040 B.
__global__ void __launch_bounds__(256, 2) flash_tc() {
    extern __shared__ float sm[];
    float* Qs   = sm;                           // 8448
    float* Kh   = sm + 8448;                    // 4224
    float* Kl   = sm + 12672;                   // 4224
    float* VsT  = sm + 16896;                   // 4608 ([128][36])
    float* sm_m = sm + 21504;                   // 128
    float* sm_l = sm + 21632;                   // 128

    int bh  = blockIdx.y;
    int it  = gridDim.x - 1 - blockIdx.x;
    int tid = threadIdx.x;
    int lane = tid & 31, warp = tid >> 5;
    int wg = warp >> 2, wq = warp & 3;
    int r = lane >> 2, c = lane & 3;

    uint32_t sbase = smem_u32(sm);
    uint32_t aoffA = ((lane & 7) + (((lane >> 3) & 1) << 3)) * 528 + ((lane >> 4) & 1) * 16;
    uint32_t boffB = ((lane & 7) + (((lane >> 4) & 1) << 3)) * 528 + ((lane >> 3) & 1) * 16;
    uint32_t boffV = ((lane & 7) + (((lane >> 4) & 1) << 3)) * 144 + ((lane >> 3) & 1) * 16;
    uint32_t qb  = sbase + aoffA + (wq * 16) * 528;
    uint32_t khb = sbase + 8448 * 4  + boffB + (wg * 16) * 528;
    uint32_t klb = sbase + 12672 * 4 + boffB + (wg * 16) * 528;
    uint32_t vb  = sbase + 16896 * 4 + boffV;

    const float* Qg = g_qr + ((size_t)bh * NN + it * 64) * DHH;
    for (int i = tid; i < 64 * 32; i += 256) {
        int row = i >> 5, col4 = (i & 31) * 4;
        *(float4*)&Qs[row * 132 + col4] = *(const float4*)(Qg + (size_t)row * DHH + col4);
    }

    float o[16][4];
    #pragma unroll
    for (int dt = 0; dt < 16; dt++)
        #pragma unroll
        for (int i = 0; i < 4; i++) o[dt][i] = 0.f;
    float m0 = -1e30f, m1 = -1e30f, l0 = 0.f, l1 = 0.f;
    int rg0 = it * 64 + wq * 16 + r;
    int rg1 = rg0 + 8;
    int rowmax = it * 64 + wq * 16 + 15;
    int rowmin = it * 64 + wq * 16;
    int ntiles = 2 * it + 2;

    const float* Khg = g_krh + (size_t)bh * NN * DHH;
    const float* Klg = g_krl + (size_t)bh * NN * DHH;
    const float* VTg = g_vtT + (size_t)bh * DHH * NN;

    for (int jt = 0; jt < ntiles; jt++) {
        __syncthreads();                                 // prev tile consumed
        #pragma unroll
        for (int ii = 0; ii < 4; ii++) {                 // 1024 total iters / 256 threads
            int i = tid + ii * 256;
            int row = i >> 5, q4e = (i & 31) * 4;        // K: 32 rows x 128 el
            CPA16(sbase + 8448 * 4  + (row * 132 + q4e) * 4, Khg + (size_t)(jt * 32 + row) * DHH + q4e);
            CPA16(sbase + 12672 * 4 + (row * 132 + q4e) * 4, Klg + (size_t)(jt * 32 + row) * DHH + q4e);
            int vr = i >> 3, vqe = (i & 7) * 4;          // V^T: 128 rows x 32 el
            CPA16(sbase + 16896 * 4 + (vr * 36 + vqe) * 4, VTg + (size_t)vr * NN + jt * 32 + vqe);
        }
        asm volatile("cp.async.commit_group;");
        asm volatile("cp.async.wait_group 0;");
        __syncthreads();

        int kmin = jt * 32 + wg * 16;
        if (kmin > rowmax) continue;

        float s[2][4];
        #pragma unroll
        for (int nt = 0; nt < 2; nt++)
            #pragma unroll
            for (int i = 0; i < 4; i++) s[nt][i] = 0.f;

        #pragma unroll 4
        for (int ks = 0; ks < 16; ks++) {
            uint32_t af[4], bh4[4], bl4[4];
            ldsm4(af,  qb  + ks * 32);
            ldsm4(bh4, khb + ks * 32);
            ldsm4(bl4, klb + ks * 32);
            mma_tf32(s[0], af, &bh4[0]);
            mma_tf32(s[0], af, &bl4[0]);
            mma_tf32(s[1], af, &bh4[2]);
            mma_tf32(s[1], af, &bl4[2]);
        }

        if (kmin + 15 > rowmin) {
            #pragma unroll
            for (int nt = 0; nt < 2; nt++) {
                int cg = kmin + nt * 8 + 2 * c;
                if (cg     > rg0) s[nt][0] = -1e30f;
                if (cg + 1 > rg0) s[nt][1] = -1e30f;
                if (cg     > rg1) s[nt][2] = -1e30f;
                if (cg + 1 > rg1) s[nt][3] = -1e30f;
            }
        }

        float tmax0 = fmaxf(fmaxf(s[0][0], s[0][1]), fmaxf(s[1][0], s[1][1]));
        float tmax1 = fmaxf(fmaxf(s[0][2], s[0][3]), fmaxf(s[1][2], s[1][3]));
        tmax0 = fmaxf(tmax0, __shfl_xor_sync(0xffffffffu, tmax0, 1));
        tmax0 = fmaxf(tmax0, __shfl_xor_sync(0xffffffffu, tmax0, 2));
        tmax1 = fmaxf(tmax1, __shfl_xor_sync(0xffffffffu, tmax1, 1));
        tmax1 = fmaxf(tmax1, __shfl_xor_sync(0xffffffffu, tmax1, 2));
        float mn0 = fmaxf(m0, tmax0), mn1 = fmaxf(m1, tmax1);
        float al0 = __expf(m0 - mn0), al1 = __expf(m1 - mn1);
        float ps0 = 0.f, ps1 = 0.f;
        #pragma unroll
        for (int nt = 0; nt < 2; nt++) {
            s[nt][0] = __expf(s[nt][0] - mn0);
            s[nt][1] = __expf(s[nt][1] - mn0);
            s[nt][2] = __expf(s[nt][2] - mn1);
            s[nt][3] = __expf(s[nt][3] - mn1);
            ps0 += s[nt][0] + s[nt][1];
            ps1 += s[nt][2] + s[nt][3];
        }
        ps0 += __shfl_xor_sync(0xffffffffu, ps0, 1);
        ps0 += __shfl_xor_sync(0xffffffffu, ps0, 2);
        ps1 += __shfl_xor_sync(0xffffffffu, ps1, 1);
        ps1 += __shfl_xor_sync(0xffffffffu, ps1, 2);
        l0 = l0 * al0 + ps0;  l1 = l1 * al1 + ps1;
        m0 = mn0;  m1 = mn1;
        if (__any_sync(0xffffffffu, (al0 < 1.f) | (al1 < 1.f))) {
            #pragma unroll
            for (int dt = 0; dt < 16; dt++) {
                o[dt][0] *= al0; o[dt][1] *= al0;
                o[dt][2] *= al1; o[dt][3] *= al1;
            }
        }

        int sA = (lane & ~3) | (c >> 1);
        int sB = sA + 2;
        #pragma unroll
        for (int nt = 0; nt < 2; nt++) {
            float t00 = __shfl_sync(0xffffffffu, s[nt][0], sA);
            float t01 = __shfl_sync(0xffffffffu, s[nt][1], sA);
            float u00 = __shfl_sync(0xffffffffu, s[nt][0], sB);
            float u01 = __shfl_sync(0xffffffffu, s[nt][1], sB);
            float t10 = __shfl_sync(0xffffffffu, s[nt][2], sA);
            float t11 = __shfl_sync(0xffffffffu, s[nt][3], sA);
            float u10 = __shfl_sync(0xffffffffu, s[nt][2], sB);
            float u11 = __shfl_sync(0xffffffffu, s[nt][3], sB);
            float a0 = (c & 1) ? t01 : t00;
            float a2 = (c & 1) ? u01 : u00;
            float a1 = (c & 1) ? t11 : t10;
            float a3 = (c & 1) ? u11 : u10;
            uint32_t ph[4];
            ph[0] = f2tf32(a0);
            ph[1] = f2tf32(a1);
            ph[2] = f2tf32(a2);
            ph[3] = f2tf32(a3);
            uint32_t voff = vb + (wg * 16 + nt * 8) * 4;
            #pragma unroll
            for (int p8 = 0; p8 < 8; p8++) {
                uint32_t vf[4];
                ldsm4(vf, voff + p8 * (16 * 144));
                mma_tf32(o[2 * p8],     ph, &vf[0]);
                mma_tf32(o[2 * p8 + 1], ph, &vf[2]);
            }
        }
    }

    int lr0 = wq * 16 + r;
    __syncthreads();
    if (c == 0) {
        sm_m[wg * 64 + lr0]     = m0;  sm_l[wg * 64 + lr0]     = l0;
        sm_m[wg * 64 + lr0 + 8] = m1;  sm_l[wg * 64 + lr0 + 8] = l1;
    }
    __syncthreads();
    float mo0 = sm_m[(1 - wg) * 64 + lr0],     lo0 = sm_l[(1 - wg) * 64 + lr0];
    float mo1 = sm_m[(1 - wg) * 64 + lr0 + 8], lo1 = sm_l[(1 - wg) * 64 + lr0 + 8];
    float mg0 = fmaxf(m0, mo0), mg1 = fmaxf(m1, mo1);
    float lg0 = l0 * __expf(m0 - mg0) + lo0 * __expf(mo0 - mg0);
    float lg1 = l1 * __expf(m1 - mg1) + lo1 * __expf(mo1 - mg1);
    float sc0 = __expf(m0 - mg0) / lg0;
    float sc1 = __expf(m1 - mg1) / lg1;

    float* Obuf = Qs;
    if (wg == 1) {
        #pragma unroll
        for (int dt = 0; dt < 16; dt++) {
            *(float2*)&Obuf[lr0 * 132 + dt*8 + 2*c]       = make_float2(o[dt][0]*sc0, o[dt][1]*sc0);
            *(float2*)&Obuf[(lr0+8) * 132 + dt*8 + 2*c]   = make_float2(o[dt][2]*sc1, o[dt][3]*sc1);
        }
    }
    __syncthreads();
    if (wg == 0) {
        float* O0 = g_attn + ((size_t)bh * NN + it * 64 + lr0    ) * DHH;
        float* O1 = g_attn + ((size_t)bh * NN + it * 64 + lr0 + 8) * DHH;
        #pragma unroll
        for (int dt = 0; dt < 16; dt++) {
            float2 b0 = *(float2*)&Obuf[lr0 * 132 + dt*8 + 2*c];
            float2 b1 = *(float2*)&Obuf[(lr0+8) * 132 + dt*8 + 2*c];
            *(float2*)&O0[dt*8 + 2*c] = make_float2(o[dt][0]*sc0 + b0.x, o[dt][1]*sc0 + b0.y);
            *(float2*)&O1[dt*8 + 2*c] = make_float2(o[dt][2]*sc1 + b1.x, o[dt][3]*sc1 + b1.y);
        }
    }
}

// ---------------- 5) memory retrieval + gate blend (stores tf32-rounded) ----------------
__global__ void retrieve_gate_k(const float* __restrict__ mem_kv,
                                const float* __restrict__ mem_norm,
                                const float* __restrict__ head_gates) {
    int bh = blockIdx.y;
    int b_ = bh >> 3, h = bh & 7;
    int t0 = blockIdx.x * 32;
    int v  = threadIdx.x;
    __shared__ float qsT[128][36];
    __shared__ float dn[32];
    __shared__ float mn[128];
    mn[v] = mem_norm[bh * DHH + v];
    const float* qf = g_qf + ((size_t)bh * NN + t0) * DHH;
    for (int i = v; i < 32 * 32; i += 128) {
        int t = i >> 5;
        int k4 = (i & 31) * 4;
        float4 qv = *(const float4*)(qf + (size_t)t * DHH + k4);
        qsT[k4+0][t] = qv.x; qsT[k4+1][t] = qv.y; qsT[k4+2][t] = qv.z; qsT[k4+3][t] = qv.w;
    }
    __syncthreads();
    if (v < 32) {
        float s = 0.f;
        #pragma unroll 8
        for (int k = 0; k < 128; k++) s += qsT[k][v] * mn[k];
        dn[v] = fmaxf(s, EPSV);
    }
    __syncthreads();
    const float* mkv = mem_kv + (size_t)bh * DHH * DHH;
    float num[32];
    #pragma unroll
    for (int t = 0; t < 32; t++) num[t] = 0.f;
    for (int k = 0; k < 128; k++) {
        float mval = mkv[k * DHH + v];
        #pragma unroll
        for (int t8 = 0; t8 < 8; t8++) {
            float4 qv = *(const float4*)&qsT[k][t8 * 4];
            num[t8*4+0] += qv.x * mval;
            num[t8*4+1] += qv.y * mval;
            num[t8*4+2] += qv.z * mval;
            num[t8*4+3] += qv.w * mval;
        }
    }
    float g = 1.f / (1.f + expf(-head_gates[h]));
    const float* at = g_attn + ((size_t)bh * NN + t0) * DHH;
    float* cb = g_comb + ((size_t)b_ * NN + t0) * DIMM + h * DHH;
    #pragma unroll 4
    for (int t = 0; t < 32; t++) {
        float mo = num[t] / dn[t];
        cb[(size_t)t * DIMM + v] = tf32f(at[(size_t)t * DHH + v] * g + mo * (1.f - g));
    }
}

// ---------------- 7a) delta-rule new_kv partials (split tokens 4x, v-dim 4x) ----------------
__global__ void __launch_bounds__(256) newkv_part_k(const float* __restrict__ mem_kv,
                                                    const float* __restrict__ mem_norm) {
    int bh    = blockIdx.x;
    int vbase = blockIdx.y * 32;
    int tch   = blockIdx.z;
    int tid   = threadIdx.x;
    int ty = tid >> 3, tx = tid & 7;
    __shared__ float kfs[32][128];
    __shared__ float vns[32][32];
    __shared__ float mn[128];
    __shared__ float dns[32];
    if (tid < 128) mn[tid] = mem_norm[bh * DHH + tid];
    const float* mkv = mem_kv + (size_t)bh * DHH * DHH;
    const float* kfb = g_kf + (size_t)bh * NN * DHH;
    const float* vb  = g_v  + (size_t)bh * NN * DHH;
    float C[4][4];
    #pragma unroll
    for (int i = 0; i < 4; i++)
        #pragma unroll
        for (int j = 0; j < 4; j++) C[i][j] = 0.f;

    int vlane = tid & 31, tg = tid >> 5;
    int tstart = tch * 512;

    for (int t0 = tstart; t0 < tstart + 512; t0 += 32) {
        __syncthreads();
        #pragma unroll
        for (int i = 0; i < 4; i++) {
            int idx = tid + i * 256;
            int t = idx >> 5, kq = (idx & 31) * 4;
            *(float4*)&kfs[t][kq] = *(const float4*)(kfb + (size_t)(t0 + t) * DHH + kq);
        }
        {
            int t = tid >> 3, vq = (tid & 7) * 4;
            *(float4*)&vns[t][vq] = *(const float4*)(vb + (size_t)(t0 + t) * DHH + vbase + vq);
        }
        __syncthreads();
        if (tid < 32) {
            float s = 0.f;
            #pragma unroll 8
            for (int k = 0; k < 128; k++) {
                int kk = (k + tid) & 127;
                s += kfs[tid][kk] * mn[kk];
            }
            dns[tid] = fmaxf(s, EPSV);
        }
        __syncthreads();
        {
            float numv[4] = {0.f, 0.f, 0.f, 0.f};
            for (int k = 0; k < 128; k++) {
                float mval = mkv[k * DHH + vbase + vlane];
                #pragma unroll
                for (int j = 0; j < 4; j++) numv[j] += kfs[tg * 4 + j][k] * mval;
            }
            #pragma unroll
            for (int j = 0; j < 4; j++) vns[tg * 4 + j][vlane] -= numv[j] / dns[tg * 4 + j];
        }
        __syncthreads();
        #pragma unroll 4
        for (int t = 0; t < 32; t++) {
            float4 a = *(const float4*)&kfs[t][ty * 4];
            float4 b = *(const float4*)&vns[t][tx * 4];
            float av[4] = {a.x, a.y, a.z, a.w};
            float bv[4] = {b.x, b.y, b.z, b.w};
            #pragma unroll
            for (int i = 0; i < 4; i++)
                #pragma unroll
                for (int j = 0; j < 4; j++) C[i][j] += av[i] * bv[j];
        }
    }
    #pragma unroll
    for (int i = 0; i < 4; i++)
        #pragma unroll
        for (int j = 0; j < 4; j++) {
            int kd = ty * 4 + i, vd = vbase + tx * 4 + j;
            g_ckv[(((size_t)bh * 4 + tch) * DHH + kd) * DHH + vd] = C[i][j];
        }
}

// ---------------- 7b) new_kv reduce ----------------
__global__ void newkv_red_k(const float* __restrict__ mem_kv, float* __restrict__ out_kv) {
    int bh = blockIdx.x;
    const float4* mk = (const float4*)(mem_kv + (size_t)bh * DHH * DHH);
    float4* ok = (float4*)(out_kv + (size_t)bh * DHH * DHH);
    for (int i = threadIdx.x; i < DHH * DHH / 4; i += 256) {
        float4 s = mk[i];
        #pragma unroll
        for (int c = 0; c < 4; c++) {
            float4 p = ((const float4*)(g_ckv + ((size_t)bh * 4 + c) * DHH * DHH))[i];
            s.x += p.x; s.y += p.y; s.z += p.z; s.w += p.w;
        }
        ok[i] = s;
    }
}

// ---------------- 8) new_norm: two-stage parallel sum ----------------
__global__ void newnorm_part_k() {
    int bh = blockIdx.x, ch = blockIdx.y;
    int k  = threadIdx.x;
    const float* kf = g_kf + (size_t)bh * NN * DHH + (size_t)ch * 256 * DHH;
    float s = 0.f;
    #pragma unroll 8
    for (int n_ = 0; n_ < 256; n_++) s += kf[(size_t)n_ * DHH + k];
    g_pnorm[((size_t)bh * 8 + ch) * DHH + k] = s;
}
__global__ void newnorm_red_k(const float* __restrict__ mem_norm, float* __restrict__ out_norm) {
    int bh = blockIdx.x;
    int k  = threadIdx.x;
    float s = mem_norm[bh * DHH + k];
    #pragma unroll
    for (int c = 0; c < 8; c++) s += g_pnorm[((size_t)bh * 8 + c) * DHH + k];
    out_norm[bh * DHH + k] = s;
}

// ---------------- launch ----------------
extern "C" void kernel_launch(void* const* d_in, const int* in_sizes, int n_in,
                              void* d_out, int out_size) {
    (void)in_sizes; (void)n_in; (void)out_size;
    const float* x          = (const float*)d_in[0];
    const float* gamma      = (const float*)d_in[1];
    const float* w_qkv      = (const float*)d_in[2];
    const float* w_out      = (const float*)d_in[3];
    const float* head_gates = (const float*)d_in[4];
    const float* mem_kv     = (const float*)d_in[5];
    const float* mem_norm   = (const float*)d_in[6];
    float* out      = (float*)d_out;
    float* out_kv   = out + (size_t)BB * NN * DIMM;
    float* out_norm = out_kv + BB * HH * DHH * DHH;

    const int FLASH_SMEM = 21760 * 4;     // 87040 B
    const int GEMM_SMEM  = 4 * 4608 * 4;  // 73728 B
    cudaFuncSetAttribute(flash_tc, cudaFuncAttributeMaxDynamicSharedMemorySize, FLASH_SMEM);
    cudaFuncSetAttribute(sgemm_tc, cudaFuncAttributeMaxDynamicSharedMemorySize, GEMM_SMEM);

    uint32_t* wq_t; cudaGetSymbolAddress((void**)&wq_t, g_wqt);
    uint32_t* wo_t; cudaGetSymbolAddress((void**)&wo_t, g_wot);

    wcvt_k<<<S3 * DIMM / 1024, 256>>>(w_qkv, wq_t);
    wcvt_k<<<DIMM * DIMM / 1024, 256>>>(w_out, wo_t);
    rmsnorm_k<<<BB * NN, 256>>>(x, gamma);
    sgemm_tc<<<dim3(S3 / 128, BB * NN / 128), 256, GEMM_SMEM>>>(0, nullptr);
    rope_feat_k<<<BB * HH * NN / 4, dim3(64, 4)>>>();
    vtrans_k<<<dim3(NN / 32, DHH / 32, BB * HH), dim3(32, 8)>>>();
    flash_tc<<<dim3(NN / 64, BB * HH), 256, FLASH_SMEM>>>();
    retrieve_gate_k<<<dim3(NN / 32, BB * HH), 128>>>(mem_kv, mem_norm, head_gates);
    sgemm_tc<<<dim3(DIMM / 128, BB * NN / 128), 256, GEMM_SMEM>>>(1, out);
    newkv_part_k<<<dim3(BB * HH, 4, 4), 256>>>(mem_kv, mem_norm);
    newkv_red_k<<<BB * HH, 256>>>(mem_kv, out_kv);
    newnorm_part_k<<<dim3(BB * HH, 8), 128>>>();
    newnorm_red_k<<<BB * HH, 128>>>(mem_norm, out_norm);
}